// round 4
// baseline (speedup 1.0000x reference)
#include <cuda_runtime.h>
#include <math.h>

// Problem constants
#define Bb   128
#define Cc   1024
#define Hh   24
#define Ww   12
#define Nn   288           // H*W
#define EPSv 1e-5f

// ---------------------------------------------------------------------------
// Scratch (static device globals — allocation-free per harness rules)
// ---------------------------------------------------------------------------
__device__ float g_F [(size_t)Bb * Nn * Nn];   // spatial attention (b, n, n)
__device__ float g_Y [(size_t)Bb * Cc * Nn];   // spatial AV output
__device__ float g_Z [(size_t)Bb * Cc * Nn];   // residual 1 output
__device__ float g_Y2[(size_t)Bb * Cc * Nn];   // channel AV output
__device__ float g_F2[(size_t)Bb * Cc * Cc];   // channel attention (b, c, c)
__device__ float g_scale[Cc];
__device__ float g_shift[Cc];

// ---------------------------------------------------------------------------
// f32x2 packed helpers (FFMA2 — PTX only, ptxas never auto-emits)
// ---------------------------------------------------------------------------
__device__ __forceinline__ unsigned long long pack2(float x, float y) {
    unsigned long long r;
    asm("mov.b64 %0, {%1, %2};" : "=l"(r) : "f"(x), "f"(y));
    return r;
}
__device__ __forceinline__ float2 unpack2(unsigned long long v) {
    float2 r;
    asm("mov.b64 {%0, %1}, %2;" : "=f"(r.x), "=f"(r.y) : "l"(v));
    return r;
}
__device__ __forceinline__ void fma2(unsigned long long& d,
                                     unsigned long long a, unsigned long long b) {
    asm("fma.rn.f32x2 %0, %1, %2, %0;" : "+l"(d) : "l"(a), "l"(b));
}

// ---------------------------------------------------------------------------
// Block reduction helper (works for blockDim.x in {256, 288})
// op: 0 = max, 1 = sum
// ---------------------------------------------------------------------------
__device__ __forceinline__ float block_reduce(float v, int op) {
    __shared__ float red[32];
    #pragma unroll
    for (int o = 16; o > 0; o >>= 1) {
        float other = __shfl_xor_sync(0xffffffffu, v, o);
        v = op ? (v + other) : fmaxf(v, other);
    }
    int lane = threadIdx.x & 31;
    int wid  = threadIdx.x >> 5;
    int nw   = (blockDim.x + 31) >> 5;
    if (lane == 0) red[wid] = v;
    __syncthreads();
    if (wid == 0) {
        float r = (lane < nw) ? red[lane] : (op ? 0.0f : -3.4e38f);
        #pragma unroll
        for (int o = 16; o > 0; o >>= 1) {
            float other = __shfl_xor_sync(0xffffffffu, r, o);
            r = op ? (r + other) : fmaxf(r, other);
        }
        if (lane == 0) red[0] = r;
    }
    __syncthreads();
    float r = red[0];
    __syncthreads();
    return r;
}

// ---------------------------------------------------------------------------
// Unified f32x2 GEMM: C[b,m,n] = alpha * sum_k opA(A)[m,k] * opB(B)[k,n]
//   AT=false: A stored (K x M) row-major, row stride lda  (gram / NN-B style)
//   AT=true : A stored (M x K) row-major, row stride lda  (transpose-load)
//   BT=false: B stored (K x N) row-major, row stride ldb
//   BT=true : B stored (N x K) row-major, row stride ldb  (transpose-load)
// Tile 128(m) x 96(n) x 16(k), 256 threads, 8x6 microtile via FFMA2.
// Register-staged double buffering in smem.
// ---------------------------------------------------------------------------
template<bool AT, bool BT>
__global__ __launch_bounds__(256, 2) void k_gemm_f32x2(
    const float* __restrict__ A, const float* __restrict__ Bm, float* __restrict__ Cd,
    int M, int Nd, int K, int lda, int ldb,
    size_t sA, size_t sB, size_t sC, float alpha)
{
    __shared__ __align__(16) float As[2][16][128];
    __shared__ __align__(16) float Bs[2][16][98];

    const int bz = blockIdx.z;
    const int m0 = blockIdx.y * 128;
    const int n0 = blockIdx.x * 96;
    const float* Ab = A  + (size_t)bz * sA;
    const float* Bb_ = Bm + (size_t)bz * sB;

    const int t  = threadIdx.x;
    const int tx = t & 15;     // n group (6 cols each)
    const int ty = t >> 4;     // m group (8 rows each)

    // staging registers
    float rA[8];
    float rB[8];   // BT uses 8, direct uses 6

    // ---- global -> regs loader ----
    auto ldg_tile = [&](int k0) {
        if (AT) {
            int row = t >> 1, kc = (t & 1) * 8;
            bool v = (m0 + row) < M;
            const float* p = Ab + (size_t)(m0 + row) * lda + k0 + kc;
            float4 x0 = v ? *(const float4*)p       : make_float4(0,0,0,0);
            float4 x1 = v ? *(const float4*)(p + 4) : make_float4(0,0,0,0);
            rA[0]=x0.x; rA[1]=x0.y; rA[2]=x0.z; rA[3]=x0.w;
            rA[4]=x1.x; rA[5]=x1.y; rA[6]=x1.z; rA[7]=x1.w;
        } else {
            int k = t >> 4, mc = (t & 15) * 8;
            bool v = (m0 + mc) < M;           // M % 8 == 0 -> whole chunk validity
            const float* p = Ab + (size_t)(k0 + k) * lda + m0 + mc;
            float4 x0 = v ? *(const float4*)p       : make_float4(0,0,0,0);
            float4 x1 = v ? *(const float4*)(p + 4) : make_float4(0,0,0,0);
            rA[0]=x0.x; rA[1]=x0.y; rA[2]=x0.z; rA[3]=x0.w;
            rA[4]=x1.x; rA[5]=x1.y; rA[6]=x1.z; rA[7]=x1.w;
        }
        if (BT) {
            #pragma unroll
            for (int u = 0; u < 2; u++) {
                int idx = t + u * 256;          // 0..511 -> 384 used
                int row = idx >> 2, kc = (idx & 3) * 4;
                bool v = (row < 96) && ((n0 + row) < Nd);
                const float* p = Bb_ + (size_t)(n0 + row) * ldb + k0 + kc;
                float4 x = v ? *(const float4*)p : make_float4(0,0,0,0);
                rB[u*4+0]=x.x; rB[u*4+1]=x.y; rB[u*4+2]=x.z; rB[u*4+3]=x.w;
            }
        } else {
            int k = t >> 4, nc = (t & 15) * 6;
            const float* p = Bb_ + (size_t)(k0 + k) * ldb + n0 + nc;
            #pragma unroll
            for (int i = 0; i < 3; i++) {
                bool v = (n0 + nc + 2*i) < Nd;  // Nd even -> pair validity
                float2 x = v ? *(const float2*)(p + 2*i) : make_float2(0,0);
                rB[2*i]=x.x; rB[2*i+1]=x.y;
            }
        }
    };

    // ---- regs -> smem ----
    auto sts_tile = [&](int buf) {
        if (AT) {
            int row = t >> 1, kc = (t & 1) * 8;
            #pragma unroll
            for (int i = 0; i < 8; i++) As[buf][kc + i][row] = rA[i];
        } else {
            int k = t >> 4, mc = (t & 15) * 8;
            *(float4*)&As[buf][k][mc]     = make_float4(rA[0],rA[1],rA[2],rA[3]);
            *(float4*)&As[buf][k][mc + 4] = make_float4(rA[4],rA[5],rA[6],rA[7]);
        }
        if (BT) {
            #pragma unroll
            for (int u = 0; u < 2; u++) {
                int idx = t + u * 256;
                int row = idx >> 2, kc = (idx & 3) * 4;
                if (row < 96) {
                    #pragma unroll
                    for (int i = 0; i < 4; i++) Bs[buf][kc + i][row] = rB[u*4+i];
                }
            }
        } else {
            int k = t >> 4, nc = (t & 15) * 6;
            #pragma unroll
            for (int i = 0; i < 3; i++)
                *(float2*)&Bs[buf][k][nc + 2*i] = make_float2(rB[2*i], rB[2*i+1]);
        }
    };

    unsigned long long acc[8][3];
    #pragma unroll
    for (int i = 0; i < 8; i++)
        #pragma unroll
        for (int j = 0; j < 3; j++) acc[i][j] = 0ull;   // {+0.f, +0.f}

    const int nk = K / 16;
    ldg_tile(0);
    sts_tile(0);
    int p = 0;

    for (int kt = 0; kt < nk; kt++) {
        __syncthreads();
        if (kt + 1 < nk) ldg_tile((kt + 1) * 16);   // issue LDGs early

        #pragma unroll
        for (int kk = 0; kk < 16; kk++) {
            const float* ar = &As[p][kk][ty * 8];
            float4 a0 = *(const float4*)ar;
            float4 a1 = *(const float4*)(ar + 4);
            float av[8] = {a0.x,a0.y,a0.z,a0.w,a1.x,a1.y,a1.z,a1.w};
            const float* br = &Bs[p][kk][tx * 6];
            unsigned long long b0 = *(const unsigned long long*)br;
            unsigned long long b1 = *(const unsigned long long*)(br + 2);
            unsigned long long b2 = *(const unsigned long long*)(br + 4);
            #pragma unroll
            for (int i = 0; i < 8; i++) {
                unsigned long long ad = pack2(av[i], av[i]);
                fma2(acc[i][0], ad, b0);
                fma2(acc[i][1], ad, b1);
                fma2(acc[i][2], ad, b2);
            }
        }
        __syncthreads();
        if (kt + 1 < nk) sts_tile(p ^ 1);
        p ^= 1;
    }

    // epilogue
    #pragma unroll
    for (int i = 0; i < 8; i++) {
        int m = m0 + ty * 8 + i;
        if (m >= M) continue;
        float* cp = Cd + (size_t)bz * sC + (size_t)m * Nd + n0 + tx * 6;
        #pragma unroll
        for (int j = 0; j < 3; j++) {
            int n = n0 + tx * 6 + 2 * j;
            if (n < Nd) {
                float2 v = unpack2(acc[i][j]);
                v.x *= alpha; v.y *= alpha;
                *(float2*)(cp + 2 * j) = v;
            }
        }
    }
}

// ---------------------------------------------------------------------------
// Spatial softmax with gaussian prior: per row (b,p) of g_F (length Nn=288):
//   p1 = softmax(row); w = p1 * dis[p,:]; row = softmax(w)
// ---------------------------------------------------------------------------
__global__ __launch_bounds__(288) void k_softmax_prior(const float* __restrict__ dis)
{
    int p = blockIdx.x;
    int b = blockIdx.y;
    float* f = g_F + ((size_t)b * Nn + p) * Nn;
    const float* d = dis + (size_t)p * Nn;
    int t = threadIdx.x;

    float v = f[t];
    float m1 = block_reduce(v, 0);
    float e1 = __expf(v - m1);
    float s1 = block_reduce(e1, 1);
    float w  = (e1 / s1) * d[t];
    float m2 = block_reduce(w, 0);
    float e2 = __expf(w - m2);
    float s2 = block_reduce(e2, 1);
    f[t] = e2 / s2;
}

// ---------------------------------------------------------------------------
// Channel softmax: rows of g_F2 (length Cc=1024), 256 threads x 4 elems.
// ---------------------------------------------------------------------------
__global__ __launch_bounds__(256) void k_softmax_chan()
{
    size_t row = blockIdx.x;
    float* f = g_F2 + row * (size_t)Cc;
    int t = threadIdx.x;

    float v[4];
    #pragma unroll
    for (int i = 0; i < 4; i++) v[i] = f[t + 256 * i];
    float lm = fmaxf(fmaxf(v[0], v[1]), fmaxf(v[2], v[3]));
    float m = block_reduce(lm, 0);
    float e[4], ls = 0.0f;
    #pragma unroll
    for (int i = 0; i < 4; i++) { e[i] = __expf(v[i] - m); ls += e[i]; }
    float s = block_reduce(ls, 1);
    float inv = 1.0f / s;
    #pragma unroll
    for (int i = 0; i < 4; i++) f[t + 256 * i] = e[i] * inv;
}

// ---------------------------------------------------------------------------
// BatchNorm stats: per channel mean/var over (B, N). float4 + flat indexing.
// ---------------------------------------------------------------------------
__global__ __launch_bounds__(256) void k_bnstats(
    const float* __restrict__ Y,
    const float* __restrict__ gamma, const float* __restrict__ beta)
{
    int c = blockIdx.x;
    int t = threadIdx.x;
    const int n4 = Nn / 4;                 // 72
    const int tot4 = Bb * n4;              // 9216
    float s = 0.0f, sq = 0.0f;
    #pragma unroll 4
    for (int idx = t; idx < tot4; idx += 256) {
        int b = idx / n4;
        int i = idx - b * n4;
        float4 v = *(const float4*)(Y + ((size_t)b * Cc + c) * Nn + i * 4);
        s  += (v.x + v.y) + (v.z + v.w);
        sq += (v.x*v.x + v.y*v.y) + (v.z*v.z + v.w*v.w);
    }
    s  = block_reduce(s, 1);
    sq = block_reduce(sq, 1);
    if (t == 0) {
        const float invN = 1.0f / (float)(Bb * Nn);
        float mean = s * invN;
        float var  = sq * invN - mean * mean;
        float sc = gamma[c] * rsqrtf(var + EPSv);
        g_scale[c] = sc;
        g_shift[c] = beta[c] - mean * sc;
    }
}

// ---------------------------------------------------------------------------
// out = scale[c]*y + shift[c] + residual   (float4)
// ---------------------------------------------------------------------------
__global__ __launch_bounds__(256) void k_bn_apply_add(
    const float* __restrict__ Y, const float* __restrict__ R, float* __restrict__ out)
{
    size_t i4 = (size_t)blockIdx.x * blockDim.x + threadIdx.x;
    const size_t total4 = (size_t)Bb * Cc * Nn / 4;
    if (i4 >= total4) return;
    size_t e = i4 * 4;
    int c = (int)((e / Nn) % Cc);
    float4 y = ((const float4*)Y)[i4];
    float4 r = ((const float4*)R)[i4];
    float sc = g_scale[c], sh = g_shift[c];
    float4 o;
    o.x = fmaf(sc, y.x, sh) + r.x;
    o.y = fmaf(sc, y.y, sh) + r.y;
    o.z = fmaf(sc, y.z, sh) + r.z;
    o.w = fmaf(sc, y.w, sh) + r.w;
    ((float4*)out)[i4] = o;
}

// ---------------------------------------------------------------------------
// Launch
// ---------------------------------------------------------------------------
extern "C" void kernel_launch(void* const* d_in, const int* in_sizes, int n_in,
                              void* d_out, int out_size)
{
    const float* x      = (const float*)d_in[0];
    const float* dis    = (const float*)d_in[1];
    const float* gamma1 = (const float*)d_in[2];
    const float* beta1  = (const float*)d_in[3];
    const float* gamma2 = (const float*)d_in[4];
    const float* beta2  = (const float*)d_in[5];
    float* out = (float*)d_out;

    float *pF, *pY, *pZ, *pY2, *pF2;
    cudaGetSymbolAddress((void**)&pF,  g_F);
    cudaGetSymbolAddress((void**)&pY,  g_Y);
    cudaGetSymbolAddress((void**)&pZ,  g_Z);
    cudaGetSymbolAddress((void**)&pY2, g_Y2);
    cudaGetSymbolAddress((void**)&pF2, g_F2);

    const size_t sXN = (size_t)Cc * Nn;   // per-batch stride of (C,N) tensors
    const size_t sFF = (size_t)Nn * Nn;   // per-batch stride of F
    const size_t sCC = (size_t)Cc * Cc;   // per-batch stride of F2

    // 1) F = X^T X / sqrt(C)          M=N=288, K=1024 ; both operands K-major
    k_gemm_f32x2<false,false><<<dim3(3, 3, Bb), 256>>>(
        x, x, pF, Nn, Nn, Cc, Nn, Nn, sXN, sXN, sFF, 0.03125f);

    // 2) softmax -> *dis -> softmax   (in place on g_F)
    k_softmax_prior<<<dim3(Nn, Bb), 288>>>(dis);

    // 3) Y = X F^T                    M=1024, N=288, K=288 (NT)
    k_gemm_f32x2<true,true><<<dim3(3, 8, Bb), 256>>>(
        x, pF, pY, Cc, Nn, Nn, Nn, Nn, sXN, sFF, sXN, 1.0f);

    // 4) BN1 stats + 5) Z = bn1(Y) + X
    k_bnstats<<<Cc, 256>>>(pY, gamma1, beta1);
    {
        size_t total4 = (size_t)Bb * Cc * Nn / 4;
        int blocks = (int)((total4 + 255) / 256);
        k_bn_apply_add<<<blocks, 256>>>(pY, x, pZ);
    }

    // 6) F2 = Z Z^T                   M=N=1024, K=288 (NT)
    k_gemm_f32x2<true,true><<<dim3(11, 8, Bb), 256>>>(
        pZ, pZ, pF2, Cc, Cc, Nn, Nn, Nn, sXN, sXN, sCC, 1.0f);

    // 7) softmax rows of F2
    k_softmax_chan<<<Bb * Cc, 256>>>();

    // 8) Y2 = F2 Z                    M=1024, N=288, K=1024 (NN)
    k_gemm_f32x2<true,false><<<dim3(3, 8, Bb), 256>>>(
        pF2, pZ, pY2, Cc, Nn, Cc, Cc, Nn, sCC, sXN, sXN, 1.0f);

    // 9) BN2 stats + 10) out = bn2(Y2) + Z
    k_bnstats<<<Cc, 256>>>(pY2, gamma2, beta2);
    {
        size_t total4 = (size_t)Bb * Cc * Nn / 4;
        int blocks = (int)((total4 + 255) / 256);
        k_bn_apply_add<<<blocks, 256>>>(pY2, pZ, out);
    }
}

// round 6
// speedup vs baseline: 1.9290x; 1.9290x over previous
#include <cuda_runtime.h>
#include <cuda_bf16.h>
#include <math.h>
#include <stdint.h>

#define Bb   128
#define Cc   1024
#define Nn   288
#define Kp1  320            // padded K for K=288 (multiple of 32)
#define EPSv 1e-5f

typedef __nv_bfloat16 bf16;

// fp32 scratch
__device__ float g_F [(size_t)Bb * Nn * Nn];
__device__ float g_Y [(size_t)Bb * Cc * Nn];
__device__ float g_Z [(size_t)Bb * Cc * Nn];
__device__ float g_Y2[(size_t)Bb * Cc * Nn];
__device__ float g_F2[(size_t)Bb * Cc * Cc];
__device__ float g_scale[Cc];
__device__ float g_shift[Cc];
// bf16 hi/lo K-major operands (pads stay zero: zero-init, never written)
__device__ bf16 g_Xh [(size_t)Bb * Cc * Kp1];
__device__ bf16 g_Xl [(size_t)Bb * Cc * Kp1];
__device__ bf16 g_XTh[(size_t)Bb * Nn * Cc];
__device__ bf16 g_XTl[(size_t)Bb * Nn * Cc];
__device__ bf16 g_Zh [(size_t)Bb * Cc * Kp1];
__device__ bf16 g_Zl [(size_t)Bb * Cc * Kp1];
__device__ bf16 g_ZTh[(size_t)Bb * Nn * Cc];
__device__ bf16 g_ZTl[(size_t)Bb * Nn * Cc];
__device__ bf16 g_Fh [(size_t)Bb * Nn * Kp1];
__device__ bf16 g_Fl [(size_t)Bb * Nn * Kp1];
__device__ bf16 g_F2h[(size_t)Bb * Cc * Cc];
__device__ bf16 g_F2l[(size_t)Bb * Cc * Cc];

// ---------------- helpers ----------------
__device__ __forceinline__ uint32_t smem_u32(const void* p) {
    uint32_t a;
    asm("{ .reg .u64 t; cvta.to.shared.u64 t, %1; cvt.u32.u64 %0, t; }" : "=r"(a) : "l"(p));
    return a;
}
__device__ __forceinline__ void split_bf16(float x, bf16& h, bf16& l) {
    h = __float2bfloat16(x);
    l = __float2bfloat16(x - __bfloat162float(h));
}

#define LDMX4(r, a) \
    asm volatile("ldmatrix.sync.aligned.m8n8.x4.shared.b16 {%0,%1,%2,%3}, [%4];" \
        : "=r"((r)[0]), "=r"((r)[1]), "=r"((r)[2]), "=r"((r)[3]) : "r"(a))

__device__ __forceinline__ void mma16816(float* c, const uint32_t* a, const uint32_t* b) {
    asm volatile("mma.sync.aligned.m16n8k16.row.col.f32.bf16.bf16.f32 "
        "{%0,%1,%2,%3}, {%4,%5,%6,%7}, {%8,%9}, {%0,%1,%2,%3};"
        : "+f"(c[0]), "+f"(c[1]), "+f"(c[2]), "+f"(c[3])
        : "r"(a[0]), "r"(a[1]), "r"(a[2]), "r"(a[3]), "r"(b[0]), "r"(b[1]));
}

// ---------------- block reduce ----------------
__device__ __forceinline__ float block_reduce(float v, int op) {
    __shared__ float red[32];
    #pragma unroll
    for (int o = 16; o > 0; o >>= 1) {
        float u = __shfl_xor_sync(0xffffffffu, v, o);
        v = op ? (v + u) : fmaxf(v, u);
    }
    int lane = threadIdx.x & 31, wid = threadIdx.x >> 5;
    int nw = (blockDim.x + 31) >> 5;
    if (lane == 0) red[wid] = v;
    __syncthreads();
    if (wid == 0) {
        float r = (lane < nw) ? red[lane] : (op ? 0.0f : -3.4e38f);
        #pragma unroll
        for (int o = 16; o > 0; o >>= 1) {
            float u = __shfl_xor_sync(0xffffffffu, r, o);
            r = op ? (r + u) : fmaxf(r, u);
        }
        if (lane == 0) red[0] = r;
    }
    __syncthreads();
    float r = red[0];
    __syncthreads();
    return r;
}

// ---------------------------------------------------------------------------
// HMMA GEMM: C[b,m,n] = alpha * sum_k A[m,k]*B[n,k]
// A (M x Kp), B (Nd x Kp) K-major bf16 hi/lo; Kp multiple of 32, pads zero.
// 128x128x32 tile, 256 thr, warp grid 2x4 (warp tile 64x32), m16n8k16.
// 3 passes fused per k-slice: hh + h*lo + lo*h into same fp32 accum.
// Smem: 2 bufs x 4 segs (Ah,Al,Bh,Bl) x 128 rows x 4 x 16B chunks, XOR swizzle.
// ---------------------------------------------------------------------------
__global__ __launch_bounds__(256, 1) void k_mma_hmma(
    const bf16* __restrict__ Ah, const bf16* __restrict__ Al,
    const bf16* __restrict__ Bh, const bf16* __restrict__ Bl,
    float* __restrict__ Cd, int M, int Nd, int Kp,
    size_t sA, size_t sB, size_t sC, float alpha)
{
    extern __shared__ __align__(16) char dsm[];
    const int bz = blockIdx.z;
    const int m0 = blockIdx.y * 128, n0 = blockIdx.x * 128;
    const int t = threadIdx.x;
    const int lane = t & 31, warp = t >> 5;
    const int mbase = (warp >> 2) * 64, nbase = (warp & 3) * 32;

    const bf16* Abh = Ah + (size_t)bz * sA;
    const bf16* Abl = Al + (size_t)bz * sA;
    const bf16* Bbh = Bh + (size_t)bz * sB;
    const bf16* Bbl = Bl + (size_t)bz * sB;

    const uint32_t sbase = smem_u32(dsm);
    // byte offset inside one buffer: seg(0..3) 8192B each, row swizzled chunks
    auto soff = [](int seg, int row, int chunk) -> uint32_t {
        return (uint32_t)(seg * 8192 + (row * 4 + (chunk ^ (row & 3))) * 16);
    };

    uint4 st[8];
    auto ldg_tile = [&](int k0) {
        #pragma unroll
        for (int i = 0; i < 8; i++) {
            int idx = t + i * 256;          // 0..2047
            int op = idx >> 10;             // 0 = A, 1 = B
            int hl = (idx >> 9) & 1;
            int r  = idx & 511;
            int row = r >> 2, chunk = r & 3;
            int g = (op ? n0 : m0) + row;
            bool valid = g < (op ? Nd : M);
            const bf16* base = op ? (hl ? Bbl : Bbh) : (hl ? Abl : Abh);
            st[i] = valid ? *(const uint4*)(base + (size_t)g * Kp + k0 + chunk * 8)
                          : make_uint4(0, 0, 0, 0);
        }
    };
    auto sts_tile = [&](int buf) {
        #pragma unroll
        for (int i = 0; i < 8; i++) {
            int idx = t + i * 256;
            int op = idx >> 10, hl = (idx >> 9) & 1;
            int r = idx & 511;
            int row = r >> 2, chunk = r & 3;
            *(uint4*)(dsm + buf * 32768 + soff(op * 2 + hl, row, chunk)) = st[i];
        }
    };

    float acc[4][4][4];
    #pragma unroll
    for (int mi = 0; mi < 4; mi++)
        #pragma unroll
        for (int ni = 0; ni < 4; ni++)
            #pragma unroll
            for (int q = 0; q < 4; q++) acc[mi][ni][q] = 0.0f;

    const int nk = Kp / 32;
    ldg_tile(0);
    sts_tile(0);
    __syncthreads();
    int buf = 0;

    for (int kt = 0; kt < nk; kt++) {
        if (kt + 1 < nk) ldg_tile((kt + 1) * 32);

        #pragma unroll
        for (int s = 0; s < 2; s++) {
            const int c0 = s * 2;
            // fragment addresses
            const int arow = (lane & 15), achk = c0 + (lane >> 4);
            const int brow = (lane & 7) + ((lane & 16) >> 1);
            const int bchk = c0 + ((lane >> 3) & 1);
            uint32_t ah[4][4], al[4][4], bhf[4][2], blf[4][2];
            #pragma unroll
            for (int mi = 0; mi < 4; mi++) {
                uint32_t a0 = sbase + buf * 32768 + soff(0, mbase + mi * 16 + arow, achk);
                uint32_t a1 = sbase + buf * 32768 + soff(1, mbase + mi * 16 + arow, achk);
                LDMX4(ah[mi], a0);
                LDMX4(al[mi], a1);
            }
            #pragma unroll
            for (int h = 0; h < 2; h++) {
                uint32_t r4[4];
                uint32_t b0 = sbase + buf * 32768 + soff(2, nbase + h * 16 + brow, bchk);
                LDMX4(r4, b0);
                bhf[h*2][0] = r4[0]; bhf[h*2][1] = r4[1];
                bhf[h*2+1][0] = r4[2]; bhf[h*2+1][1] = r4[3];
                uint32_t b1 = sbase + buf * 32768 + soff(3, nbase + h * 16 + brow, bchk);
                LDMX4(r4, b1);
                blf[h*2][0] = r4[0]; blf[h*2][1] = r4[1];
                blf[h*2+1][0] = r4[2]; blf[h*2+1][1] = r4[3];
            }
            #pragma unroll
            for (int mi = 0; mi < 4; mi++)
                #pragma unroll
                for (int ni = 0; ni < 4; ni++) {
                    mma16816(acc[mi][ni], ah[mi], bhf[ni]);   // hi*hi
                    mma16816(acc[mi][ni], ah[mi], blf[ni]);   // hi*lo
                    mma16816(acc[mi][ni], al[mi], bhf[ni]);   // lo*hi
                }
        }

        if (kt + 1 < nk) {
            __syncthreads();
            sts_tile(buf ^ 1);
            __syncthreads();
            buf ^= 1;
        }
    }

    // epilogue
    #pragma unroll
    for (int mi = 0; mi < 4; mi++) {
        #pragma unroll
        for (int ni = 0; ni < 4; ni++) {
            int row = m0 + mbase + mi * 16 + (lane >> 2);
            int col = n0 + nbase + ni * 8 + (lane & 3) * 2;
            if (col < Nd) {
                float* cp = Cd + (size_t)bz * sC;
                if (row < M) {
                    float2 v = make_float2(acc[mi][ni][0] * alpha, acc[mi][ni][1] * alpha);
                    *(float2*)(cp + (size_t)row * Nd + col) = v;
                }
                if (row + 8 < M) {
                    float2 v = make_float2(acc[mi][ni][2] * alpha, acc[mi][ni][3] * alpha);
                    *(float2*)(cp + (size_t)(row + 8) * Nd + col) = v;
                }
            }
        }
    }
}

// ---------------------------------------------------------------------------
// fp32 (rows x cols) -> direct hi/lo (stride ds) + transposed hi/lo (stride ts)
// ---------------------------------------------------------------------------
__global__ __launch_bounds__(256) void k_split_both(
    const float* __restrict__ src,
    bf16* __restrict__ dh, bf16* __restrict__ dl, int ds,
    bf16* __restrict__ th, bf16* __restrict__ tl, int ts,
    int rows, int cols)
{
    __shared__ float tile[32][33];
    const int b = blockIdx.z;
    const int c0 = blockIdx.x * 32, r0 = blockIdx.y * 32;
    const float* s = src + (size_t)b * rows * cols;
    const size_t dbs = (size_t)b * rows * ds;
    const size_t tbs = (size_t)b * cols * ts;

    #pragma unroll
    for (int i = 0; i < 4; i++) {
        int r = r0 + threadIdx.y + i * 8, c = c0 + threadIdx.x;
        float v = s[(size_t)r * cols + c];
        tile[threadIdx.y + i * 8][threadIdx.x] = v;
        bf16 h, l; split_bf16(v, h, l);
        size_t o = dbs + (size_t)r * ds + c;
        dh[o] = h; dl[o] = l;
    }
    __syncthreads();
    #pragma unroll
    for (int i = 0; i < 4; i++) {
        int tr = c0 + threadIdx.y + i * 8, tc = r0 + threadIdx.x;
        float v = tile[threadIdx.x][threadIdx.y + i * 8];
        bf16 h, l; split_bf16(v, h, l);
        size_t o = tbs + (size_t)tr * ts + tc;
        th[o] = h; tl[o] = l;
    }
}

// ---------------------------------------------------------------------------
__global__ __launch_bounds__(288) void k_softmax_prior(const float* __restrict__ dis)
{
    int p = blockIdx.x, b = blockIdx.y, t = threadIdx.x;
    const float* f = g_F + ((size_t)b * Nn + p) * Nn;
    float v = f[t];
    float m1 = block_reduce(v, 0);
    float e1 = __expf(v - m1);
    float s1 = block_reduce(e1, 1);
    float w  = (e1 / s1) * dis[(size_t)p * Nn + t];
    float m2 = block_reduce(w, 0);
    float e2 = __expf(w - m2);
    float s2 = block_reduce(e2, 1);
    bf16 h, l; split_bf16(e2 / s2, h, l);
    size_t o = ((size_t)b * Nn + p) * Kp1 + t;
    g_Fh[o] = h; g_Fl[o] = l;
}

__global__ __launch_bounds__(256) void k_softmax_chan()
{
    size_t row = blockIdx.x;
    const float* f = g_F2 + row * (size_t)Cc;
    int t = threadIdx.x;
    float v[4];
    #pragma unroll
    for (int i = 0; i < 4; i++) v[i] = f[t + 256 * i];
    float m = block_reduce(fmaxf(fmaxf(v[0], v[1]), fmaxf(v[2], v[3])), 0);
    float e[4], ls = 0.0f;
    #pragma unroll
    for (int i = 0; i < 4; i++) { e[i] = __expf(v[i] - m); ls += e[i]; }
    float s = block_reduce(ls, 1);
    float inv = 1.0f / s;
    #pragma unroll
    for (int i = 0; i < 4; i++) {
        bf16 h, l; split_bf16(e[i] * inv, h, l);
        size_t o = row * (size_t)Cc + t + 256 * i;
        g_F2h[o] = h; g_F2l[o] = l;
    }
}

__global__ __launch_bounds__(256) void k_bnstats(
    const float* __restrict__ Y,
    const float* __restrict__ gamma, const float* __restrict__ beta)
{
    int c = blockIdx.x, t = threadIdx.x;
    const int n4 = Nn / 4, tot4 = Bb * n4;
    float s = 0.0f, sq = 0.0f;
    #pragma unroll 4
    for (int idx = t; idx < tot4; idx += 256) {
        int b = idx / n4, i = idx - b * n4;
        float4 v = *(const float4*)(Y + ((size_t)b * Cc + c) * Nn + i * 4);
        s  += (v.x + v.y) + (v.z + v.w);
        sq += (v.x * v.x + v.y * v.y) + (v.z * v.z + v.w * v.w);
    }
    s = block_reduce(s, 1);
    sq = block_reduce(sq, 1);
    if (t == 0) {
        const float invN = 1.0f / (float)(Bb * Nn);
        float mean = s * invN;
        float var  = sq * invN - mean * mean;
        float sc = gamma[c] * rsqrtf(var + EPSv);
        g_scale[c] = sc;
        g_shift[c] = beta[c] - mean * sc;
    }
}

__global__ __launch_bounds__(256) void k_bn_apply_add(
    const float* __restrict__ Y, const float* __restrict__ R, float* __restrict__ out)
{
    size_t i4 = (size_t)blockIdx.x * blockDim.x + threadIdx.x;
    const size_t total4 = (size_t)Bb * Cc * Nn / 4;
    if (i4 >= total4) return;
    int c = (int)((i4 * 4 / Nn) % Cc);
    float4 y = ((const float4*)Y)[i4];
    float4 r = ((const float4*)R)[i4];
    float sc = g_scale[c], sh = g_shift[c];
    float4 o;
    o.x = fmaf(sc, y.x, sh) + r.x;
    o.y = fmaf(sc, y.y, sh) + r.y;
    o.z = fmaf(sc, y.z, sh) + r.z;
    o.w = fmaf(sc, y.w, sh) + r.w;
    ((float4*)out)[i4] = o;
}

// ---------------------------------------------------------------------------
extern "C" void kernel_launch(void* const* d_in, const int* in_sizes, int n_in,
                              void* d_out, int out_size)
{
    const float* x      = (const float*)d_in[0];
    const float* dis    = (const float*)d_in[1];
    const float* gamma1 = (const float*)d_in[2];
    const float* beta1  = (const float*)d_in[3];
    const float* gamma2 = (const float*)d_in[4];
    const float* beta2  = (const float*)d_in[5];
    float* out = (float*)d_out;

    float *pF, *pY, *pZ, *pY2, *pF2;
    cudaGetSymbolAddress((void**)&pF,  g_F);
    cudaGetSymbolAddress((void**)&pY,  g_Y);
    cudaGetSymbolAddress((void**)&pZ,  g_Z);
    cudaGetSymbolAddress((void**)&pY2, g_Y2);
    cudaGetSymbolAddress((void**)&pF2, g_F2);
    bf16 *pXh,*pXl,*pXTh,*pXTl,*pZh,*pZl,*pZTh,*pZTl,*pFh,*pFl,*pF2h,*pF2l;
    cudaGetSymbolAddress((void**)&pXh,  g_Xh);  cudaGetSymbolAddress((void**)&pXl,  g_Xl);
    cudaGetSymbolAddress((void**)&pXTh, g_XTh); cudaGetSymbolAddress((void**)&pXTl, g_XTl);
    cudaGetSymbolAddress((void**)&pZh,  g_Zh);  cudaGetSymbolAddress((void**)&pZl,  g_Zl);
    cudaGetSymbolAddress((void**)&pZTh, g_ZTh); cudaGetSymbolAddress((void**)&pZTl, g_ZTl);
    cudaGetSymbolAddress((void**)&pFh,  g_Fh);  cudaGetSymbolAddress((void**)&pFl,  g_Fl);
    cudaGetSymbolAddress((void**)&pF2h, g_F2h); cudaGetSymbolAddress((void**)&pF2l, g_F2l);

    const int SMEM = 65536;   // 2 bufs x 4 segs x 8192B
    cudaFuncSetAttribute(k_mma_hmma, cudaFuncAttributeMaxDynamicSharedMemorySize, SMEM);

    const size_t sX  = (size_t)Cc * Kp1;   // X/Z hi-lo per-batch
    const size_t sXT = (size_t)Nn * Cc;    // XT/ZT
    const size_t sFb = (size_t)Nn * Kp1;   // F hi/lo
    const size_t sF  = (size_t)Nn * Nn;    // F fp32
    const size_t sYb = (size_t)Cc * Nn;    // Y/Z/Y2 fp32
    const size_t sF2 = (size_t)Cc * Cc;

    // 0) split X -> X(hi/lo, Kp=320) + XT(hi/lo, K=1024)
    k_split_both<<<dim3(Nn / 32, Cc / 32, Bb), dim3(32, 8)>>>(
        x, pXh, pXl, Kp1, pXTh, pXTl, Cc, Cc, Nn);

    // 1) F = XT·XTᵀ / 32   (M=N=288, K=1024)
    k_mma_hmma<<<dim3(3, 3, Bb), 256, SMEM>>>(
        pXTh, pXTl, pXTh, pXTl, pF, Nn, Nn, Cc, sXT, sXT, sF, 0.03125f);

    // 2) softmax+prior -> F hi/lo (Kp=320)
    k_softmax_prior<<<dim3(Nn, Bb), 288>>>(dis);

    // 3) Y = X·Fᵀ          (M=1024, N=288, Kp=320)
    k_mma_hmma<<<dim3(3, 8, Bb), 256, SMEM>>>(
        pXh, pXl, pFh, pFl, pY, Cc, Nn, Kp1, sX, sFb, sYb, 1.0f);

    // 4) BN1 + residual
    k_bnstats<<<Cc, 256>>>(pY, gamma1, beta1);
    k_bn_apply_add<<<(int)(((size_t)Bb * Cc * Nn / 4 + 255) / 256), 256>>>(pY, x, pZ);

    // 5) split Z
    k_split_both<<<dim3(Nn / 32, Cc / 32, Bb), dim3(32, 8)>>>(
        pZ, pZh, pZl, Kp1, pZTh, pZTl, Cc, Cc, Nn);

    // 6) F2 = Z·Zᵀ         (M=N=1024, Kp=320)
    k_mma_hmma<<<dim3(8, 8, Bb), 256, SMEM>>>(
        pZh, pZl, pZh, pZl, pF2, Cc, Cc, Kp1, sX, sX, sF2, 1.0f);

    // 7) softmax rows of F2 -> F2 hi/lo
    k_softmax_chan<<<Bb * Cc, 256>>>();

    // 8) Y2 = F2·ZTᵀ       (M=1024, N=288, K=1024)
    k_mma_hmma<<<dim3(3, 8, Bb), 256, SMEM>>>(
        pF2h, pF2l, pZTh, pZTl, pY2, Cc, Nn, Cc, sF2, sXT, sYb, 1.0f);

    // 9) BN2 + residual -> out
    k_bnstats<<<Cc, 256>>>(pY2, gamma2, beta2);
    k_bn_apply_add<<<(int)(((size_t)Bb * Cc * Nn / 4 + 255) / 256), 256>>>(pY2, pZ, out);
}

// round 7
// speedup vs baseline: 3.1939x; 1.6557x over previous
#include <cuda_runtime.h>
#include <cuda_fp16.h>
#include <math.h>
#include <stdint.h>

#define Bb   128
#define Cc   1024
#define Nn   288
#define Kp1  320            // padded K for K=288 (multiple of 32)
#define EPSv 1e-5f

typedef __half h16;

// fp32 scratch
__device__ float g_F [(size_t)Bb * Nn * Nn];
__device__ float g_Y [(size_t)Bb * Cc * Nn];
__device__ float g_Z [(size_t)Bb * Cc * Nn];
__device__ float g_Y2[(size_t)Bb * Cc * Nn];
__device__ float g_F2[(size_t)Bb * Cc * Cc];
__device__ float g_scale[Cc];
__device__ float g_shift[Cc];
// fp16 hi/lo K-major operands (pads stay zero: zero-init, never written)
__device__ h16 g_Xh [(size_t)Bb * Cc * Kp1];     // A-side only: hi suffices
__device__ h16 g_XTh[(size_t)Bb * Nn * Cc];
__device__ h16 g_XTl[(size_t)Bb * Nn * Cc];
__device__ h16 g_Zh [(size_t)Bb * Cc * Kp1];
__device__ h16 g_Zl [(size_t)Bb * Cc * Kp1];
__device__ h16 g_ZTh[(size_t)Bb * Nn * Cc];
__device__ h16 g_ZTl[(size_t)Bb * Nn * Cc];
__device__ h16 g_Fh [(size_t)Bb * Nn * Kp1];
__device__ h16 g_Fl [(size_t)Bb * Nn * Kp1];
__device__ h16 g_F2h[(size_t)Bb * Cc * Cc];      // A-side only: hi suffices

// ---------------- helpers ----------------
__device__ __forceinline__ uint32_t smem_u32(const void* p) {
    uint32_t a;
    asm("{ .reg .u64 t; cvta.to.shared.u64 t, %1; cvt.u32.u64 %0, t; }" : "=r"(a) : "l"(p));
    return a;
}
__device__ __forceinline__ void split_h16(float x, h16& h, h16& l) {
    h = __float2half(x);
    l = __float2half(x - __half2float(h));
}

#define LDMX4(r, a) \
    asm volatile("ldmatrix.sync.aligned.m8n8.x4.shared.b16 {%0,%1,%2,%3}, [%4];" \
        : "=r"((r)[0]), "=r"((r)[1]), "=r"((r)[2]), "=r"((r)[3]) : "r"(a))

__device__ __forceinline__ void mma16816(float* c, const uint32_t* a, const uint32_t* b) {
    asm volatile("mma.sync.aligned.m16n8k16.row.col.f32.f16.f16.f32 "
        "{%0,%1,%2,%3}, {%4,%5,%6,%7}, {%8,%9}, {%0,%1,%2,%3};"
        : "+f"(c[0]), "+f"(c[1]), "+f"(c[2]), "+f"(c[3])
        : "r"(a[0]), "r"(a[1]), "r"(a[2]), "r"(a[3]), "r"(b[0]), "r"(b[1]));
}

#define CP_ASYNC(dst, src, sz) \
    asm volatile("cp.async.cg.shared.global [%0], [%1], 16, %2;" \
        :: "r"(dst), "l"(src), "r"(sz) : "memory")
#define CP_COMMIT() asm volatile("cp.async.commit_group;" ::: "memory")
#define CP_WAIT1()  asm volatile("cp.async.wait_group 1;" ::: "memory")
#define CP_WAIT0()  asm volatile("cp.async.wait_group 0;" ::: "memory")

// ---------------- block reduce ----------------
__device__ __forceinline__ float block_reduce(float v, int op) {
    __shared__ float red[32];
    #pragma unroll
    for (int o = 16; o > 0; o >>= 1) {
        float u = __shfl_xor_sync(0xffffffffu, v, o);
        v = op ? (v + u) : fmaxf(v, u);
    }
    int lane = threadIdx.x & 31, wid = threadIdx.x >> 5;
    int nw = (blockDim.x + 31) >> 5;
    if (lane == 0) red[wid] = v;
    __syncthreads();
    if (wid == 0) {
        float r = (lane < nw) ? red[lane] : (op ? 0.0f : -3.4e38f);
        #pragma unroll
        for (int o = 16; o > 0; o >>= 1) {
            float u = __shfl_xor_sync(0xffffffffu, r, o);
            r = op ? (r + u) : fmaxf(r, u);
        }
        if (lane == 0) red[0] = r;
    }
    __syncthreads();
    float r = red[0];
    __syncthreads();
    return r;
}

// ---------------------------------------------------------------------------
// HMMA GEMM (fp16 2-pass split): C[b,m,n] = alpha * sum_k A[m,k]*B[n,k]
//   ~ A_hi*B_hi + A_hi*B_lo  (A_lo*B_hi dropped: <=2^-11 relative)
// A (M x Kp) hi only; B (Nd x Kp) hi+lo; Kp multiple of 32, pads zero.
// Block tile 128x128x32, 128 threads, 4 warps 2x2, warp tile 64x64, m16n8k16.
// Smem: 2 bufs x 3 segs (Ah,Bh,Bl) x 128 rows x 4 x 16B chunks, XOR swizzle.
// cp.async double-buffered staging.
// ---------------------------------------------------------------------------
__global__ __launch_bounds__(128, 2) void k_mma_hmma(
    const h16* __restrict__ Ah,
    const h16* __restrict__ Bh, const h16* __restrict__ Bl,
    float* __restrict__ Cd, int M, int Nd, int Kp,
    size_t sA, size_t sB, size_t sC, float alpha)
{
    extern __shared__ __align__(16) char dsm[];
    const int bz = blockIdx.z;
    const int m0 = blockIdx.y * 128, n0 = blockIdx.x * 128;
    const int t = threadIdx.x;
    const int lane = t & 31, warp = t >> 5;
    const int mbase = (warp >> 1) * 64, nbase = (warp & 1) * 64;

    const h16* Abh = Ah + (size_t)bz * sA;
    const h16* Bbh = Bh + (size_t)bz * sB;
    const h16* Bbl = Bl + (size_t)bz * sB;

    const uint32_t sbase = smem_u32(dsm);
    // byte offset inside one buffer: seg(0..2) 8192B each, row-swizzled 16B chunks
    auto soff = [](int seg, int row, int chunk) -> uint32_t {
        return (uint32_t)(seg * 8192 + (row * 4 + (chunk ^ (row & 3))) * 16);
    };

    // cp.async staging of one 24KB buffer: 12 chunks per thread
    auto stage = [&](int buf, int k0) {
        #pragma unroll
        for (int i = 0; i < 12; i++) {
            int idx = t + i * 128;          // 0..1535
            int seg = idx >> 9;             // 0=Ah 1=Bh 2=Bl
            int r = idx & 511;
            int row = r >> 2, chunk = r & 3;
            int g = (seg ? n0 : m0) + row;
            bool valid = g < (seg ? Nd : M);
            const h16* base = (seg == 0) ? Abh : (seg == 1 ? Bbh : Bbl);
            const h16* src = base + (size_t)g * Kp + k0 + chunk * 8;
            uint32_t dst = sbase + buf * 24576 + soff(seg, row, chunk);
            CP_ASYNC(dst, src, valid ? 16 : 0);
        }
        CP_COMMIT();
    };

    float acc[4][8][4];
    #pragma unroll
    for (int mi = 0; mi < 4; mi++)
        #pragma unroll
        for (int ni = 0; ni < 8; ni++)
            #pragma unroll
            for (int q = 0; q < 4; q++) acc[mi][ni][q] = 0.0f;

    const int nk = Kp / 32;
    stage(0, 0);

    for (int kt = 0; kt < nk; kt++) {
        const int buf = kt & 1;
        if (kt + 1 < nk) { stage(buf ^ 1, (kt + 1) * 32); CP_WAIT1(); }
        else             { CP_WAIT0(); }
        __syncthreads();

        #pragma unroll
        for (int s = 0; s < 2; s++) {
            const int c0 = s * 2;
            const int arow = (lane & 15), achk = c0 + (lane >> 4);
            const int brow = (lane & 7) + ((lane & 16) >> 1);
            const int bchk = c0 + ((lane >> 3) & 1);
            uint32_t ah[4][4], bhf[8][2], blf[8][2];
            #pragma unroll
            for (int mi = 0; mi < 4; mi++)
                LDMX4(ah[mi], sbase + buf * 24576 + soff(0, mbase + mi * 16 + arow, achk));
            #pragma unroll
            for (int h = 0; h < 4; h++) {
                uint32_t r4[4];
                LDMX4(r4, sbase + buf * 24576 + soff(1, nbase + h * 16 + brow, bchk));
                bhf[h*2][0] = r4[0]; bhf[h*2][1] = r4[1];
                bhf[h*2+1][0] = r4[2]; bhf[h*2+1][1] = r4[3];
                LDMX4(r4, sbase + buf * 24576 + soff(2, nbase + h * 16 + brow, bchk));
                blf[h*2][0] = r4[0]; blf[h*2][1] = r4[1];
                blf[h*2+1][0] = r4[2]; blf[h*2+1][1] = r4[3];
            }
            #pragma unroll
            for (int mi = 0; mi < 4; mi++)
                #pragma unroll
                for (int ni = 0; ni < 8; ni++) {
                    mma16816(acc[mi][ni], ah[mi], bhf[ni]);   // hi*hi
                    mma16816(acc[mi][ni], ah[mi], blf[ni]);   // hi*lo
                }
        }
        __syncthreads();   // all reads of buf done before it is restaged
    }

    // epilogue
    #pragma unroll
    for (int mi = 0; mi < 4; mi++) {
        #pragma unroll
        for (int ni = 0; ni < 8; ni++) {
            int row = m0 + mbase + mi * 16 + (lane >> 2);
            int col = n0 + nbase + ni * 8 + (lane & 3) * 2;
            if (col < Nd) {
                float* cp = Cd + (size_t)bz * sC;
                if (row < M) {
                    float2 v = make_float2(acc[mi][ni][0] * alpha, acc[mi][ni][1] * alpha);
                    *(float2*)(cp + (size_t)row * Nd + col) = v;
                }
                if (row + 8 < M) {
                    float2 v = make_float2(acc[mi][ni][2] * alpha, acc[mi][ni][3] * alpha);
                    *(float2*)(cp + (size_t)(row + 8) * Nd + col) = v;
                }
            }
        }
    }
}

// ---------------------------------------------------------------------------
// fp32 (rows x cols) -> direct hi[/lo] (stride ds) + transposed hi/lo (stride ts)
// dl may be null (A-side operands need hi only)
// ---------------------------------------------------------------------------
__global__ __launch_bounds__(256) void k_split_both(
    const float* __restrict__ src,
    h16* __restrict__ dh, h16* __restrict__ dl, int ds,
    h16* __restrict__ th, h16* __restrict__ tl, int ts,
    int rows, int cols)
{
    __shared__ float tile[32][33];
    const int b = blockIdx.z;
    const int c0 = blockIdx.x * 32, r0 = blockIdx.y * 32;
    const float* s = src + (size_t)b * rows * cols;
    const size_t dbs = (size_t)b * rows * ds;
    const size_t tbs = (size_t)b * cols * ts;

    #pragma unroll
    for (int i = 0; i < 4; i++) {
        int r = r0 + threadIdx.y + i * 8, c = c0 + threadIdx.x;
        float v = s[(size_t)r * cols + c];
        tile[threadIdx.y + i * 8][threadIdx.x] = v;
        h16 h, l; split_h16(v, h, l);
        size_t o = dbs + (size_t)r * ds + c;
        dh[o] = h;
        if (dl) dl[o] = l;
    }
    __syncthreads();
    #pragma unroll
    for (int i = 0; i < 4; i++) {
        int tr = c0 + threadIdx.y + i * 8, tc = r0 + threadIdx.x;
        float v = tile[threadIdx.x][threadIdx.y + i * 8];
        h16 h, l; split_h16(v, h, l);
        size_t o = tbs + (size_t)tr * ts + tc;
        th[o] = h; tl[o] = l;
    }
}

// ---------------------------------------------------------------------------
__global__ __launch_bounds__(288) void k_softmax_prior(const float* __restrict__ dis)
{
    int p = blockIdx.x, b = blockIdx.y, t = threadIdx.x;
    const float* f = g_F + ((size_t)b * Nn + p) * Nn;
    float v = f[t];
    float m1 = block_reduce(v, 0);
    float e1 = __expf(v - m1);
    float s1 = block_reduce(e1, 1);
    float w  = (e1 / s1) * dis[(size_t)p * Nn + t];
    float m2 = block_reduce(w, 0);
    float e2 = __expf(w - m2);
    float s2 = block_reduce(e2, 1);
    h16 h, l; split_h16(e2 / s2, h, l);
    size_t o = ((size_t)b * Nn + p) * Kp1 + t;
    g_Fh[o] = h; g_Fl[o] = l;
}

__global__ __launch_bounds__(256) void k_softmax_chan()
{
    size_t row = blockIdx.x;
    const float* f = g_F2 + row * (size_t)Cc;
    int t = threadIdx.x;
    float v[4];
    #pragma unroll
    for (int i = 0; i < 4; i++) v[i] = f[t + 256 * i];
    float m = block_reduce(fmaxf(fmaxf(v[0], v[1]), fmaxf(v[2], v[3])), 0);
    float e[4], ls = 0.0f;
    #pragma unroll
    for (int i = 0; i < 4; i++) { e[i] = __expf(v[i] - m); ls += e[i]; }
    float s = block_reduce(ls, 1);
    float inv = 1.0f / s;
    #pragma unroll
    for (int i = 0; i < 4; i++)
        g_F2h[row * (size_t)Cc + t + 256 * i] = __float2half(e[i] * inv);
}

__global__ __launch_bounds__(256) void k_bnstats(
    const float* __restrict__ Y,
    const float* __restrict__ gamma, const float* __restrict__ beta)
{
    int c = blockIdx.x, t = threadIdx.x;
    const int n4 = Nn / 4, tot4 = Bb * n4;
    float s = 0.0f, sq = 0.0f;
    #pragma unroll 4
    for (int idx = t; idx < tot4; idx += 256) {
        int b = idx / n4, i = idx - b * n4;
        float4 v = *(const float4*)(Y + ((size_t)b * Cc + c) * Nn + i * 4);
        s  += (v.x + v.y) + (v.z + v.w);
        sq += (v.x * v.x + v.y * v.y) + (v.z * v.z + v.w * v.w);
    }
    s = block_reduce(s, 1);
    sq = block_reduce(sq, 1);
    if (t == 0) {
        const float invN = 1.0f / (float)(Bb * Nn);
        float mean = s * invN;
        float var  = sq * invN - mean * mean;
        float sc = gamma[c] * rsqrtf(var + EPSv);
        g_scale[c] = sc;
        g_shift[c] = beta[c] - mean * sc;
    }
}

__global__ __launch_bounds__(256) void k_bn_apply_add(
    const float* __restrict__ Y, const float* __restrict__ R, float* __restrict__ out)
{
    size_t i4 = (size_t)blockIdx.x * blockDim.x + threadIdx.x;
    const size_t total4 = (size_t)Bb * Cc * Nn / 4;
    if (i4 >= total4) return;
    int c = (int)((i4 * 4 / Nn) % Cc);
    float4 y = ((const float4*)Y)[i4];
    float4 r = ((const float4*)R)[i4];
    float sc = g_scale[c], sh = g_shift[c];
    float4 o;
    o.x = fmaf(sc, y.x, sh) + r.x;
    o.y = fmaf(sc, y.y, sh) + r.y;
    o.z = fmaf(sc, y.z, sh) + r.z;
    o.w = fmaf(sc, y.w, sh) + r.w;
    ((float4*)out)[i4] = o;
}

// ---------------------------------------------------------------------------
extern "C" void kernel_launch(void* const* d_in, const int* in_sizes, int n_in,
                              void* d_out, int out_size)
{
    const float* x      = (const float*)d_in[0];
    const float* dis    = (const float*)d_in[1];
    const float* gamma1 = (const float*)d_in[2];
    const float* beta1  = (const float*)d_in[3];
    const float* gamma2 = (const float*)d_in[4];
    const float* beta2  = (const float*)d_in[5];
    float* out = (float*)d_out;

    float *pF, *pY, *pZ, *pY2, *pF2;
    cudaGetSymbolAddress((void**)&pF,  g_F);
    cudaGetSymbolAddress((void**)&pY,  g_Y);
    cudaGetSymbolAddress((void**)&pZ,  g_Z);
    cudaGetSymbolAddress((void**)&pY2, g_Y2);
    cudaGetSymbolAddress((void**)&pF2, g_F2);
    h16 *pXh,*pXTh,*pXTl,*pZh,*pZl,*pZTh,*pZTl,*pFh,*pFl,*pF2h;
    cudaGetSymbolAddress((void**)&pXh,  g_Xh);
    cudaGetSymbolAddress((void**)&pXTh, g_XTh); cudaGetSymbolAddress((void**)&pXTl, g_XTl);
    cudaGetSymbolAddress((void**)&pZh,  g_Zh);  cudaGetSymbolAddress((void**)&pZl,  g_Zl);
    cudaGetSymbolAddress((void**)&pZTh, g_ZTh); cudaGetSymbolAddress((void**)&pZTl, g_ZTl);
    cudaGetSymbolAddress((void**)&pFh,  g_Fh);  cudaGetSymbolAddress((void**)&pFl,  g_Fl);
    cudaGetSymbolAddress((void**)&pF2h, g_F2h);

    const int SMEM = 49152;   // 2 bufs x 3 segs x 8192B
    static bool attr_set = false;
    if (!attr_set) {
        cudaFuncSetAttribute(k_mma_hmma, cudaFuncAttributeMaxDynamicSharedMemorySize, SMEM);
        attr_set = true;
    }

    const size_t sX  = (size_t)Cc * Kp1;   // X/Z hi-lo per-batch
    const size_t sXT = (size_t)Nn * Cc;    // XT/ZT
    const size_t sFb = (size_t)Nn * Kp1;   // F hi/lo
    const size_t sF  = (size_t)Nn * Nn;    // F fp32
    const size_t sYb = (size_t)Cc * Nn;    // Y/Z/Y2 fp32
    const size_t sF2 = (size_t)Cc * Cc;

    // 0) split X -> Xh (hi only, Kp=320) + XT hi/lo (K=1024)
    k_split_both<<<dim3(Nn / 32, Cc / 32, Bb), dim3(32, 8)>>>(
        x, pXh, nullptr, Kp1, pXTh, pXTl, Cc, Cc, Nn);

    // 1) F = XT·XTᵀ / 32   (M=N=288, K=1024)
    k_mma_hmma<<<dim3(3, 3, Bb), 128, SMEM>>>(
        pXTh, pXTh, pXTl, pF, Nn, Nn, Cc, sXT, sXT, sF, 0.03125f);

    // 2) softmax+prior -> F hi/lo (Kp=320)
    k_softmax_prior<<<dim3(Nn, Bb), 288>>>(dis);

    // 3) Y = X·Fᵀ          (M=1024, N=288, Kp=320)
    k_mma_hmma<<<dim3(3, 8, Bb), 128, SMEM>>>(
        pXh, pFh, pFl, pY, Cc, Nn, Kp1, sX, sFb, sYb, 1.0f);

    // 4) BN1 + residual
    k_bnstats<<<Cc, 256>>>(pY, gamma1, beta1);
    k_bn_apply_add<<<(int)(((size_t)Bb * Cc * Nn / 4 + 255) / 256), 256>>>(pY, x, pZ);

    // 5) split Z -> Zh/Zl (Kp=320) + ZT hi/lo (K=1024)
    k_split_both<<<dim3(Nn / 32, Cc / 32, Bb), dim3(32, 8)>>>(
        pZ, pZh, pZl, Kp1, pZTh, pZTl, Cc, Cc, Nn);

    // 6) F2 = Z·Zᵀ         (M=N=1024, Kp=320)
    k_mma_hmma<<<dim3(8, 8, Bb), 128, SMEM>>>(
        pZh, pZh, pZl, pF2, Cc, Cc, Kp1, sX, sX, sF2, 1.0f);

    // 7) softmax rows of F2 -> F2 hi
    k_softmax_chan<<<Bb * Cc, 256>>>();

    // 8) Y2 = F2·ZTᵀ       (M=1024, N=288, K=1024)
    k_mma_hmma<<<dim3(3, 8, Bb), 128, SMEM>>>(
        pF2h, pZTh, pZTl, pY2, Cc, Nn, Cc, sF2, sXT, sYb, 1.0f);

    // 9) BN2 + residual -> out
    k_bnstats<<<Cc, 256>>>(pY2, gamma2, beta2);
    k_bn_apply_add<<<(int)(((size_t)Bb * Cc * Nn / 4 + 255) / 256), 256>>>(pY2, pZ, out);
}

// round 8
// speedup vs baseline: 3.6652x; 1.1476x over previous
#include <cuda_runtime.h>
#include <cuda_fp16.h>
#include <math.h>
#include <stdint.h>

#define Bb   128
#define Cc   1024
#define Nn   288
#define Kp1  320            // padded K for K=288 (multiple of 32)
#define EPSv 1e-5f

typedef __half h16;

// fp32 scratch
__device__ float g_F [(size_t)Bb * Nn * Nn];
__device__ float g_Y [(size_t)Bb * Cc * Nn];
__device__ float g_Z [(size_t)Bb * Cc * Nn];
__device__ float g_Y2[(size_t)Bb * Cc * Nn];
__device__ float g_F2[(size_t)Bb * Cc * Cc];
__device__ float g_scale[Cc];
__device__ float g_shift[Cc];
// fp16 hi/lo K-major operands (pads stay zero: zero-init, never written)
__device__ h16 g_Xh [(size_t)Bb * Cc * Kp1];
__device__ h16 g_XTh[(size_t)Bb * Nn * Cc];
__device__ h16 g_XTl[(size_t)Bb * Nn * Cc];
__device__ h16 g_Zh [(size_t)Bb * Cc * Kp1];
__device__ h16 g_Zl [(size_t)Bb * Cc * Kp1];
__device__ h16 g_ZTh[(size_t)Bb * Nn * Cc];
__device__ h16 g_ZTl[(size_t)Bb * Nn * Cc];
__device__ h16 g_Fh [(size_t)Bb * Nn * Kp1];
__device__ h16 g_Fl [(size_t)Bb * Nn * Kp1];
__device__ h16 g_F2h[(size_t)Bb * Cc * Cc];

// ---------------- helpers ----------------
__device__ __forceinline__ uint32_t smem_u32(const void* p) {
    uint32_t a;
    asm("{ .reg .u64 t; cvta.to.shared.u64 t, %1; cvt.u32.u64 %0, t; }" : "=r"(a) : "l"(p));
    return a;
}
__device__ __forceinline__ void split_h16(float x, h16& h, h16& l) {
    h = __float2half(x);
    l = __float2half(x - __half2float(h));
}

#define LDMX4(r, a) \
    asm volatile("ldmatrix.sync.aligned.m8n8.x4.shared.b16 {%0,%1,%2,%3}, [%4];" \
        : "=r"((r)[0]), "=r"((r)[1]), "=r"((r)[2]), "=r"((r)[3]) : "r"(a))

__device__ __forceinline__ void mma16816(float* c, const uint32_t* a, const uint32_t* b) {
    asm volatile("mma.sync.aligned.m16n8k16.row.col.f32.f16.f16.f32 "
        "{%0,%1,%2,%3}, {%4,%5,%6,%7}, {%8,%9}, {%0,%1,%2,%3};"
        : "+f"(c[0]), "+f"(c[1]), "+f"(c[2]), "+f"(c[3])
        : "r"(a[0]), "r"(a[1]), "r"(a[2]), "r"(a[3]), "r"(b[0]), "r"(b[1]));
}

#define CP_ASYNC(dst, src, sz) \
    asm volatile("cp.async.cg.shared.global [%0], [%1], 16, %2;" \
        :: "r"(dst), "l"(src), "r"(sz) : "memory")
#define CP_COMMIT() asm volatile("cp.async.commit_group;" ::: "memory")
#define CP_WAIT1()  asm volatile("cp.async.wait_group 1;" ::: "memory")
#define CP_WAIT0()  asm volatile("cp.async.wait_group 0;" ::: "memory")

// ---------------- block reduce ----------------
__device__ __forceinline__ float block_reduce(float v, int op) {
    __shared__ float red[32];
    #pragma unroll
    for (int o = 16; o > 0; o >>= 1) {
        float u = __shfl_xor_sync(0xffffffffu, v, o);
        v = op ? (v + u) : fmaxf(v, u);
    }
    int lane = threadIdx.x & 31, wid = threadIdx.x >> 5;
    int nw = (blockDim.x + 31) >> 5;
    if (lane == 0) red[wid] = v;
    __syncthreads();
    if (wid == 0) {
        float r = (lane < nw) ? red[lane] : (op ? 0.0f : -3.4e38f);
        #pragma unroll
        for (int o = 16; o > 0; o >>= 1) {
            float u = __shfl_xor_sync(0xffffffffu, r, o);
            r = op ? (r + u) : fmaxf(r, u);
        }
        if (lane == 0) red[0] = r;
    }
    __syncthreads();
    float r = red[0];
    __syncthreads();
    return r;
}

// ---------------------------------------------------------------------------
// HMMA GEMM: C[b,m,n] = alpha * sum_k A[m,k]*B[n,k]
//   THREE=false: Ah*Bh + Ah*Bl        (drop Al*Bh, ~2^-11)
//   THREE=true : Ah*Bh + Ah*Bl + Al*Bh (drop Al*Bl, ~2^-22)
// SYM: C symmetric (M==Nd): skip blocks with bx<by, mirror-write bx>by.
// Block tile 128 x NTILE x 32; 128 threads; 4 warps 2x2; warp tile 64 x NTILE/2.
// ---------------------------------------------------------------------------
template<int NTILE, bool THREE, bool SYM>
__global__ __launch_bounds__(128, 2) void k_mma(
    const h16* __restrict__ Ah, const h16* __restrict__ Al,
    const h16* __restrict__ Bh, const h16* __restrict__ Bl,
    float* __restrict__ Cd, int M, int Nd, int Kp, int n_off,
    size_t sA, size_t sB, size_t sC, float alpha)
{
    constexpr int ABYTES = 8192 * (THREE ? 2 : 1);
    constexpr int BSEG   = NTILE * 64;
    constexpr int BUF    = ABYTES + 2 * BSEG;
    constexpr int A_CH   = THREE ? 1024 : 512;   // 16B chunks in A region
    constexpr int CH     = A_CH + NTILE * 8;
    constexpr int PER_T  = CH / 128;
    constexpr int NI     = NTILE / 16;           // n-frags per warp
    constexpr int G      = (NI > 4) ? 4 : NI;    // frags per group
    constexpr int NG     = NI / G;

    extern __shared__ __align__(16) char dsm[];
    const int bx = blockIdx.x, by = blockIdx.y, bz = blockIdx.z;
    if (SYM && bx < by) return;
    const int m0 = by * 128, n0 = n_off + bx * NTILE;
    const int t = threadIdx.x;
    const int lane = t & 31, warp = t >> 5;
    const int mbase = (warp >> 1) * 64, nbase = (warp & 1) * (NTILE / 2);

    const h16* Abh = Ah + (size_t)bz * sA;
    const h16* Abl = Al + (size_t)bz * sA;
    const h16* Bbh = Bh + (size_t)bz * sB;
    const h16* Bbl = Bl + (size_t)bz * sB;

    const uint32_t sbase = smem_u32(dsm);
    auto sw = [](int row, int chunk) -> uint32_t {
        return (uint32_t)((row * 4 + (chunk ^ (row & 3))) * 16);
    };

    auto stage = [&](int buf, int k0) {
        #pragma unroll
        for (int i = 0; i < PER_T; i++) {
            int idx = t + i * 128;
            const h16* base; int g, row, chunk; uint32_t dstoff; bool valid;
            if (idx < A_CH) {
                int hl = THREE ? (idx >> 9) : 0;
                int r = idx & 511;
                row = r >> 2; chunk = r & 3;
                base = hl ? Abl : Abh;
                g = m0 + row; valid = g < M;
                dstoff = hl * 8192 + sw(row, chunk);
            } else {
                int idxb = idx - A_CH;
                int hl = idxb >= NTILE * 4;
                int r = idxb - hl * NTILE * 4;
                row = r >> 2; chunk = r & 3;
                base = hl ? Bbl : Bbh;
                g = n0 + row; valid = g < Nd;
                dstoff = ABYTES + hl * BSEG + sw(row, chunk);
            }
            CP_ASYNC(sbase + buf * BUF + dstoff,
                     base + (size_t)g * Kp + k0 + chunk * 8, valid ? 16 : 0);
        }
        CP_COMMIT();
    };

    float acc[4][NI][4];
    #pragma unroll
    for (int mi = 0; mi < 4; mi++)
        #pragma unroll
        for (int ni = 0; ni < NI; ni++)
            #pragma unroll
            for (int q = 0; q < 4; q++) acc[mi][ni][q] = 0.0f;

    const int nk = Kp / 32;
    stage(0, 0);

    for (int kt = 0; kt < nk; kt++) {
        const int buf = kt & 1;
        if (kt + 1 < nk) { stage(buf ^ 1, (kt + 1) * 32); CP_WAIT1(); }
        else             { CP_WAIT0(); }
        __syncthreads();
        const uint32_t bb = sbase + buf * BUF;

        #pragma unroll
        for (int s = 0; s < 2; s++) {
            const int c0 = s * 2;
            const int arow = (lane & 15), achk = c0 + (lane >> 4);
            const int brow = (lane & 7) + ((lane & 16) >> 1);
            const int bchk = c0 + ((lane >> 3) & 1);

            uint32_t ah[4][4], al[THREE ? 4 : 1][4];
            #pragma unroll
            for (int mi = 0; mi < 4; mi++) {
                LDMX4(ah[mi], bb + sw(mbase + mi * 16 + arow, achk));
                if (THREE)
                    LDMX4(al[mi], bb + 8192 + sw(mbase + mi * 16 + arow, achk));
            }

            #pragma unroll
            for (int grp = 0; grp < NG; grp++) {
                uint32_t bh[G][2], bl[G][2];
                #pragma unroll
                for (int h = 0; h < G / 2; h++) {
                    uint32_t r4[4];
                    int rw = nbase + grp * (G * 8) + h * 16 + brow;
                    LDMX4(r4, bb + ABYTES + sw(rw, bchk));
                    bh[h*2][0] = r4[0]; bh[h*2][1] = r4[1];
                    bh[h*2+1][0] = r4[2]; bh[h*2+1][1] = r4[3];
                    LDMX4(r4, bb + ABYTES + BSEG + sw(rw, bchk));
                    bl[h*2][0] = r4[0]; bl[h*2][1] = r4[1];
                    bl[h*2+1][0] = r4[2]; bl[h*2+1][1] = r4[3];
                }
                #pragma unroll
                for (int mi = 0; mi < 4; mi++)
                    #pragma unroll
                    for (int nj = 0; nj < G; nj++) {
                        float* a = acc[mi][grp * G + nj];
                        mma16816(a, ah[mi], bh[nj]);            // hi*hi
                        mma16816(a, ah[mi], bl[nj]);            // hi*lo
                        if (THREE) mma16816(a, al[mi], bh[nj]); // lo*hi
                    }
            }
        }
        __syncthreads();
    }

    // epilogue (+ mirror for SYM off-diagonal blocks)
    float* cb = Cd + (size_t)bz * sC;
    #pragma unroll
    for (int mi = 0; mi < 4; mi++) {
        #pragma unroll
        for (int ni = 0; ni < NI; ni++) {
            int row = m0 + mbase + mi * 16 + (lane >> 2);
            int col = n0 + nbase + ni * 8 + (lane & 3) * 2;
            float v0 = acc[mi][ni][0] * alpha, v1 = acc[mi][ni][1] * alpha;
            float v2 = acc[mi][ni][2] * alpha, v3 = acc[mi][ni][3] * alpha;
            if (col < Nd) {
                if (row < M)
                    *(float2*)(cb + (size_t)row * Nd + col) = make_float2(v0, v1);
                if (row + 8 < M)
                    *(float2*)(cb + (size_t)(row + 8) * Nd + col) = make_float2(v2, v3);
            }
            if (SYM && bx > by && col < M && row < Nd) {
                cb[(size_t)col * Nd + row] = v0;
                cb[(size_t)(col + 1) * Nd + row] = v1;
                if (row + 8 < Nd) {
                    cb[(size_t)col * Nd + row + 8] = v2;
                    cb[(size_t)(col + 1) * Nd + row + 8] = v3;
                }
            }
        }
    }
}

// ---------------------------------------------------------------------------
// fp32 (rows x cols) -> direct hi[/lo] (stride ds) + transposed hi/lo (stride ts)
// ---------------------------------------------------------------------------
__global__ __launch_bounds__(256) void k_split_both(
    const float* __restrict__ src,
    h16* __restrict__ dh, h16* __restrict__ dl, int ds,
    h16* __restrict__ th, h16* __restrict__ tl, int ts,
    int rows, int cols)
{
    __shared__ float tile[32][33];
    const int b = blockIdx.z;
    const int c0 = blockIdx.x * 32, r0 = blockIdx.y * 32;
    const float* s = src + (size_t)b * rows * cols;
    const size_t dbs = (size_t)b * rows * ds;
    const size_t tbs = (size_t)b * cols * ts;

    #pragma unroll
    for (int i = 0; i < 4; i++) {
        int r = r0 + threadIdx.y + i * 8, c = c0 + threadIdx.x;
        float v = s[(size_t)r * cols + c];
        tile[threadIdx.y + i * 8][threadIdx.x] = v;
        h16 h, l; split_h16(v, h, l);
        size_t o = dbs + (size_t)r * ds + c;
        dh[o] = h;
        if (dl) dl[o] = l;
    }
    __syncthreads();
    #pragma unroll
    for (int i = 0; i < 4; i++) {
        int tr = c0 + threadIdx.y + i * 8, tc = r0 + threadIdx.x;
        float v = tile[threadIdx.x][threadIdx.y + i * 8];
        h16 h, l; split_h16(v, h, l);
        size_t o = tbs + (size_t)tr * ts + tc;
        th[o] = h; tl[o] = l;
    }
}

// ---------------------------------------------------------------------------
__global__ __launch_bounds__(288) void k_softmax_prior(const float* __restrict__ dis)
{
    int p = blockIdx.x, b = blockIdx.y, t = threadIdx.x;
    const float* f = g_F + ((size_t)b * Nn + p) * Nn;
    float v = f[t];
    float m1 = block_reduce(v, 0);
    float e1 = __expf(v - m1);
    float s1 = block_reduce(e1, 1);
    float w  = (e1 / s1) * dis[(size_t)p * Nn + t];
    float m2 = block_reduce(w, 0);
    float e2 = __expf(w - m2);
    float s2 = block_reduce(e2, 1);
    h16 h, l; split_h16(e2 / s2, h, l);
    size_t o = ((size_t)b * Nn + p) * Kp1 + t;
    g_Fh[o] = h; g_Fl[o] = l;
}

__global__ __launch_bounds__(256) void k_softmax_chan()
{
    size_t row = blockIdx.x;
    const float* f = g_F2 + row * (size_t)Cc;
    int t = threadIdx.x;
    float v[4];
    #pragma unroll
    for (int i = 0; i < 4; i++) v[i] = f[t + 256 * i];
    float m = block_reduce(fmaxf(fmaxf(v[0], v[1]), fmaxf(v[2], v[3])), 0);
    float e[4], ls = 0.0f;
    #pragma unroll
    for (int i = 0; i < 4; i++) { e[i] = __expf(v[i] - m); ls += e[i]; }
    float s = block_reduce(ls, 1);
    float inv = 1.0f / s;
    #pragma unroll
    for (int i = 0; i < 4; i++)
        g_F2h[row * (size_t)Cc + t + 256 * i] = __float2half(e[i] * inv);
}

__global__ __launch_bounds__(256) void k_bnstats(
    const float* __restrict__ Y,
    const float* __restrict__ gamma, const float* __restrict__ beta)
{
    int c = blockIdx.x, t = threadIdx.x;
    const int n4 = Nn / 4, tot4 = Bb * n4;
    float s = 0.0f, sq = 0.0f;
    #pragma unroll 4
    for (int idx = t; idx < tot4; idx += 256) {
        int b = idx / n4, i = idx - b * n4;
        float4 v = *(const float4*)(Y + ((size_t)b * Cc + c) * Nn + i * 4);
        s  += (v.x + v.y) + (v.z + v.w);
        sq += (v.x * v.x + v.y * v.y) + (v.z * v.z + v.w * v.w);
    }
    s = block_reduce(s, 1);
    sq = block_reduce(sq, 1);
    if (t == 0) {
        const float invN = 1.0f / (float)(Bb * Nn);
        float mean = s * invN;
        float var  = sq * invN - mean * mean;
        float sc = gamma[c] * rsqrtf(var + EPSv);
        g_scale[c] = sc;
        g_shift[c] = beta[c] - mean * sc;
    }
}

__global__ __launch_bounds__(256) void k_bn_apply_add(
    const float* __restrict__ Y, const float* __restrict__ R, float* __restrict__ out)
{
    size_t i4 = (size_t)blockIdx.x * blockDim.x + threadIdx.x;
    const size_t total4 = (size_t)Bb * Cc * Nn / 4;
    if (i4 >= total4) return;
    int c = (int)((i4 * 4 / Nn) % Cc);
    float4 y = ((const float4*)Y)[i4];
    float4 r = ((const float4*)R)[i4];
    float sc = g_scale[c], sh = g_shift[c];
    float4 o;
    o.x = fmaf(sc, y.x, sh) + r.x;
    o.y = fmaf(sc, y.y, sh) + r.y;
    o.z = fmaf(sc, y.z, sh) + r.z;
    o.w = fmaf(sc, y.w, sh) + r.w;
    ((float4*)out)[i4] = o;
}

// ---------------------------------------------------------------------------
extern "C" void kernel_launch(void* const* d_in, const int* in_sizes, int n_in,
                              void* d_out, int out_size)
{
    const float* x      = (const float*)d_in[0];
    const float* dis    = (const float*)d_in[1];
    const float* gamma1 = (const float*)d_in[2];
    const float* beta1  = (const float*)d_in[3];
    const float* gamma2 = (const float*)d_in[4];
    const float* beta2  = (const float*)d_in[5];
    float* out = (float*)d_out;

    float *pF, *pY, *pZ, *pY2, *pF2;
    cudaGetSymbolAddress((void**)&pF,  g_F);
    cudaGetSymbolAddress((void**)&pY,  g_Y);
    cudaGetSymbolAddress((void**)&pZ,  g_Z);
    cudaGetSymbolAddress((void**)&pY2, g_Y2);
    cudaGetSymbolAddress((void**)&pF2, g_F2);
    h16 *pXh,*pXTh,*pXTl,*pZh,*pZl,*pZTh,*pZTl,*pFh,*pFl,*pF2h;
    cudaGetSymbolAddress((void**)&pXh,  g_Xh);
    cudaGetSymbolAddress((void**)&pXTh, g_XTh); cudaGetSymbolAddress((void**)&pXTl, g_XTl);
    cudaGetSymbolAddress((void**)&pZh,  g_Zh);  cudaGetSymbolAddress((void**)&pZl,  g_Zl);
    cudaGetSymbolAddress((void**)&pZTh, g_ZTh); cudaGetSymbolAddress((void**)&pZTl, g_ZTl);
    cudaGetSymbolAddress((void**)&pFh,  g_Fh);  cudaGetSymbolAddress((void**)&pFl,  g_Fl);
    cudaGetSymbolAddress((void**)&pF2h, g_F2h);

    const int SM3 = 2 * (16384 + 2 * 8192);   // THREE, NTILE=128: 65536
    const int SM2 = 2 * (8192 + 2 * 8192);    // 2-pass, NTILE=128: 49152
    const int SMT = 2 * (8192 + 2 * 2048);    // 2-pass, NTILE=32:  24576
    static bool attr_set = false;
    if (!attr_set) {
        cudaFuncSetAttribute((const void*)k_mma<128, true,  true >,
                             cudaFuncAttributeMaxDynamicSharedMemorySize, SM3);
        cudaFuncSetAttribute((const void*)k_mma<128, false, false>,
                             cudaFuncAttributeMaxDynamicSharedMemorySize, SM2);
        cudaFuncSetAttribute((const void*)k_mma<32,  false, false>,
                             cudaFuncAttributeMaxDynamicSharedMemorySize, SMT);
        attr_set = true;
    }

    const size_t sX  = (size_t)Cc * Kp1;
    const size_t sXT = (size_t)Nn * Cc;
    const size_t sFb = (size_t)Nn * Kp1;
    const size_t sF  = (size_t)Nn * Nn;
    const size_t sYb = (size_t)Cc * Nn;
    const size_t sF2 = (size_t)Cc * Cc;

    // 0) split X -> Xh (hi only, Kp=320) + XT hi/lo (K=1024)
    k_split_both<<<dim3(Nn / 32, Cc / 32, Bb), dim3(32, 8)>>>(
        x, pXh, nullptr, Kp1, pXTh, pXTl, Cc, Cc, Nn);

    // 1) F = XT·XTᵀ / 32  (sym, 3-pass)  M=N=288, K=1024
    k_mma<128, true, true><<<dim3(3, 3, Bb), 128, SM3>>>(
        pXTh, pXTl, pXTh, pXTl, pF, Nn, Nn, Cc, 0, sXT, sXT, sF, 0.03125f);

    // 2) softmax+prior -> F hi/lo (Kp=320)
    k_softmax_prior<<<dim3(Nn, Bb), 288>>>(dis);

    // 3) Y = X·Fᵀ  (2-pass)  M=1024, N=288, Kp=320: full tiles + 32-wide tail
    k_mma<128, false, false><<<dim3(2, 8, Bb), 128, SM2>>>(
        pXh, pXh, pFh, pFl, pY, Cc, Nn, Kp1, 0, sX, sFb, sYb, 1.0f);
    k_mma<32, false, false><<<dim3(1, 8, Bb), 128, SMT>>>(
        pXh, pXh, pFh, pFl, pY, Cc, Nn, Kp1, 256, sX, sFb, sYb, 1.0f);

    // 4) BN1 + residual
    k_bnstats<<<Cc, 256>>>(pY, gamma1, beta1);
    k_bn_apply_add<<<(int)(((size_t)Bb * Cc * Nn / 4 + 255) / 256), 256>>>(pY, x, pZ);

    // 5) split Z -> Zh/Zl (Kp=320) + ZT hi/lo (K=1024)
    k_split_both<<<dim3(Nn / 32, Cc / 32, Bb), dim3(32, 8)>>>(
        pZ, pZh, pZl, Kp1, pZTh, pZTl, Cc, Cc, Nn);

    // 6) F2 = Z·Zᵀ  (sym, 3-pass)  M=N=1024, Kp=320
    k_mma<128, true, true><<<dim3(8, 8, Bb), 128, SM3>>>(
        pZh, pZl, pZh, pZl, pF2, Cc, Cc, Kp1, 0, sX, sX, sF2, 1.0f);

    // 7) softmax rows of F2 -> F2 hi
    k_softmax_chan<<<Bb * Cc, 256>>>();

    // 8) Y2 = F2·ZTᵀ  (2-pass)  M=1024, N=288, K=1024: full tiles + tail
    k_mma<128, false, false><<<dim3(2, 8, Bb), 128, SM2>>>(
        pF2h, pF2h, pZTh, pZTl, pY2, Cc, Nn, Cc, 0, sF2, sXT, sYb, 1.0f);
    k_mma<32, false, false><<<dim3(1, 8, Bb), 128, SMT>>>(
        pF2h, pF2h, pZTh, pZTl, pY2, Cc, Nn, Cc, 256, sF2, sXT, sYb, 1.0f);

    // 9) BN2 + residual -> out
    k_bnstats<<<Cc, 256>>>(pY2, gamma2, beta2);
    k_bn_apply_add<<<(int)(((size_t)Bb * Cc * Nn / 4 + 255) / 256), 256>>>(pY2, pZ, out);
}

// round 9
// speedup vs baseline: 3.8922x; 1.0619x over previous
#include <cuda_runtime.h>
#include <cuda_fp16.h>
#include <math.h>
#include <stdint.h>

#define Bb   128
#define Cc   1024
#define Nn   288
#define Kp1  320            // padded K for K=288 (multiple of 32)
#define EPSv 1e-5f

typedef __half h16;

// fp32 scratch
__device__ float g_F [(size_t)Bb * Nn * Nn];
__device__ float g_Y [(size_t)Bb * Cc * Nn];
__device__ float g_Z [(size_t)Bb * Cc * Nn];
__device__ float g_Y2[(size_t)Bb * Cc * Nn];
__device__ float g_F2[(size_t)Bb * Cc * Cc];
__device__ float g_scale[Cc];
__device__ float g_shift[Cc];
// fp16 hi/lo K-major operands (pads stay zero: zero-init, never written)
__device__ h16 g_Xh [(size_t)Bb * Cc * Kp1];
__device__ h16 g_XTh[(size_t)Bb * Nn * Cc];
__device__ h16 g_XTl[(size_t)Bb * Nn * Cc];
__device__ h16 g_Zh [(size_t)Bb * Cc * Kp1];
__device__ h16 g_Zl [(size_t)Bb * Cc * Kp1];
__device__ h16 g_ZTh[(size_t)Bb * Nn * Cc];
__device__ h16 g_ZTl[(size_t)Bb * Nn * Cc];
__device__ h16 g_Fh [(size_t)Bb * Nn * Kp1];
__device__ h16 g_Fl [(size_t)Bb * Nn * Kp1];
__device__ h16 g_F2h[(size_t)Bb * Cc * Cc];

// ---------------- helpers ----------------
__device__ __forceinline__ uint32_t smem_u32(const void* p) {
    uint32_t a;
    asm("{ .reg .u64 t; cvta.to.shared.u64 t, %1; cvt.u32.u64 %0, t; }" : "=r"(a) : "l"(p));
    return a;
}
__device__ __forceinline__ void split_h16(float x, h16& h, h16& l) {
    h = __float2half(x);
    l = __float2half(x - __half2float(h));
}

#define LDMX4(r, a) \
    asm volatile("ldmatrix.sync.aligned.m8n8.x4.shared.b16 {%0,%1,%2,%3}, [%4];" \
        : "=r"((r)[0]), "=r"((r)[1]), "=r"((r)[2]), "=r"((r)[3]) : "r"(a))

__device__ __forceinline__ void mma16816(float* c, const uint32_t* a, const uint32_t* b) {
    asm volatile("mma.sync.aligned.m16n8k16.row.col.f32.f16.f16.f32 "
        "{%0,%1,%2,%3}, {%4,%5,%6,%7}, {%8,%9}, {%0,%1,%2,%3};"
        : "+f"(c[0]), "+f"(c[1]), "+f"(c[2]), "+f"(c[3])
        : "r"(a[0]), "r"(a[1]), "r"(a[2]), "r"(a[3]), "r"(b[0]), "r"(b[1]));
}

#define CP_ASYNC(dst, src, sz) \
    asm volatile("cp.async.cg.shared.global [%0], [%1], 16, %2;" \
        :: "r"(dst), "l"(src), "r"(sz) : "memory")
#define CP_COMMIT() asm volatile("cp.async.commit_group;" ::: "memory")
#define CP_WAIT2()  asm volatile("cp.async.wait_group 2;" ::: "memory")
#define CP_WAIT1()  asm volatile("cp.async.wait_group 1;" ::: "memory")
#define CP_WAIT0()  asm volatile("cp.async.wait_group 0;" ::: "memory")

// ---------------- block reduce ----------------
__device__ __forceinline__ float block_reduce(float v, int op) {
    __shared__ float red[32];
    #pragma unroll
    for (int o = 16; o > 0; o >>= 1) {
        float u = __shfl_xor_sync(0xffffffffu, v, o);
        v = op ? (v + u) : fmaxf(v, u);
    }
    int lane = threadIdx.x & 31, wid = threadIdx.x >> 5;
    int nw = (blockDim.x + 31) >> 5;
    if (lane == 0) red[wid] = v;
    __syncthreads();
    if (wid == 0) {
        float r = (lane < nw) ? red[lane] : (op ? 0.0f : -3.4e38f);
        #pragma unroll
        for (int o = 16; o > 0; o >>= 1) {
            float u = __shfl_xor_sync(0xffffffffu, r, o);
            r = op ? (r + u) : fmaxf(r, u);
        }
        if (lane == 0) red[0] = r;
    }
    __syncthreads();
    float r = red[0];
    __syncthreads();
    return r;
}

// ---------------------------------------------------------------------------
// HMMA GEMM (fp16 2-pass split): C[b,m,n] = alpha * sum_k A[m,k]*B[n,k]
//   C ~ Ah*Bh + Ah*Bl  (Al*Bh dropped: <=2^-11 relative — measured 6e-4 end2end)
// SYM: C symmetric (M==Nd): skip blocks with bx<by, mirror-write bx>by.
// Block tile 128 x NTILE x 32; 128 threads; 4 warps 2x2; warp tile 64 x NTILE/2.
// 3-stage cp.async pipeline.
// ---------------------------------------------------------------------------
template<int NTILE, bool SYM>
__global__ __launch_bounds__(128, 2) void k_mma(
    const h16* __restrict__ Ah,
    const h16* __restrict__ Bh, const h16* __restrict__ Bl,
    float* __restrict__ Cd, int M, int Nd, int Kp, int n_off,
    size_t sA, size_t sB, size_t sC, float alpha)
{
    constexpr int ABYTES = 8192;
    constexpr int BSEG   = NTILE * 64;
    constexpr int BUF    = ABYTES + 2 * BSEG;
    constexpr int A_CH   = 512;                  // 16B chunks in A region
    constexpr int CH     = A_CH + NTILE * 8;
    constexpr int PER_T  = CH / 128;
    constexpr int NI     = NTILE / 16;           // n-frags per warp
    constexpr int G      = (NI > 4) ? 4 : NI;
    constexpr int NG     = NI / G;

    extern __shared__ __align__(16) char dsm[];
    const int bx = blockIdx.x, by = blockIdx.y, bz = blockIdx.z;
    if (SYM && bx < by) return;
    const int m0 = by * 128, n0 = n_off + bx * NTILE;
    const int t = threadIdx.x;
    const int lane = t & 31, warp = t >> 5;
    const int mbase = (warp >> 1) * 64, nbase = (warp & 1) * (NTILE / 2);

    const h16* Abh = Ah + (size_t)bz * sA;
    const h16* Bbh = Bh + (size_t)bz * sB;
    const h16* Bbl = Bl + (size_t)bz * sB;

    const uint32_t sbase = smem_u32(dsm);
    auto sw = [](int row, int chunk) -> uint32_t {
        return (uint32_t)((row * 4 + (chunk ^ (row & 3))) * 16);
    };

    auto stage = [&](int buf, int k0) {
        #pragma unroll
        for (int i = 0; i < PER_T; i++) {
            int idx = t + i * 128;
            const h16* base; int g, row, chunk; uint32_t dstoff; bool valid;
            if (idx < A_CH) {
                row = idx >> 2; chunk = idx & 3;
                base = Abh;
                g = m0 + row; valid = g < M;
                dstoff = sw(row, chunk);
            } else {
                int idxb = idx - A_CH;
                int hl = idxb >= NTILE * 4;
                int r = idxb - hl * NTILE * 4;
                row = r >> 2; chunk = r & 3;
                base = hl ? Bbl : Bbh;
                g = n0 + row; valid = g < Nd;
                dstoff = ABYTES + hl * BSEG + sw(row, chunk);
            }
            CP_ASYNC(sbase + buf * BUF + dstoff,
                     base + (size_t)g * Kp + k0 + chunk * 8, valid ? 16 : 0);
        }
        CP_COMMIT();
    };

    float acc[4][NI][4];
    #pragma unroll
    for (int mi = 0; mi < 4; mi++)
        #pragma unroll
        for (int ni = 0; ni < NI; ni++)
            #pragma unroll
            for (int q = 0; q < 4; q++) acc[mi][ni][q] = 0.0f;

    const int nk = Kp / 32;
    stage(0, 0);
    if (nk > 1) stage(1, 32);

    for (int kt = 0; kt < nk; kt++) {
        const int buf = kt % 3;
        // stage two ahead (that slot was consumed at kt-1)
        if (kt + 2 < nk) { stage((kt + 2) % 3, (kt + 2) * 32); CP_WAIT2(); }
        else if (kt + 1 < nk) { CP_WAIT1(); }
        else { CP_WAIT0(); }
        __syncthreads();
        const uint32_t bb = sbase + buf * BUF;

        #pragma unroll
        for (int s = 0; s < 2; s++) {
            const int c0 = s * 2;
            const int arow = (lane & 15), achk = c0 + (lane >> 4);
            const int brow = (lane & 7) + ((lane & 16) >> 1);
            const int bchk = c0 + ((lane >> 3) & 1);

            uint32_t ah[4][4];
            #pragma unroll
            for (int mi = 0; mi < 4; mi++)
                LDMX4(ah[mi], bb + sw(mbase + mi * 16 + arow, achk));

            #pragma unroll
            for (int grp = 0; grp < NG; grp++) {
                uint32_t bh[G][2], bl[G][2];
                #pragma unroll
                for (int h = 0; h < G / 2; h++) {
                    uint32_t r4[4];
                    int rw = nbase + grp * (G * 8) + h * 16 + brow;
                    LDMX4(r4, bb + ABYTES + sw(rw, bchk));
                    bh[h*2][0] = r4[0]; bh[h*2][1] = r4[1];
                    bh[h*2+1][0] = r4[2]; bh[h*2+1][1] = r4[3];
                    LDMX4(r4, bb + ABYTES + BSEG + sw(rw, bchk));
                    bl[h*2][0] = r4[0]; bl[h*2][1] = r4[1];
                    bl[h*2+1][0] = r4[2]; bl[h*2+1][1] = r4[3];
                }
                #pragma unroll
                for (int mi = 0; mi < 4; mi++)
                    #pragma unroll
                    for (int nj = 0; nj < G; nj++) {
                        float* a = acc[mi][grp * G + nj];
                        mma16816(a, ah[mi], bh[nj]);   // hi*hi
                        mma16816(a, ah[mi], bl[nj]);   // hi*lo
                    }
            }
        }
        __syncthreads();
    }

    // epilogue (+ mirror for SYM off-diagonal blocks)
    float* cb = Cd + (size_t)bz * sC;
    #pragma unroll
    for (int mi = 0; mi < 4; mi++) {
        #pragma unroll
        for (int ni = 0; ni < NI; ni++) {
            int row = m0 + mbase + mi * 16 + (lane >> 2);
            int col = n0 + nbase + ni * 8 + (lane & 3) * 2;
            float v0 = acc[mi][ni][0] * alpha, v1 = acc[mi][ni][1] * alpha;
            float v2 = acc[mi][ni][2] * alpha, v3 = acc[mi][ni][3] * alpha;
            if (col < Nd) {
                if (row < M)
                    *(float2*)(cb + (size_t)row * Nd + col) = make_float2(v0, v1);
                if (row + 8 < M)
                    *(float2*)(cb + (size_t)(row + 8) * Nd + col) = make_float2(v2, v3);
            }
            if (SYM && bx > by && col < M && row < Nd) {
                cb[(size_t)col * Nd + row] = v0;
                cb[(size_t)(col + 1) * Nd + row] = v1;
                if (row + 8 < Nd) {
                    cb[(size_t)col * Nd + row + 8] = v2;
                    cb[(size_t)(col + 1) * Nd + row + 8] = v3;
                }
            }
        }
    }
}

// ---------------------------------------------------------------------------
// fp32 (rows x cols) -> direct hi[/lo] (stride ds) + transposed hi/lo (stride ts)
// ---------------------------------------------------------------------------
__global__ __launch_bounds__(256) void k_split_both(
    const float* __restrict__ src,
    h16* __restrict__ dh, h16* __restrict__ dl, int ds,
    h16* __restrict__ th, h16* __restrict__ tl, int ts,
    int rows, int cols)
{
    __shared__ float tile[32][33];
    const int b = blockIdx.z;
    const int c0 = blockIdx.x * 32, r0 = blockIdx.y * 32;
    const float* s = src + (size_t)b * rows * cols;
    const size_t dbs = (size_t)b * rows * ds;
    const size_t tbs = (size_t)b * cols * ts;

    #pragma unroll
    for (int i = 0; i < 4; i++) {
        int r = r0 + threadIdx.y + i * 8, c = c0 + threadIdx.x;
        float v = s[(size_t)r * cols + c];
        tile[threadIdx.y + i * 8][threadIdx.x] = v;
        h16 h, l; split_h16(v, h, l);
        size_t o = dbs + (size_t)r * ds + c;
        dh[o] = h;
        if (dl) dl[o] = l;
    }
    __syncthreads();
    #pragma unroll
    for (int i = 0; i < 4; i++) {
        int tr = c0 + threadIdx.y + i * 8, tc = r0 + threadIdx.x;
        float v = tile[threadIdx.x][threadIdx.y + i * 8];
        h16 h, l; split_h16(v, h, l);
        size_t o = tbs + (size_t)tr * ts + tc;
        th[o] = h; tl[o] = l;
    }
}

// ---------------------------------------------------------------------------
// Fused: Z = scale[c]*Y + shift[c] + X, plus fp16 hi/lo split of Z (direct,
// stride Kp1) and its transpose (stride Cc). rows=Cc (c), cols=Nn (n).
// ---------------------------------------------------------------------------
__global__ __launch_bounds__(256) void k_bn_res_split(
    const float* __restrict__ Y, const float* __restrict__ X, float* __restrict__ Z,
    h16* __restrict__ dh, h16* __restrict__ dl,
    h16* __restrict__ th, h16* __restrict__ tl)
{
    __shared__ float tile[32][33];
    const int b = blockIdx.z;
    const int c0 = blockIdx.x * 32, r0 = blockIdx.y * 32;
    const size_t fb = (size_t)b * Cc * Nn;
    const size_t dbs = (size_t)b * Cc * Kp1;
    const size_t tbs = (size_t)b * Nn * Cc;

    #pragma unroll
    for (int i = 0; i < 4; i++) {
        int r = r0 + threadIdx.y + i * 8, c = c0 + threadIdx.x;
        size_t off = fb + (size_t)r * Nn + c;
        float z = fmaf(g_scale[r], Y[off], g_shift[r]) + X[off];
        Z[off] = z;
        tile[threadIdx.y + i * 8][threadIdx.x] = z;
        h16 h, l; split_h16(z, h, l);
        size_t o = dbs + (size_t)r * Kp1 + c;
        dh[o] = h; dl[o] = l;
    }
    __syncthreads();
    #pragma unroll
    for (int i = 0; i < 4; i++) {
        int tr = c0 + threadIdx.y + i * 8, tc = r0 + threadIdx.x;
        float v = tile[threadIdx.x][threadIdx.y + i * 8];
        h16 h, l; split_h16(v, h, l);
        size_t o = tbs + (size_t)tr * Cc + tc;
        th[o] = h; tl[o] = l;
    }
}

// ---------------------------------------------------------------------------
__global__ __launch_bounds__(288) void k_softmax_prior(const float* __restrict__ dis)
{
    int p = blockIdx.x, b = blockIdx.y, t = threadIdx.x;
    const float* f = g_F + ((size_t)b * Nn + p) * Nn;
    float v = f[t];
    float m1 = block_reduce(v, 0);
    float e1 = __expf(v - m1);
    float s1 = block_reduce(e1, 1);
    float w  = (e1 / s1) * dis[(size_t)p * Nn + t];
    float m2 = block_reduce(w, 0);
    float e2 = __expf(w - m2);
    float s2 = block_reduce(e2, 1);
    h16 h, l; split_h16(e2 / s2, h, l);
    size_t o = ((size_t)b * Nn + p) * Kp1 + t;
    g_Fh[o] = h; g_Fl[o] = l;
}

__global__ __launch_bounds__(256) void k_softmax_chan()
{
    size_t row = blockIdx.x;
    const float* f = g_F2 + row * (size_t)Cc;
    int t = threadIdx.x;
    float v[4];
    #pragma unroll
    for (int i = 0; i < 4; i++) v[i] = f[t + 256 * i];
    float m = block_reduce(fmaxf(fmaxf(v[0], v[1]), fmaxf(v[2], v[3])), 0);
    float e[4], ls = 0.0f;
    #pragma unroll
    for (int i = 0; i < 4; i++) { e[i] = __expf(v[i] - m); ls += e[i]; }
    float s = block_reduce(ls, 1);
    float inv = 1.0f / s;
    #pragma unroll
    for (int i = 0; i < 4; i++)
        g_F2h[row * (size_t)Cc + t + 256 * i] = __float2half(e[i] * inv);
}

__global__ __launch_bounds__(256) void k_bnstats(
    const float* __restrict__ Y,
    const float* __restrict__ gamma, const float* __restrict__ beta)
{
    int c = blockIdx.x, t = threadIdx.x;
    const int n4 = Nn / 4, tot4 = Bb * n4;
    float s = 0.0f, sq = 0.0f;
    #pragma unroll 4
    for (int idx = t; idx < tot4; idx += 256) {
        int b = idx / n4, i = idx - b * n4;
        float4 v = *(const float4*)(Y + ((size_t)b * Cc + c) * Nn + i * 4);
        s  += (v.x + v.y) + (v.z + v.w);
        sq += (v.x * v.x + v.y * v.y) + (v.z * v.z + v.w * v.w);
    }
    s = block_reduce(s, 1);
    sq = block_reduce(sq, 1);
    if (t == 0) {
        const float invN = 1.0f / (float)(Bb * Nn);
        float mean = s * invN;
        float var  = sq * invN - mean * mean;
        float sc = gamma[c] * rsqrtf(var + EPSv);
        g_scale[c] = sc;
        g_shift[c] = beta[c] - mean * sc;
    }
}

__global__ __launch_bounds__(256) void k_bn_apply_add(
    const float* __restrict__ Y, const float* __restrict__ R, float* __restrict__ out)
{
    size_t i4 = (size_t)blockIdx.x * blockDim.x + threadIdx.x;
    const size_t total4 = (size_t)Bb * Cc * Nn / 4;
    if (i4 >= total4) return;
    int c = (int)((i4 * 4 / Nn) % Cc);
    float4 y = ((const float4*)Y)[i4];
    float4 r = ((const float4*)R)[i4];
    float sc = g_scale[c], sh = g_shift[c];
    float4 o;
    o.x = fmaf(sc, y.x, sh) + r.x;
    o.y = fmaf(sc, y.y, sh) + r.y;
    o.z = fmaf(sc, y.z, sh) + r.z;
    o.w = fmaf(sc, y.w, sh) + r.w;
    ((float4*)out)[i4] = o;
}

// ---------------------------------------------------------------------------
extern "C" void kernel_launch(void* const* d_in, const int* in_sizes, int n_in,
                              void* d_out, int out_size)
{
    const float* x      = (const float*)d_in[0];
    const float* dis    = (const float*)d_in[1];
    const float* gamma1 = (const float*)d_in[2];
    const float* beta1  = (const float*)d_in[3];
    const float* gamma2 = (const float*)d_in[4];
    const float* beta2  = (const float*)d_in[5];
    float* out = (float*)d_out;

    float *pF, *pY, *pZ, *pY2, *pF2;
    cudaGetSymbolAddress((void**)&pF,  g_F);
    cudaGetSymbolAddress((void**)&pY,  g_Y);
    cudaGetSymbolAddress((void**)&pZ,  g_Z);
    cudaGetSymbolAddress((void**)&pY2, g_Y2);
    cudaGetSymbolAddress((void**)&pF2, g_F2);
    h16 *pXh,*pXTh,*pXTl,*pZh,*pZl,*pZTh,*pZTl,*pFh,*pFl,*pF2h;
    cudaGetSymbolAddress((void**)&pXh,  g_Xh);
    cudaGetSymbolAddress((void**)&pXTh, g_XTh); cudaGetSymbolAddress((void**)&pXTl, g_XTl);
    cudaGetSymbolAddress((void**)&pZh,  g_Zh);  cudaGetSymbolAddress((void**)&pZl,  g_Zl);
    cudaGetSymbolAddress((void**)&pZTh, g_ZTh); cudaGetSymbolAddress((void**)&pZTl, g_ZTl);
    cudaGetSymbolAddress((void**)&pFh,  g_Fh);  cudaGetSymbolAddress((void**)&pFl,  g_Fl);
    cudaGetSymbolAddress((void**)&pF2h, g_F2h);

    const int SM2 = 3 * (8192 + 2 * 8192);    // NTILE=128, 3 stages: 73728
    const int SMT = 3 * (8192 + 2 * 2048);    // NTILE=32,  3 stages: 36864
    static bool attr_set = false;
    if (!attr_set) {
        cudaFuncSetAttribute((const void*)k_mma<128, true >,
                             cudaFuncAttributeMaxDynamicSharedMemorySize, SM2);
        cudaFuncSetAttribute((const void*)k_mma<128, false>,
                             cudaFuncAttributeMaxDynamicSharedMemorySize, SM2);
        cudaFuncSetAttribute((const void*)k_mma<32,  false>,
                             cudaFuncAttributeMaxDynamicSharedMemorySize, SMT);
        attr_set = true;
    }

    const size_t sX  = (size_t)Cc * Kp1;
    const size_t sXT = (size_t)Nn * Cc;
    const size_t sFb = (size_t)Nn * Kp1;
    const size_t sF  = (size_t)Nn * Nn;
    const size_t sYb = (size_t)Cc * Nn;
    const size_t sF2 = (size_t)Cc * Cc;

    // 0) split X -> Xh (hi only, Kp=320) + XT hi/lo (K=1024)
    k_split_both<<<dim3(Nn / 32, Cc / 32, Bb), dim3(32, 8)>>>(
        x, pXh, nullptr, Kp1, pXTh, pXTl, Cc, Cc, Nn);

    // 1) F = XT·XTᵀ / 32  (sym, 2-pass)  M=N=288, K=1024
    k_mma<128, true><<<dim3(3, 3, Bb), 128, SM2>>>(
        pXTh, pXTh, pXTl, pF, Nn, Nn, Cc, 0, sXT, sXT, sF, 0.03125f);

    // 2) softmax+prior -> F hi/lo (Kp=320)
    k_softmax_prior<<<dim3(Nn, Bb), 288>>>(dis);

    // 3) Y = X·Fᵀ  M=1024, N=288, Kp=320: full tiles + 32-wide tail
    k_mma<128, false><<<dim3(2, 8, Bb), 128, SM2>>>(
        pXh, pFh, pFl, pY, Cc, Nn, Kp1, 0, sX, sFb, sYb, 1.0f);
    k_mma<32, false><<<dim3(1, 8, Bb), 128, SMT>>>(
        pXh, pFh, pFl, pY, Cc, Nn, Kp1, 256, sX, sFb, sYb, 1.0f);

    // 4) BN1 stats + fused (residual + Z split direct/transposed)
    k_bnstats<<<Cc, 256>>>(pY, gamma1, beta1);
    k_bn_res_split<<<dim3(Nn / 32, Cc / 32, Bb), dim3(32, 8)>>>(
        pY, x, pZ, pZh, pZl, pZTh, pZTl);

    // 6) F2 = Z·Zᵀ  (sym, 2-pass)  M=N=1024, Kp=320
    k_mma<128, true><<<dim3(8, 8, Bb), 128, SM2>>>(
        pZh, pZh, pZl, pF2, Cc, Cc, Kp1, 0, sX, sX, sF2, 1.0f);

    // 7) softmax rows of F2 -> F2 hi
    k_softmax_chan<<<Bb * Cc, 256>>>();

    // 8) Y2 = F2·ZTᵀ  M=1024, N=288, K=1024: full tiles + tail
    k_mma<128, false><<<dim3(2, 8, Bb), 128, SM2>>>(
        pF2h, pZTh, pZTl, pY2, Cc, Nn, Cc, 0, sF2, sXT, sYb, 1.0f);
    k_mma<32, false><<<dim3(1, 8, Bb), 128, SMT>>>(
        pF2h, pZTh, pZTl, pY2, Cc, Nn, Cc, 256, sF2, sXT, sYb, 1.0f);

    // 9) BN2 + residual -> out
    k_bnstats<<<Cc, 256>>>(pY2, gamma2, beta2);
    k_bn_apply_add<<<(int)(((size_t)Bb * Cc * Nn / 4 + 255) / 256), 256>>>(pY2, pZ, out);
}

// round 10
// speedup vs baseline: 3.9065x; 1.0037x over previous
#include <cuda_runtime.h>
#include <cuda_fp16.h>
#include <math.h>
#include <stdint.h>

#define Bb   128
#define Cc   1024
#define Nn   288
#define Kp1  320            // padded K for K=288 (multiple of 32)
#define EPSv 1e-5f

typedef __half h16;

// fp32 scratch
__device__ float g_F [(size_t)Bb * Nn * Nn];
__device__ float g_Y [(size_t)Bb * Cc * Nn];
__device__ float g_Z [(size_t)Bb * Cc * Nn];
__device__ float g_Y2[(size_t)Bb * Cc * Nn];
__device__ float g_F2[(size_t)Bb * Cc * Cc];
__device__ float g_scale[Cc];
__device__ float g_shift[Cc];
// fp16 hi/lo K-major operands (pads stay zero: zero-init, never written)
__device__ h16 g_Xh [(size_t)Bb * Cc * Kp1];
__device__ h16 g_XTh[(size_t)Bb * Nn * Cc];
__device__ h16 g_XTl[(size_t)Bb * Nn * Cc];
__device__ h16 g_Zh [(size_t)Bb * Cc * Kp1];
__device__ h16 g_Zl [(size_t)Bb * Cc * Kp1];
__device__ h16 g_ZTh[(size_t)Bb * Nn * Cc];
__device__ h16 g_ZTl[(size_t)Bb * Nn * Cc];
__device__ h16 g_Fh [(size_t)Bb * Nn * Kp1];
__device__ h16 g_Fl [(size_t)Bb * Nn * Kp1];
__device__ h16 g_F2h[(size_t)Bb * Cc * Cc];

// ---------------- helpers ----------------
__device__ __forceinline__ uint32_t smem_u32(const void* p) {
    uint32_t a;
    asm("{ .reg .u64 t; cvta.to.shared.u64 t, %1; cvt.u32.u64 %0, t; }" : "=r"(a) : "l"(p));
    return a;
}
__device__ __forceinline__ void split_h16(float x, h16& h, h16& l) {
    h = __float2half(x);
    l = __float2half(x - __half2float(h));
}

#define LDMX4(r, a) \
    asm volatile("ldmatrix.sync.aligned.m8n8.x4.shared.b16 {%0,%1,%2,%3}, [%4];" \
        : "=r"((r)[0]), "=r"((r)[1]), "=r"((r)[2]), "=r"((r)[3]) : "r"(a))

__device__ __forceinline__ void mma16816(float* c, const uint32_t* a, const uint32_t* b) {
    asm volatile("mma.sync.aligned.m16n8k16.row.col.f32.f16.f16.f32 "
        "{%0,%1,%2,%3}, {%4,%5,%6,%7}, {%8,%9}, {%0,%1,%2,%3};"
        : "+f"(c[0]), "+f"(c[1]), "+f"(c[2]), "+f"(c[3])
        : "r"(a[0]), "r"(a[1]), "r"(a[2]), "r"(a[3]), "r"(b[0]), "r"(b[1]));
}

#define CP_ASYNC(dst, src, sz) \
    asm volatile("cp.async.cg.shared.global [%0], [%1], 16, %2;" \
        :: "r"(dst), "l"(src), "r"(sz) : "memory")
#define CP_COMMIT() asm volatile("cp.async.commit_group;" ::: "memory")
#define CP_WAIT2()  asm volatile("cp.async.wait_group 2;" ::: "memory")
#define CP_WAIT1()  asm volatile("cp.async.wait_group 1;" ::: "memory")
#define CP_WAIT0()  asm volatile("cp.async.wait_group 0;" ::: "memory")

// ---------------- block reduce ----------------
__device__ __forceinline__ float block_reduce(float v, int op) {
    __shared__ float red[32];
    #pragma unroll
    for (int o = 16; o > 0; o >>= 1) {
        float u = __shfl_xor_sync(0xffffffffu, v, o);
        v = op ? (v + u) : fmaxf(v, u);
    }
    int lane = threadIdx.x & 31, wid = threadIdx.x >> 5;
    int nw = (blockDim.x + 31) >> 5;
    if (lane == 0) red[wid] = v;
    __syncthreads();
    if (wid == 0) {
        float r = (lane < nw) ? red[lane] : (op ? 0.0f : -3.4e38f);
        #pragma unroll
        for (int o = 16; o > 0; o >>= 1) {
            float u = __shfl_xor_sync(0xffffffffu, r, o);
            r = op ? (r + u) : fmaxf(r, u);
        }
        if (lane == 0) red[0] = r;
    }
    __syncthreads();
    float r = red[0];
    __syncthreads();
    return r;
}

// ---------------------------------------------------------------------------
// HMMA GEMM (fp16 2-pass split): C[b,m,n] = alpha * sum_k A[m,k]*B[n,k]
//   C ~ Ah*Bh + Ah*Bl  (Al*Bh dropped: <=2^-11 relative — measured 6e-4 end2end)
// SYM: C symmetric (M==Nd): skip blocks with bx<by, mirror-write bx>by.
// Block tile 128 x NTILE x 32; 128 threads; 4 warps 2x2; warp tile 64 x NTILE/2.
// 4-stage cp.async pipeline, ONE __syncthreads per k-chunk:
//   iter kt: stage(kt+3) [slot fenced by prev sync] -> compute(kt) -> wait -> sync
// ---------------------------------------------------------------------------
template<int NTILE, bool SYM>
__global__ __launch_bounds__(128, 2) void k_mma(
    const h16* __restrict__ Ah,
    const h16* __restrict__ Bh, const h16* __restrict__ Bl,
    float* __restrict__ Cd, int M, int Nd, int Kp, int n_off,
    size_t sA, size_t sB, size_t sC, float alpha)
{
    constexpr int ABYTES = 8192;
    constexpr int BSEG   = NTILE * 64;
    constexpr int BUF    = ABYTES + 2 * BSEG;
    constexpr int A_CH   = 512;                  // 16B chunks in A region
    constexpr int CH     = A_CH + NTILE * 8;
    constexpr int PER_T  = CH / 128;
    constexpr int NI     = NTILE / 16;           // n-frags per warp
    constexpr int G      = (NI > 4) ? 4 : NI;
    constexpr int NG     = NI / G;

    extern __shared__ __align__(16) char dsm[];
    const int bx = blockIdx.x, by = blockIdx.y, bz = blockIdx.z;
    if (SYM && bx < by) return;
    const int m0 = by * 128, n0 = n_off + bx * NTILE;
    const int t = threadIdx.x;
    const int lane = t & 31, warp = t >> 5;
    const int mbase = (warp >> 1) * 64, nbase = (warp & 1) * (NTILE / 2);

    const h16* Abh = Ah + (size_t)bz * sA;
    const h16* Bbh = Bh + (size_t)bz * sB;
    const h16* Bbl = Bl + (size_t)bz * sB;

    const uint32_t sbase = smem_u32(dsm);
    auto sw = [](int row, int chunk) -> uint32_t {
        return (uint32_t)((row * 4 + (chunk ^ (row & 3))) * 16);
    };

    auto stage = [&](int buf, int k0) {
        #pragma unroll
        for (int i = 0; i < PER_T; i++) {
            int idx = t + i * 128;
            const h16* base; int g, row, chunk; uint32_t dstoff; bool valid;
            if (idx < A_CH) {
                row = idx >> 2; chunk = idx & 3;
                base = Abh;
                g = m0 + row; valid = g < M;
                dstoff = sw(row, chunk);
            } else {
                int idxb = idx - A_CH;
                int hl = idxb >= NTILE * 4;
                int r = idxb - hl * NTILE * 4;
                row = r >> 2; chunk = r & 3;
                base = hl ? Bbl : Bbh;
                g = n0 + row; valid = g < Nd;
                dstoff = ABYTES + hl * BSEG + sw(row, chunk);
            }
            CP_ASYNC(sbase + buf * BUF + dstoff,
                     base + (size_t)g * Kp + k0 + chunk * 8, valid ? 16 : 0);
        }
        CP_COMMIT();
    };

    float acc[4][NI][4];
    #pragma unroll
    for (int mi = 0; mi < 4; mi++)
        #pragma unroll
        for (int ni = 0; ni < NI; ni++)
            #pragma unroll
            for (int q = 0; q < 4; q++) acc[mi][ni][q] = 0.0f;

    const int nk = Kp / 32;
    // prologue: fill 3 of 4 stages
    stage(0, 0);
    if (nk > 1) stage(1, 32);
    if (nk > 2) stage(2, 64);
    if (nk > 2)      { CP_WAIT2(); }
    else if (nk > 1) { CP_WAIT1(); }
    else             { CP_WAIT0(); }
    __syncthreads();

    for (int kt = 0; kt < nk; kt++) {
        const int buf = kt & 3;
        // stage 3 ahead; slot (kt+3)&3 == (kt-1)&3 was fenced by prev iter's sync
        if (kt + 3 < nk) stage((kt + 3) & 3, (kt + 3) * 32);

        const uint32_t bb = sbase + buf * BUF;
        #pragma unroll
        for (int s = 0; s < 2; s++) {
            const int c0 = s * 2;
            const int arow = (lane & 15), achk = c0 + (lane >> 4);
            const int brow = (lane & 7) + ((lane & 16) >> 1);
            const int bchk = c0 + ((lane >> 3) & 1);

            uint32_t ah[4][4];
            #pragma unroll
            for (int mi = 0; mi < 4; mi++)
                LDMX4(ah[mi], bb + sw(mbase + mi * 16 + arow, achk));

            #pragma unroll
            for (int grp = 0; grp < NG; grp++) {
                uint32_t bh[G][2], bl[G][2];
                #pragma unroll
                for (int h = 0; h < G / 2; h++) {
                    uint32_t r4[4];
                    int rw = nbase + grp * (G * 8) + h * 16 + brow;
                    LDMX4(r4, bb + ABYTES + sw(rw, bchk));
                    bh[h*2][0] = r4[0]; bh[h*2][1] = r4[1];
                    bh[h*2+1][0] = r4[2]; bh[h*2+1][1] = r4[3];
                    LDMX4(r4, bb + ABYTES + BSEG + sw(rw, bchk));
                    bl[h*2][0] = r4[0]; bl[h*2][1] = r4[1];
                    bl[h*2+1][0] = r4[2]; bl[h*2+1][1] = r4[3];
                }
                #pragma unroll
                for (int mi = 0; mi < 4; mi++)
                    #pragma unroll
                    for (int nj = 0; nj < G; nj++) {
                        float* a = acc[mi][grp * G + nj];
                        mma16816(a, ah[mi], bh[nj]);   // hi*hi
                        mma16816(a, ah[mi], bl[nj]);   // hi*lo
                    }
            }
        }

        // wait so that buf (kt+1) is complete, then one barrier
        if (kt + 3 < nk)      { CP_WAIT2(); }
        else if (kt + 2 < nk) { CP_WAIT1(); }
        else if (kt + 1 < nk) { CP_WAIT0(); }
        if (kt + 1 < nk) __syncthreads();
    }

    // epilogue (+ mirror for SYM off-diagonal blocks)
    float* cb = Cd + (size_t)bz * sC;
    #pragma unroll
    for (int mi = 0; mi < 4; mi++) {
        #pragma unroll
        for (int ni = 0; ni < NI; ni++) {
            int row = m0 + mbase + mi * 16 + (lane >> 2);
            int col = n0 + nbase + ni * 8 + (lane & 3) * 2;
            float v0 = acc[mi][ni][0] * alpha, v1 = acc[mi][ni][1] * alpha;
            float v2 = acc[mi][ni][2] * alpha, v3 = acc[mi][ni][3] * alpha;
            if (col < Nd) {
                if (row < M)
                    *(float2*)(cb + (size_t)row * Nd + col) = make_float2(v0, v1);
                if (row + 8 < M)
                    *(float2*)(cb + (size_t)(row + 8) * Nd + col) = make_float2(v2, v3);
            }
            if (SYM && bx > by && col < M && row < Nd) {
                cb[(size_t)col * Nd + row] = v0;
                cb[(size_t)(col + 1) * Nd + row] = v1;
                if (row + 8 < Nd) {
                    cb[(size_t)col * Nd + row + 8] = v2;
                    cb[(size_t)(col + 1) * Nd + row + 8] = v3;
                }
            }
        }
    }
}

// ---------------------------------------------------------------------------
// fp32 (rows x cols) -> direct hi[/lo] (stride ds) + transposed hi/lo (stride ts)
// ---------------------------------------------------------------------------
__global__ __launch_bounds__(256) void k_split_both(
    const float* __restrict__ src,
    h16* __restrict__ dh, h16* __restrict__ dl, int ds,
    h16* __restrict__ th, h16* __restrict__ tl, int ts,
    int rows, int cols)
{
    __shared__ float tile[32][33];
    const int b = blockIdx.z;
    const int c0 = blockIdx.x * 32, r0 = blockIdx.y * 32;
    const float* s = src + (size_t)b * rows * cols;
    const size_t dbs = (size_t)b * rows * ds;
    const size_t tbs = (size_t)b * cols * ts;

    #pragma unroll
    for (int i = 0; i < 4; i++) {
        int r = r0 + threadIdx.y + i * 8, c = c0 + threadIdx.x;
        float v = s[(size_t)r * cols + c];
        tile[threadIdx.y + i * 8][threadIdx.x] = v;
        h16 h, l; split_h16(v, h, l);
        size_t o = dbs + (size_t)r * ds + c;
        dh[o] = h;
        if (dl) dl[o] = l;
    }
    __syncthreads();
    #pragma unroll
    for (int i = 0; i < 4; i++) {
        int tr = c0 + threadIdx.y + i * 8, tc = r0 + threadIdx.x;
        float v = tile[threadIdx.x][threadIdx.y + i * 8];
        h16 h, l; split_h16(v, h, l);
        size_t o = tbs + (size_t)tr * ts + tc;
        th[o] = h; tl[o] = l;
    }
}

// ---------------------------------------------------------------------------
// Fused: Z = scale[c]*Y + shift[c] + X, plus fp16 hi/lo split of Z (direct,
// stride Kp1) and its transpose (stride Cc). rows=Cc (c), cols=Nn (n).
// ---------------------------------------------------------------------------
__global__ __launch_bounds__(256) void k_bn_res_split(
    const float* __restrict__ Y, const float* __restrict__ X, float* __restrict__ Z,
    h16* __restrict__ dh, h16* __restrict__ dl,
    h16* __restrict__ th, h16* __restrict__ tl)
{
    __shared__ float tile[32][33];
    const int b = blockIdx.z;
    const int c0 = blockIdx.x * 32, r0 = blockIdx.y * 32;
    const size_t fb = (size_t)b * Cc * Nn;
    const size_t dbs = (size_t)b * Cc * Kp1;
    const size_t tbs = (size_t)b * Nn * Cc;

    #pragma unroll
    for (int i = 0; i < 4; i++) {
        int r = r0 + threadIdx.y + i * 8, c = c0 + threadIdx.x;
        size_t off = fb + (size_t)r * Nn + c;
        float z = fmaf(g_scale[r], Y[off], g_shift[r]) + X[off];
        Z[off] = z;
        tile[threadIdx.y + i * 8][threadIdx.x] = z;
        h16 h, l; split_h16(z, h, l);
        size_t o = dbs + (size_t)r * Kp1 + c;
        dh[o] = h; dl[o] = l;
    }
    __syncthreads();
    #pragma unroll
    for (int i = 0; i < 4; i++) {
        int tr = c0 + threadIdx.y + i * 8, tc = r0 + threadIdx.x;
        float v = tile[threadIdx.x][threadIdx.y + i * 8];
        h16 h, l; split_h16(v, h, l);
        size_t o = tbs + (size_t)tr * Cc + tc;
        th[o] = h; tl[o] = l;
    }
}

// ---------------------------------------------------------------------------
__global__ __launch_bounds__(288) void k_softmax_prior(const float* __restrict__ dis)
{
    int p = blockIdx.x, b = blockIdx.y, t = threadIdx.x;
    const float* f = g_F + ((size_t)b * Nn + p) * Nn;
    float v = f[t];
    float m1 = block_reduce(v, 0);
    float e1 = __expf(v - m1);
    float s1 = block_reduce(e1, 1);
    float w  = (e1 / s1) * dis[(size_t)p * Nn + t];
    float m2 = block_reduce(w, 0);
    float e2 = __expf(w - m2);
    float s2 = block_reduce(e2, 1);
    h16 h, l; split_h16(e2 / s2, h, l);
    size_t o = ((size_t)b * Nn + p) * Kp1 + t;
    g_Fh[o] = h; g_Fl[o] = l;
}

__global__ __launch_bounds__(256) void k_softmax_chan()
{
    size_t row = blockIdx.x;
    const float* f = g_F2 + row * (size_t)Cc;
    int t = threadIdx.x;
    float v[4];
    #pragma unroll
    for (int i = 0; i < 4; i++) v[i] = f[t + 256 * i];
    float m = block_reduce(fmaxf(fmaxf(v[0], v[1]), fmaxf(v[2], v[3])), 0);
    float e[4], ls = 0.0f;
    #pragma unroll
    for (int i = 0; i < 4; i++) { e[i] = __expf(v[i] - m); ls += e[i]; }
    float s = block_reduce(ls, 1);
    float inv = 1.0f / s;
    #pragma unroll
    for (int i = 0; i < 4; i++)
        g_F2h[row * (size_t)Cc + t + 256 * i] = __float2half(e[i] * inv);
}

__global__ __launch_bounds__(256) void k_bnstats(
    const float* __restrict__ Y,
    const float* __restrict__ gamma, const float* __restrict__ beta)
{
    int c = blockIdx.x, t = threadIdx.x;
    const int n4 = Nn / 4, tot4 = Bb * n4;
    float s = 0.0f, sq = 0.0f;
    #pragma unroll 4
    for (int idx = t; idx < tot4; idx += 256) {
        int b = idx / n4, i = idx - b * n4;
        float4 v = *(const float4*)(Y + ((size_t)b * Cc + c) * Nn + i * 4);
        s  += (v.x + v.y) + (v.z + v.w);
        sq += (v.x * v.x + v.y * v.y) + (v.z * v.z + v.w * v.w);
    }
    s = block_reduce(s, 1);
    sq = block_reduce(sq, 1);
    if (t == 0) {
        const float invN = 1.0f / (float)(Bb * Nn);
        float mean = s * invN;
        float var  = sq * invN - mean * mean;
        float sc = gamma[c] * rsqrtf(var + EPSv);
        g_scale[c] = sc;
        g_shift[c] = beta[c] - mean * sc;
    }
}

__global__ __launch_bounds__(256) void k_bn_apply_add(
    const float* __restrict__ Y, const float* __restrict__ R, float* __restrict__ out)
{
    size_t i4 = (size_t)blockIdx.x * blockDim.x + threadIdx.x;
    const size_t total4 = (size_t)Bb * Cc * Nn / 4;
    if (i4 >= total4) return;
    int c = (int)((i4 * 4 / Nn) % Cc);
    float4 y = ((const float4*)Y)[i4];
    float4 r = ((const float4*)R)[i4];
    float sc = g_scale[c], sh = g_shift[c];
    float4 o;
    o.x = fmaf(sc, y.x, sh) + r.x;
    o.y = fmaf(sc, y.y, sh) + r.y;
    o.z = fmaf(sc, y.z, sh) + r.z;
    o.w = fmaf(sc, y.w, sh) + r.w;
    ((float4*)out)[i4] = o;
}

// ---------------------------------------------------------------------------
extern "C" void kernel_launch(void* const* d_in, const int* in_sizes, int n_in,
                              void* d_out, int out_size)
{
    const float* x      = (const float*)d_in[0];
    const float* dis    = (const float*)d_in[1];
    const float* gamma1 = (const float*)d_in[2];
    const float* beta1  = (const float*)d_in[3];
    const float* gamma2 = (const float*)d_in[4];
    const float* beta2  = (const float*)d_in[5];
    float* out = (float*)d_out;

    float *pF, *pY, *pZ, *pY2, *pF2;
    cudaGetSymbolAddress((void**)&pF,  g_F);
    cudaGetSymbolAddress((void**)&pY,  g_Y);
    cudaGetSymbolAddress((void**)&pZ,  g_Z);
    cudaGetSymbolAddress((void**)&pY2, g_Y2);
    cudaGetSymbolAddress((void**)&pF2, g_F2);
    h16 *pXh,*pXTh,*pXTl,*pZh,*pZl,*pZTh,*pZTl,*pFh,*pFl,*pF2h;
    cudaGetSymbolAddress((void**)&pXh,  g_Xh);
    cudaGetSymbolAddress((void**)&pXTh, g_XTh); cudaGetSymbolAddress((void**)&pXTl, g_XTl);
    cudaGetSymbolAddress((void**)&pZh,  g_Zh);  cudaGetSymbolAddress((void**)&pZl,  g_Zl);
    cudaGetSymbolAddress((void**)&pZTh, g_ZTh); cudaGetSymbolAddress((void**)&pZTl, g_ZTl);
    cudaGetSymbolAddress((void**)&pFh,  g_Fh);  cudaGetSymbolAddress((void**)&pFl,  g_Fl);
    cudaGetSymbolAddress((void**)&pF2h, g_F2h);

    const int SM2 = 4 * (8192 + 2 * 8192);    // NTILE=128, 4 stages: 98304
    const int SMT = 4 * (8192 + 2 * 2048);    // NTILE=32,  4 stages: 49152
    static bool attr_set = false;
    if (!attr_set) {
        cudaFuncSetAttribute((const void*)k_mma<128, true >,
                             cudaFuncAttributeMaxDynamicSharedMemorySize, SM2);
        cudaFuncSetAttribute((const void*)k_mma<128, false>,
                             cudaFuncAttributeMaxDynamicSharedMemorySize, SM2);
        cudaFuncSetAttribute((const void*)k_mma<32,  false>,
                             cudaFuncAttributeMaxDynamicSharedMemorySize, SMT);
        attr_set = true;
    }

    const size_t sX  = (size_t)Cc * Kp1;
    const size_t sXT = (size_t)Nn * Cc;
    const size_t sFb = (size_t)Nn * Kp1;
    const size_t sF  = (size_t)Nn * Nn;
    const size_t sYb = (size_t)Cc * Nn;
    const size_t sF2 = (size_t)Cc * Cc;

    // 0) split X -> Xh (hi only, Kp=320) + XT hi/lo (K=1024)
    k_split_both<<<dim3(Nn / 32, Cc / 32, Bb), dim3(32, 8)>>>(
        x, pXh, nullptr, Kp1, pXTh, pXTl, Cc, Cc, Nn);

    // 1) F = XT·XTᵀ / 32  (sym, 2-pass)  M=N=288, K=1024
    k_mma<128, true><<<dim3(3, 3, Bb), 128, SM2>>>(
        pXTh, pXTh, pXTl, pF, Nn, Nn, Cc, 0, sXT, sXT, sF, 0.03125f);

    // 2) softmax+prior -> F hi/lo (Kp=320)
    k_softmax_prior<<<dim3(Nn, Bb), 288>>>(dis);

    // 3) Y = X·Fᵀ  M=1024, N=288, Kp=320: full tiles + 32-wide tail
    k_mma<128, false><<<dim3(2, 8, Bb), 128, SM2>>>(
        pXh, pFh, pFl, pY, Cc, Nn, Kp1, 0, sX, sFb, sYb, 1.0f);
    k_mma<32, false><<<dim3(1, 8, Bb), 128, SMT>>>(
        pXh, pFh, pFl, pY, Cc, Nn, Kp1, 256, sX, sFb, sYb, 1.0f);

    // 4) BN1 stats + fused (residual + Z split direct/transposed)
    k_bnstats<<<Cc, 256>>>(pY, gamma1, beta1);
    k_bn_res_split<<<dim3(Nn / 32, Cc / 32, Bb), dim3(32, 8)>>>(
        pY, x, pZ, pZh, pZl, pZTh, pZTl);

    // 6) F2 = Z·Zᵀ  (sym, 2-pass)  M=N=1024, Kp=320
    k_mma<128, true><<<dim3(8, 8, Bb), 128, SM2>>>(
        pZh, pZh, pZl, pF2, Cc, Cc, Kp1, 0, sX, sX, sF2, 1.0f);

    // 7) softmax rows of F2 -> F2 hi
    k_softmax_chan<<<Bb * Cc, 256>>>();

    // 8) Y2 = F2·ZTᵀ  M=1024, N=288, K=1024: full tiles + tail
    k_mma<128, false><<<dim3(2, 8, Bb), 128, SM2>>>(
        pF2h, pZTh, pZTl, pY2, Cc, Nn, Cc, 0, sF2, sXT, sYb, 1.0f);
    k_mma<32, false><<<dim3(1, 8, Bb), 128, SMT>>>(
        pF2h, pZTh, pZTl, pY2, Cc, Nn, Cc, 256, sF2, sXT, sYb, 1.0f);

    // 9) BN2 + residual -> out
    k_bnstats<<<Cc, 256>>>(pY2, gamma2, beta2);
    k_bn_apply_add<<<(int)(((size_t)Bb * Cc * Nn / 4 + 255) / 256), 256>>>(pY2, pZ, out);
}

// round 11
// speedup vs baseline: 3.9083x; 1.0005x over previous
#include <cuda_runtime.h>
#include <cuda_fp16.h>
#include <math.h>
#include <stdint.h>

#define Bb   128
#define Cc   1024
#define Nn   288
#define Kp1  320            // padded K for K=288 (multiple of 32)
#define EPSv 1e-5f

typedef __half h16;

// fp32 scratch
__device__ float g_F [(size_t)Bb * Nn * Nn];
__device__ float g_Y [(size_t)Bb * Cc * Nn];
__device__ float g_Z [(size_t)Bb * Cc * Nn];
__device__ float g_Y2[(size_t)Bb * Cc * Nn];
__device__ float g_F2[(size_t)Bb * Cc * Cc];
__device__ float g_scale[Cc];
__device__ float g_shift[Cc];
// fp16 hi/lo K-major operands (pads stay zero: zero-init, never written)
__device__ h16 g_Xh [(size_t)Bb * Cc * Kp1];
__device__ h16 g_XTh[(size_t)Bb * Nn * Cc];
__device__ h16 g_XTl[(size_t)Bb * Nn * Cc];
__device__ h16 g_Zh [(size_t)Bb * Cc * Kp1];
__device__ h16 g_Zl [(size_t)Bb * Cc * Kp1];
__device__ h16 g_ZTh[(size_t)Bb * Nn * Cc];
__device__ h16 g_ZTl[(size_t)Bb * Nn * Cc];
__device__ h16 g_Fh [(size_t)Bb * Nn * Kp1];
__device__ h16 g_Fl [(size_t)Bb * Nn * Kp1];
__device__ h16 g_F2h[(size_t)Bb * Cc * Cc];

// ---------------- helpers ----------------
__device__ __forceinline__ uint32_t smem_u32(const void* p) {
    uint32_t a;
    asm("{ .reg .u64 t; cvta.to.shared.u64 t, %1; cvt.u32.u64 %0, t; }" : "=r"(a) : "l"(p));
    return a;
}
__device__ __forceinline__ void split_h16(float x, h16& h, h16& l) {
    h = __float2half(x);
    l = __float2half(x - __half2float(h));
}

#define LDMX4(r, a) \
    asm volatile("ldmatrix.sync.aligned.m8n8.x4.shared.b16 {%0,%1,%2,%3}, [%4];" \
        : "=r"((r)[0]), "=r"((r)[1]), "=r"((r)[2]), "=r"((r)[3]) : "r"(a))

__device__ __forceinline__ void mma16816(float* c, const uint32_t* a, const uint32_t* b) {
    asm volatile("mma.sync.aligned.m16n8k16.row.col.f32.f16.f16.f32 "
        "{%0,%1,%2,%3}, {%4,%5,%6,%7}, {%8,%9}, {%0,%1,%2,%3};"
        : "+f"(c[0]), "+f"(c[1]), "+f"(c[2]), "+f"(c[3])
        : "r"(a[0]), "r"(a[1]), "r"(a[2]), "r"(a[3]), "r"(b[0]), "r"(b[1]));
}

#define CP_ASYNC(dst, src, sz) \
    asm volatile("cp.async.cg.shared.global [%0], [%1], 16, %2;" \
        :: "r"(dst), "l"(src), "r"(sz) : "memory")
#define CP_COMMIT() asm volatile("cp.async.commit_group;" ::: "memory")
#define CP_WAIT2()  asm volatile("cp.async.wait_group 2;" ::: "memory")
#define CP_WAIT1()  asm volatile("cp.async.wait_group 1;" ::: "memory")
#define CP_WAIT0()  asm volatile("cp.async.wait_group 0;" ::: "memory")

// ---------------- block reduce ----------------
__device__ __forceinline__ float block_reduce(float v, int op) {
    __shared__ float red[32];
    #pragma unroll
    for (int o = 16; o > 0; o >>= 1) {
        float u = __shfl_xor_sync(0xffffffffu, v, o);
        v = op ? (v + u) : fmaxf(v, u);
    }
    int lane = threadIdx.x & 31, wid = threadIdx.x >> 5;
    int nw = (blockDim.x + 31) >> 5;
    if (lane == 0) red[wid] = v;
    __syncthreads();
    if (wid == 0) {
        float r = (lane < nw) ? red[lane] : (op ? 0.0f : -3.4e38f);
        #pragma unroll
        for (int o = 16; o > 0; o >>= 1) {
            float u = __shfl_xor_sync(0xffffffffu, r, o);
            r = op ? (r + u) : fmaxf(r, u);
        }
        if (lane == 0) red[0] = r;
    }
    __syncthreads();
    float r = red[0];
    __syncthreads();
    return r;
}

// ---------------------------------------------------------------------------
// HMMA GEMM (fp16 2-pass split): C[b,m,n] = alpha * sum_k A[m,k]*B[n,k]
//   C ~ Ah*Bh + Ah*Bl  (Al*Bh dropped: <=2^-11 relative — measured 6e-4 end2end)
// SYM: C symmetric (M==Nd): skip blocks with bx<by, mirror-write bx>by.
// Block tile 128 x NTILE x 32; 128 threads; 4 warps 2x2; warp tile 64 x NTILE/2.
// 4-stage cp.async pipeline, one __syncthreads per k-chunk.
// MMA schedule: per B-group, ALL hi*hi MMAs then ALL hi*lo MMAs — each acc's
// two updates are separated by G*4-1 independent MMAs (hides HMMA latency).
// ---------------------------------------------------------------------------
template<int NTILE, bool SYM>
__global__ __launch_bounds__(128, 2) void k_mma(
    const h16* __restrict__ Ah,
    const h16* __restrict__ Bh, const h16* __restrict__ Bl,
    float* __restrict__ Cd, int M, int Nd, int Kp, int n_off,
    size_t sA, size_t sB, size_t sC, float alpha)
{
    constexpr int ABYTES = 8192;
    constexpr int BSEG   = NTILE * 64;
    constexpr int BUF    = ABYTES + 2 * BSEG;
    constexpr int A_CH   = 512;                  // 16B chunks in A region
    constexpr int CH     = A_CH + NTILE * 8;
    constexpr int PER_T  = CH / 128;
    constexpr int NI     = NTILE / 16;           // n-frags per warp
    constexpr int G      = (NI > 4) ? 4 : NI;
    constexpr int NG     = NI / G;

    extern __shared__ __align__(16) char dsm[];
    const int bx = blockIdx.x, by = blockIdx.y, bz = blockIdx.z;
    if (SYM && bx < by) return;
    const int m0 = by * 128, n0 = n_off + bx * NTILE;
    const int t = threadIdx.x;
    const int lane = t & 31, warp = t >> 5;
    const int mbase = (warp >> 1) * 64, nbase = (warp & 1) * (NTILE / 2);

    const h16* Abh = Ah + (size_t)bz * sA;
    const h16* Bbh = Bh + (size_t)bz * sB;
    const h16* Bbl = Bl + (size_t)bz * sB;

    const uint32_t sbase = smem_u32(dsm);
    auto sw = [](int row, int chunk) -> uint32_t {
        return (uint32_t)((row * 4 + (chunk ^ (row & 3))) * 16);
    };

    auto stage = [&](int buf, int k0) {
        #pragma unroll
        for (int i = 0; i < PER_T; i++) {
            int idx = t + i * 128;
            const h16* base; int g, row, chunk; uint32_t dstoff; bool valid;
            if (idx < A_CH) {
                row = idx >> 2; chunk = idx & 3;
                base = Abh;
                g = m0 + row; valid = g < M;
                dstoff = sw(row, chunk);
            } else {
                int idxb = idx - A_CH;
                int hl = idxb >= NTILE * 4;
                int r = idxb - hl * NTILE * 4;
                row = r >> 2; chunk = r & 3;
                base = hl ? Bbl : Bbh;
                g = n0 + row; valid = g < Nd;
                dstoff = ABYTES + hl * BSEG + sw(row, chunk);
            }
            CP_ASYNC(sbase + buf * BUF + dstoff,
                     base + (size_t)g * Kp + k0 + chunk * 8, valid ? 16 : 0);
        }
        CP_COMMIT();
    };

    float acc[4][NI][4];
    #pragma unroll
    for (int mi = 0; mi < 4; mi++)
        #pragma unroll
        for (int ni = 0; ni < NI; ni++)
            #pragma unroll
            for (int q = 0; q < 4; q++) acc[mi][ni][q] = 0.0f;

    const int nk = Kp / 32;
    // prologue: fill 3 of 4 stages
    stage(0, 0);
    if (nk > 1) stage(1, 32);
    if (nk > 2) stage(2, 64);
    if (nk > 2)      { CP_WAIT2(); }
    else if (nk > 1) { CP_WAIT1(); }
    else             { CP_WAIT0(); }
    __syncthreads();

    for (int kt = 0; kt < nk; kt++) {
        const int buf = kt & 3;
        if (kt + 3 < nk) stage((kt + 3) & 3, (kt + 3) * 32);

        const uint32_t bb = sbase + buf * BUF;
        #pragma unroll
        for (int s = 0; s < 2; s++) {
            const int c0 = s * 2;
            const int arow = (lane & 15), achk = c0 + (lane >> 4);
            const int brow = (lane & 7) + ((lane & 16) >> 1);
            const int bchk = c0 + ((lane >> 3) & 1);

            uint32_t ah[4][4];
            #pragma unroll
            for (int mi = 0; mi < 4; mi++)
                LDMX4(ah[mi], bb + sw(mbase + mi * 16 + arow, achk));

            #pragma unroll
            for (int grp = 0; grp < NG; grp++) {
                uint32_t bh[G][2], bl[G][2];
                #pragma unroll
                for (int h = 0; h < G / 2; h++) {
                    uint32_t r4[4];
                    int rw = nbase + grp * (G * 8) + h * 16 + brow;
                    LDMX4(r4, bb + ABYTES + sw(rw, bchk));
                    bh[h*2][0] = r4[0]; bh[h*2][1] = r4[1];
                    bh[h*2+1][0] = r4[2]; bh[h*2+1][1] = r4[3];
                    LDMX4(r4, bb + ABYTES + BSEG + sw(rw, bchk));
                    bl[h*2][0] = r4[0]; bl[h*2][1] = r4[1];
                    bl[h*2+1][0] = r4[2]; bl[h*2+1][1] = r4[3];
                }
                // pass 1: all hi*hi (16 independent MMAs)
                #pragma unroll
                for (int mi = 0; mi < 4; mi++)
                    #pragma unroll
                    for (int nj = 0; nj < G; nj++)
                        mma16816(acc[mi][grp * G + nj], ah[mi], bh[nj]);
                // pass 2: all hi*lo (acc reuse distance = 16 MMAs)
                #pragma unroll
                for (int mi = 0; mi < 4; mi++)
                    #pragma unroll
                    for (int nj = 0; nj < G; nj++)
                        mma16816(acc[mi][grp * G + nj], ah[mi], bl[nj]);
            }
        }

        if (kt + 3 < nk)      { CP_WAIT2(); }
        else if (kt + 2 < nk) { CP_WAIT1(); }
        else if (kt + 1 < nk) { CP_WAIT0(); }
        if (kt + 1 < nk) __syncthreads();
    }

    // epilogue (+ mirror for SYM off-diagonal blocks)
    float* cb = Cd + (size_t)bz * sC;
    #pragma unroll
    for (int mi = 0; mi < 4; mi++) {
        #pragma unroll
        for (int ni = 0; ni < NI; ni++) {
            int row = m0 + mbase + mi * 16 + (lane >> 2);
            int col = n0 + nbase + ni * 8 + (lane & 3) * 2;
            float v0 = acc[mi][ni][0] * alpha, v1 = acc[mi][ni][1] * alpha;
            float v2 = acc[mi][ni][2] * alpha, v3 = acc[mi][ni][3] * alpha;
            if (col < Nd) {
                if (row < M)
                    *(float2*)(cb + (size_t)row * Nd + col) = make_float2(v0, v1);
                if (row + 8 < M)
                    *(float2*)(cb + (size_t)(row + 8) * Nd + col) = make_float2(v2, v3);
            }
            if (SYM && bx > by && col < M && row < Nd) {
                cb[(size_t)col * Nd + row] = v0;
                cb[(size_t)(col + 1) * Nd + row] = v1;
                if (row + 8 < Nd) {
                    cb[(size_t)col * Nd + row + 8] = v2;
                    cb[(size_t)(col + 1) * Nd + row + 8] = v3;
                }
            }
        }
    }
}

// ---------------------------------------------------------------------------
// fp32 (rows x cols) -> direct hi[/lo] (stride ds) + transposed hi/lo (stride ts)
// ---------------------------------------------------------------------------
__global__ __launch_bounds__(256) void k_split_both(
    const float* __restrict__ src,
    h16* __restrict__ dh, h16* __restrict__ dl, int ds,
    h16* __restrict__ th, h16* __restrict__ tl, int ts,
    int rows, int cols)
{
    __shared__ float tile[32][33];
    const int b = blockIdx.z;
    const int c0 = blockIdx.x * 32, r0 = blockIdx.y * 32;
    const float* s = src + (size_t)b * rows * cols;
    const size_t dbs = (size_t)b * rows * ds;
    const size_t tbs = (size_t)b * cols * ts;

    #pragma unroll
    for (int i = 0; i < 4; i++) {
        int r = r0 + threadIdx.y + i * 8, c = c0 + threadIdx.x;
        float v = s[(size_t)r * cols + c];
        tile[threadIdx.y + i * 8][threadIdx.x] = v;
        h16 h, l; split_h16(v, h, l);
        size_t o = dbs + (size_t)r * ds + c;
        dh[o] = h;
        if (dl) dl[o] = l;
    }
    __syncthreads();
    #pragma unroll
    for (int i = 0; i < 4; i++) {
        int tr = c0 + threadIdx.y + i * 8, tc = r0 + threadIdx.x;
        float v = tile[threadIdx.x][threadIdx.y + i * 8];
        h16 h, l; split_h16(v, h, l);
        size_t o = tbs + (size_t)tr * ts + tc;
        th[o] = h; tl[o] = l;
    }
}

// ---------------------------------------------------------------------------
// Fused: Z = scale[c]*Y + shift[c] + X, plus fp16 hi/lo split of Z (direct,
// stride Kp1) and its transpose (stride Cc). rows=Cc (c), cols=Nn (n).
// ---------------------------------------------------------------------------
__global__ __launch_bounds__(256) void k_bn_res_split(
    const float* __restrict__ Y, const float* __restrict__ X, float* __restrict__ Z,
    h16* __restrict__ dh, h16* __restrict__ dl,
    h16* __restrict__ th, h16* __restrict__ tl)
{
    __shared__ float tile[32][33];
    const int b = blockIdx.z;
    const int c0 = blockIdx.x * 32, r0 = blockIdx.y * 32;
    const size_t fb = (size_t)b * Cc * Nn;
    const size_t dbs = (size_t)b * Cc * Kp1;
    const size_t tbs = (size_t)b * Nn * Cc;

    #pragma unroll
    for (int i = 0; i < 4; i++) {
        int r = r0 + threadIdx.y + i * 8, c = c0 + threadIdx.x;
        size_t off = fb + (size_t)r * Nn + c;
        float z = fmaf(g_scale[r], Y[off], g_shift[r]) + X[off];
        Z[off] = z;
        tile[threadIdx.y + i * 8][threadIdx.x] = z;
        h16 h, l; split_h16(z, h, l);
        size_t o = dbs + (size_t)r * Kp1 + c;
        dh[o] = h; dl[o] = l;
    }
    __syncthreads();
    #pragma unroll
    for (int i = 0; i < 4; i++) {
        int tr = c0 + threadIdx.y + i * 8, tc = r0 + threadIdx.x;
        float v = tile[threadIdx.x][threadIdx.y + i * 8];
        h16 h, l; split_h16(v, h, l);
        size_t o = tbs + (size_t)tr * Cc + tc;
        th[o] = h; tl[o] = l;
    }
}

// ---------------------------------------------------------------------------
__global__ __launch_bounds__(288) void k_softmax_prior(const float* __restrict__ dis)
{
    int p = blockIdx.x, b = blockIdx.y, t = threadIdx.x;
    const float* f = g_F + ((size_t)b * Nn + p) * Nn;
    float v = f[t];
    float m1 = block_reduce(v, 0);
    float e1 = __expf(v - m1);
    float s1 = block_reduce(e1, 1);
    float w  = (e1 / s1) * dis[(size_t)p * Nn + t];
    float m2 = block_reduce(w, 0);
    float e2 = __expf(w - m2);
    float s2 = block_reduce(e2, 1);
    h16 h, l; split_h16(e2 / s2, h, l);
    size_t o = ((size_t)b * Nn + p) * Kp1 + t;
    g_Fh[o] = h; g_Fl[o] = l;
}

__global__ __launch_bounds__(256) void k_softmax_chan()
{
    size_t row = blockIdx.x;
    const float* f = g_F2 + row * (size_t)Cc;
    int t = threadIdx.x;
    float v[4];
    #pragma unroll
    for (int i = 0; i < 4; i++) v[i] = f[t + 256 * i];
    float m = block_reduce(fmaxf(fmaxf(v[0], v[1]), fmaxf(v[2], v[3])), 0);
    float e[4], ls = 0.0f;
    #pragma unroll
    for (int i = 0; i < 4; i++) { e[i] = __expf(v[i] - m); ls += e[i]; }
    float s = block_reduce(ls, 1);
    float inv = 1.0f / s;
    #pragma unroll
    for (int i = 0; i < 4; i++)
        g_F2h[row * (size_t)Cc + t + 256 * i] = __float2half(e[i] * inv);
}

__global__ __launch_bounds__(256) void k_bnstats(
    const float* __restrict__ Y,
    const float* __restrict__ gamma, const float* __restrict__ beta)
{
    int c = blockIdx.x, t = threadIdx.x;
    const int n4 = Nn / 4, tot4 = Bb * n4;
    float s = 0.0f, sq = 0.0f;
    #pragma unroll 4
    for (int idx = t; idx < tot4; idx += 256) {
        int b = idx / n4, i = idx - b * n4;
        float4 v = *(const float4*)(Y + ((size_t)b * Cc + c) * Nn + i * 4);
        s  += (v.x + v.y) + (v.z + v.w);
        sq += (v.x * v.x + v.y * v.y) + (v.z * v.z + v.w * v.w);
    }
    s = block_reduce(s, 1);
    sq = block_reduce(sq, 1);
    if (t == 0) {
        const float invN = 1.0f / (float)(Bb * Nn);
        float mean = s * invN;
        float var  = sq * invN - mean * mean;
        float sc = gamma[c] * rsqrtf(var + EPSv);
        g_scale[c] = sc;
        g_shift[c] = beta[c] - mean * sc;
    }
}

__global__ __launch_bounds__(256) void k_bn_apply_add(
    const float* __restrict__ Y, const float* __restrict__ R, float* __restrict__ out)
{
    size_t i4 = (size_t)blockIdx.x * blockDim.x + threadIdx.x;
    const size_t total4 = (size_t)Bb * Cc * Nn / 4;
    if (i4 >= total4) return;
    int c = (int)((i4 * 4 / Nn) % Cc);
    float4 y = ((const float4*)Y)[i4];
    float4 r = ((const float4*)R)[i4];
    float sc = g_scale[c], sh = g_shift[c];
    float4 o;
    o.x = fmaf(sc, y.x, sh) + r.x;
    o.y = fmaf(sc, y.y, sh) + r.y;
    o.z = fmaf(sc, y.z, sh) + r.z;
    o.w = fmaf(sc, y.w, sh) + r.w;
    ((float4*)out)[i4] = o;
}

// ---------------------------------------------------------------------------
extern "C" void kernel_launch(void* const* d_in, const int* in_sizes, int n_in,
                              void* d_out, int out_size)
{
    const float* x      = (const float*)d_in[0];
    const float* dis    = (const float*)d_in[1];
    const float* gamma1 = (const float*)d_in[2];
    const float* beta1  = (const float*)d_in[3];
    const float* gamma2 = (const float*)d_in[4];
    const float* beta2  = (const float*)d_in[5];
    float* out = (float*)d_out;

    float *pF, *pY, *pZ, *pY2, *pF2;
    cudaGetSymbolAddress((void**)&pF,  g_F);
    cudaGetSymbolAddress((void**)&pY,  g_Y);
    cudaGetSymbolAddress((void**)&pZ,  g_Z);
    cudaGetSymbolAddress((void**)&pY2, g_Y2);
    cudaGetSymbolAddress((void**)&pF2, g_F2);
    h16 *pXh,*pXTh,*pXTl,*pZh,*pZl,*pZTh,*pZTl,*pFh,*pFl,*pF2h;
    cudaGetSymbolAddress((void**)&pXh,  g_Xh);
    cudaGetSymbolAddress((void**)&pXTh, g_XTh); cudaGetSymbolAddress((void**)&pXTl, g_XTl);
    cudaGetSymbolAddress((void**)&pZh,  g_Zh);  cudaGetSymbolAddress((void**)&pZl,  g_Zl);
    cudaGetSymbolAddress((void**)&pZTh, g_ZTh); cudaGetSymbolAddress((void**)&pZTl, g_ZTl);
    cudaGetSymbolAddress((void**)&pFh,  g_Fh);  cudaGetSymbolAddress((void**)&pFl,  g_Fl);
    cudaGetSymbolAddress((void**)&pF2h, g_F2h);

    const int SM2 = 4 * (8192 + 2 * 8192);    // NTILE=128, 4 stages: 98304
    const int SMT = 4 * (8192 + 2 * 2048);    // NTILE=32,  4 stages: 49152
    static bool attr_set = false;
    if (!attr_set) {
        cudaFuncSetAttribute((const void*)k_mma<128, true >,
                             cudaFuncAttributeMaxDynamicSharedMemorySize, SM2);
        cudaFuncSetAttribute((const void*)k_mma<128, false>,
                             cudaFuncAttributeMaxDynamicSharedMemorySize, SM2);
        cudaFuncSetAttribute((const void*)k_mma<32,  false>,
                             cudaFuncAttributeMaxDynamicSharedMemorySize, SMT);
        attr_set = true;
    }

    const size_t sX  = (size_t)Cc * Kp1;
    const size_t sXT = (size_t)Nn * Cc;
    const size_t sFb = (size_t)Nn * Kp1;
    const size_t sF  = (size_t)Nn * Nn;
    const size_t sYb = (size_t)Cc * Nn;
    const size_t sF2 = (size_t)Cc * Cc;

    // 0) split X -> Xh (hi only, Kp=320) + XT hi/lo (K=1024)
    k_split_both<<<dim3(Nn / 32, Cc / 32, Bb), dim3(32, 8)>>>(
        x, pXh, nullptr, Kp1, pXTh, pXTl, Cc, Cc, Nn);

    // 1) F = XT·XTᵀ / 32  (sym, 2-pass)  M=N=288, K=1024
    k_mma<128, true><<<dim3(3, 3, Bb), 128, SM2>>>(
        pXTh, pXTh, pXTl, pF, Nn, Nn, Cc, 0, sXT, sXT, sF, 0.03125f);

    // 2) softmax+prior -> F hi/lo (Kp=320)
    k_softmax_prior<<<dim3(Nn, Bb), 288>>>(dis);

    // 3) Y = X·Fᵀ  M=1024, N=288, Kp=320: full tiles + 32-wide tail
    k_mma<128, false><<<dim3(2, 8, Bb), 128, SM2>>>(
        pXh, pFh, pFl, pY, Cc, Nn, Kp1, 0, sX, sFb, sYb, 1.0f);
    k_mma<32, false><<<dim3(1, 8, Bb), 128, SMT>>>(
        pXh, pFh, pFl, pY, Cc, Nn, Kp1, 256, sX, sFb, sYb, 1.0f);

    // 4) BN1 stats + fused (residual + Z split direct/transposed)
    k_bnstats<<<Cc, 256>>>(pY, gamma1, beta1);
    k_bn_res_split<<<dim3(Nn / 32, Cc / 32, Bb), dim3(32, 8)>>>(
        pY, x, pZ, pZh, pZl, pZTh, pZTl);

    // 6) F2 = Z·Zᵀ  (sym, 2-pass)  M=N=1024, Kp=320
    k_mma<128, true><<<dim3(8, 8, Bb), 128, SM2>>>(
        pZh, pZh, pZl, pF2, Cc, Cc, Kp1, 0, sX, sX, sF2, 1.0f);

    // 7) softmax rows of F2 -> F2 hi
    k_softmax_chan<<<Bb * Cc, 256>>>();

    // 8) Y2 = F2·ZTᵀ  M=1024, N=288, K=1024: full tiles + tail
    k_mma<128, false><<<dim3(2, 8, Bb), 128, SM2>>>(
        pF2h, pZTh, pZTl, pY2, Cc, Nn, Cc, 0, sF2, sXT, sYb, 1.0f);
    k_mma<32, false><<<dim3(1, 8, Bb), 128, SMT>>>(
        pF2h, pZTh, pZTl, pY2, Cc, Nn, Cc, 256, sF2, sXT, sYb, 1.0f);

    // 9) BN2 + residual -> out
    k_bnstats<<<Cc, 256>>>(pY2, gamma2, beta2);
    k_bn_apply_add<<<(int)(((size_t)Bb * Cc * Nn / 4 + 255) / 256), 256>>>(pY2, pZ, out);
}

// round 12
// speedup vs baseline: 4.1367x; 1.0584x over previous
#include <cuda_runtime.h>
#include <cuda_fp16.h>
#include <math.h>
#include <stdint.h>

#define Bb   128
#define Cc   1024
#define Nn   288
#define Kp1  320            // padded K for K=288 (multiple of 32)
#define EPSv 1e-5f

typedef __half h16;

// fp32 scratch
__device__ float g_F [(size_t)Bb * Nn * Nn];
__device__ float g_Y [(size_t)Bb * Cc * Nn];
__device__ float g_Z [(size_t)Bb * Cc * Nn];
__device__ float g_Y2[(size_t)Bb * Cc * Nn];
__device__ float g_F2[(size_t)Bb * Cc * Cc];
__device__ float g_scale[Cc];
__device__ float g_shift[Cc];
// fp16 hi/lo K-major operands (pads stay zero: zero-init, never written)
__device__ h16 g_Xh [(size_t)Bb * Cc * Kp1];
__device__ h16 g_XTh[(size_t)Bb * Nn * Cc];
__device__ h16 g_XTl[(size_t)Bb * Nn * Cc];
__device__ h16 g_Zh [(size_t)Bb * Cc * Kp1];
__device__ h16 g_Zl [(size_t)Bb * Cc * Kp1];
__device__ h16 g_ZTh[(size_t)Bb * Nn * Cc];
__device__ h16 g_ZTl[(size_t)Bb * Nn * Cc];
__device__ h16 g_Fh [(size_t)Bb * Nn * Kp1];
__device__ h16 g_Fl [(size_t)Bb * Nn * Kp1];
__device__ h16 g_F2h[(size_t)Bb * Cc * Cc];

// ---------------- helpers ----------------
__device__ __forceinline__ uint32_t smem_u32(const void* p) {
    uint32_t a;
    asm("{ .reg .u64 t; cvta.to.shared.u64 t, %1; cvt.u32.u64 %0, t; }" : "=r"(a) : "l"(p));
    return a;
}
__device__ __forceinline__ void split_h16(float x, h16& h, h16& l) {
    h = __float2half(x);
    l = __float2half(x - __half2float(h));
}

#define LDMX4(r, a) \
    asm volatile("ldmatrix.sync.aligned.m8n8.x4.shared.b16 {%0,%1,%2,%3}, [%4];" \
        : "=r"((r)[0]), "=r"((r)[1]), "=r"((r)[2]), "=r"((r)[3]) : "r"(a))

__device__ __forceinline__ void mma16816(float* c, const uint32_t* a, const uint32_t* b) {
    asm volatile("mma.sync.aligned.m16n8k16.row.col.f32.f16.f16.f32 "
        "{%0,%1,%2,%3}, {%4,%5,%6,%7}, {%8,%9}, {%0,%1,%2,%3};"
        : "+f"(c[0]), "+f"(c[1]), "+f"(c[2]), "+f"(c[3])
        : "r"(a[0]), "r"(a[1]), "r"(a[2]), "r"(a[3]), "r"(b[0]), "r"(b[1]));
}

#define CP_ASYNC(dst, src, sz) \
    asm volatile("cp.async.cg.shared.global [%0], [%1], 16, %2;" \
        :: "r"(dst), "l"(src), "r"(sz) : "memory")
#define CP_COMMIT() asm volatile("cp.async.commit_group;" ::: "memory")
#define CP_WAIT2()  asm volatile("cp.async.wait_group 2;" ::: "memory")
#define CP_WAIT1()  asm volatile("cp.async.wait_group 1;" ::: "memory")
#define CP_WAIT0()  asm volatile("cp.async.wait_group 0;" ::: "memory")

// ---------------- block reduce ----------------
__device__ __forceinline__ float block_reduce(float v, int op) {
    __shared__ float red[32];
    #pragma unroll
    for (int o = 16; o > 0; o >>= 1) {
        float u = __shfl_xor_sync(0xffffffffu, v, o);
        v = op ? (v + u) : fmaxf(v, u);
    }
    int lane = threadIdx.x & 31, wid = threadIdx.x >> 5;
    int nw = (blockDim.x + 31) >> 5;
    if (lane == 0) red[wid] = v;
    __syncthreads();
    if (wid == 0) {
        float r = (lane < nw) ? red[lane] : (op ? 0.0f : -3.4e38f);
        #pragma unroll
        for (int o = 16; o > 0; o >>= 1) {
            float u = __shfl_xor_sync(0xffffffffu, r, o);
            r = op ? (r + u) : fmaxf(r, u);
        }
        if (lane == 0) red[0] = r;
    }
    __syncthreads();
    float r = red[0];
    __syncthreads();
    return r;
}

// ---------------------------------------------------------------------------
// HMMA GEMM (fp16 2-pass split): C[b,m,n] = alpha * sum_k A[m,k]*B[n,k]
//   C ~ Ah*Bh + Ah*Bl  (Al*Bh dropped: <=2^-11 relative — measured 6e-4 end2end)
// SYM: C symmetric (M==Nd): skip blocks with bx<by, mirror-write bx>by.
// Block tile 128 x NTILE x 32; 128 threads; 4 warps 2x2; warp tile 64 x NTILE/2.
// 4-stage cp.async pipeline, one __syncthreads per k-chunk.
// Swizzle: chunk ^ ((row>>1)&3) — LDSM phase (8 rows, 1 chunk) hits 8 DISTINCT
// bank groups mod 8 (old row&3 swizzle collided r with r+4: 2-way conflict).
// ---------------------------------------------------------------------------
template<int NTILE, bool SYM>
__global__ __launch_bounds__(128, 2) void k_mma(
    const h16* __restrict__ Ah,
    const h16* __restrict__ Bh, const h16* __restrict__ Bl,
    float* __restrict__ Cd, int M, int Nd, int Kp, int n_off,
    size_t sA, size_t sB, size_t sC, float alpha)
{
    constexpr int ABYTES = 8192;
    constexpr int BSEG   = NTILE * 64;
    constexpr int BUF    = ABYTES + 2 * BSEG;
    constexpr int A_CH   = 512;                  // 16B chunks in A region
    constexpr int CH     = A_CH + NTILE * 8;
    constexpr int PER_T  = CH / 128;
    constexpr int NI     = NTILE / 16;           // n-frags per warp
    constexpr int G      = (NI > 4) ? 4 : NI;
    constexpr int NG     = NI / G;

    extern __shared__ __align__(16) char dsm[];
    const int bx = blockIdx.x, by = blockIdx.y, bz = blockIdx.z;
    if (SYM && bx < by) return;
    const int m0 = by * 128, n0 = n_off + bx * NTILE;
    const int t = threadIdx.x;
    const int lane = t & 31, warp = t >> 5;
    const int mbase = (warp >> 1) * 64, nbase = (warp & 1) * (NTILE / 2);

    const h16* Abh = Ah + (size_t)bz * sA;
    const h16* Bbh = Bh + (size_t)bz * sB;
    const h16* Bbl = Bl + (size_t)bz * sB;

    const uint32_t sbase = smem_u32(dsm);
    // conflict-free swizzle: residues {c^j, 4+c^j} all distinct over 8-row phase
    auto sw = [](int row, int chunk) -> uint32_t {
        return (uint32_t)((row * 4 + (chunk ^ ((row >> 1) & 3))) * 16);
    };

    auto stage = [&](int buf, int k0) {
        #pragma unroll
        for (int i = 0; i < PER_T; i++) {
            int idx = t + i * 128;
            const h16* base; int g, row, chunk; uint32_t dstoff; bool valid;
            if (idx < A_CH) {
                row = idx >> 2; chunk = idx & 3;
                base = Abh;
                g = m0 + row; valid = g < M;
                dstoff = sw(row, chunk);
            } else {
                int idxb = idx - A_CH;
                int hl = idxb >= NTILE * 4;
                int r = idxb - hl * NTILE * 4;
                row = r >> 2; chunk = r & 3;
                base = hl ? Bbl : Bbh;
                g = n0 + row; valid = g < Nd;
                dstoff = ABYTES + hl * BSEG + sw(row, chunk);
            }
            CP_ASYNC(sbase + buf * BUF + dstoff,
                     base + (size_t)g * Kp + k0 + chunk * 8, valid ? 16 : 0);
        }
        CP_COMMIT();
    };

    float acc[4][NI][4];
    #pragma unroll
    for (int mi = 0; mi < 4; mi++)
        #pragma unroll
        for (int ni = 0; ni < NI; ni++)
            #pragma unroll
            for (int q = 0; q < 4; q++) acc[mi][ni][q] = 0.0f;

    const int nk = Kp / 32;
    // prologue: fill 3 of 4 stages
    stage(0, 0);
    if (nk > 1) stage(1, 32);
    if (nk > 2) stage(2, 64);
    if (nk > 2)      { CP_WAIT2(); }
    else if (nk > 1) { CP_WAIT1(); }
    else             { CP_WAIT0(); }
    __syncthreads();

    for (int kt = 0; kt < nk; kt++) {
        const int buf = kt & 3;
        if (kt + 3 < nk) stage((kt + 3) & 3, (kt + 3) * 32);

        const uint32_t bb = sbase + buf * BUF;
        #pragma unroll
        for (int s = 0; s < 2; s++) {
            const int c0 = s * 2;
            const int arow = (lane & 15), achk = c0 + (lane >> 4);
            const int brow = (lane & 7) + ((lane & 16) >> 1);
            const int bchk = c0 + ((lane >> 3) & 1);

            uint32_t ah[4][4];
            #pragma unroll
            for (int mi = 0; mi < 4; mi++)
                LDMX4(ah[mi], bb + sw(mbase + mi * 16 + arow, achk));

            #pragma unroll
            for (int grp = 0; grp < NG; grp++) {
                uint32_t bh[G][2], bl[G][2];
                #pragma unroll
                for (int h = 0; h < G / 2; h++) {
                    uint32_t r4[4];
                    int rw = nbase + grp * (G * 8) + h * 16 + brow;
                    LDMX4(r4, bb + ABYTES + sw(rw, bchk));
                    bh[h*2][0] = r4[0]; bh[h*2][1] = r4[1];
                    bh[h*2+1][0] = r4[2]; bh[h*2+1][1] = r4[3];
                    LDMX4(r4, bb + ABYTES + BSEG + sw(rw, bchk));
                    bl[h*2][0] = r4[0]; bl[h*2][1] = r4[1];
                    bl[h*2+1][0] = r4[2]; bl[h*2+1][1] = r4[3];
                }
                // pass 1: all hi*hi (16 independent MMAs)
                #pragma unroll
                for (int mi = 0; mi < 4; mi++)
                    #pragma unroll
                    for (int nj = 0; nj < G; nj++)
                        mma16816(acc[mi][grp * G + nj], ah[mi], bh[nj]);
                // pass 2: all hi*lo (acc reuse distance = 16 MMAs)
                #pragma unroll
                for (int mi = 0; mi < 4; mi++)
                    #pragma unroll
                    for (int nj = 0; nj < G; nj++)
                        mma16816(acc[mi][grp * G + nj], ah[mi], bl[nj]);
            }
        }

        if (kt + 3 < nk)      { CP_WAIT2(); }
        else if (kt + 2 < nk) { CP_WAIT1(); }
        else if (kt + 1 < nk) { CP_WAIT0(); }
        if (kt + 1 < nk) __syncthreads();
    }

    // epilogue (+ mirror for SYM off-diagonal blocks)
    float* cb = Cd + (size_t)bz * sC;
    #pragma unroll
    for (int mi = 0; mi < 4; mi++) {
        #pragma unroll
        for (int ni = 0; ni < NI; ni++) {
            int row = m0 + mbase + mi * 16 + (lane >> 2);
            int col = n0 + nbase + ni * 8 + (lane & 3) * 2;
            float v0 = acc[mi][ni][0] * alpha, v1 = acc[mi][ni][1] * alpha;
            float v2 = acc[mi][ni][2] * alpha, v3 = acc[mi][ni][3] * alpha;
            if (col < Nd) {
                if (row < M)
                    *(float2*)(cb + (size_t)row * Nd + col) = make_float2(v0, v1);
                if (row + 8 < M)
                    *(float2*)(cb + (size_t)(row + 8) * Nd + col) = make_float2(v2, v3);
            }
            if (SYM && bx > by && col < M && row < Nd) {
                cb[(size_t)col * Nd + row] = v0;
                cb[(size_t)(col + 1) * Nd + row] = v1;
                if (row + 8 < Nd) {
                    cb[(size_t)col * Nd + row + 8] = v2;
                    cb[(size_t)(col + 1) * Nd + row + 8] = v3;
                }
            }
        }
    }
}

// ---------------------------------------------------------------------------
// fp32 (rows x cols) -> direct hi[/lo] (stride ds) + transposed hi/lo (stride ts)
// ---------------------------------------------------------------------------
__global__ __launch_bounds__(256) void k_split_both(
    const float* __restrict__ src,
    h16* __restrict__ dh, h16* __restrict__ dl, int ds,
    h16* __restrict__ th, h16* __restrict__ tl, int ts,
    int rows, int cols)
{
    __shared__ float tile[32][33];
    const int b = blockIdx.z;
    const int c0 = blockIdx.x * 32, r0 = blockIdx.y * 32;
    const float* s = src + (size_t)b * rows * cols;
    const size_t dbs = (size_t)b * rows * ds;
    const size_t tbs = (size_t)b * cols * ts;

    #pragma unroll
    for (int i = 0; i < 4; i++) {
        int r = r0 + threadIdx.y + i * 8, c = c0 + threadIdx.x;
        float v = s[(size_t)r * cols + c];
        tile[threadIdx.y + i * 8][threadIdx.x] = v;
        h16 h, l; split_h16(v, h, l);
        size_t o = dbs + (size_t)r * ds + c;
        dh[o] = h;
        if (dl) dl[o] = l;
    }
    __syncthreads();
    #pragma unroll
    for (int i = 0; i < 4; i++) {
        int tr = c0 + threadIdx.y + i * 8, tc = r0 + threadIdx.x;
        float v = tile[threadIdx.x][threadIdx.y + i * 8];
        h16 h, l; split_h16(v, h, l);
        size_t o = tbs + (size_t)tr * ts + tc;
        th[o] = h; tl[o] = l;
    }
}

// ---------------------------------------------------------------------------
// Fused: Z = scale[c]*Y + shift[c] + X, plus fp16 hi/lo split of Z (direct,
// stride Kp1) and its transpose (stride Cc). rows=Cc (c), cols=Nn (n).
// ---------------------------------------------------------------------------
__global__ __launch_bounds__(256) void k_bn_res_split(
    const float* __restrict__ Y, const float* __restrict__ X, float* __restrict__ Z,
    h16* __restrict__ dh, h16* __restrict__ dl,
    h16* __restrict__ th, h16* __restrict__ tl)
{
    __shared__ float tile[32][33];
    const int b = blockIdx.z;
    const int c0 = blockIdx.x * 32, r0 = blockIdx.y * 32;
    const size_t fb = (size_t)b * Cc * Nn;
    const size_t dbs = (size_t)b * Cc * Kp1;
    const size_t tbs = (size_t)b * Nn * Cc;

    #pragma unroll
    for (int i = 0; i < 4; i++) {
        int r = r0 + threadIdx.y + i * 8, c = c0 + threadIdx.x;
        size_t off = fb + (size_t)r * Nn + c;
        float z = fmaf(g_scale[r], Y[off], g_shift[r]) + X[off];
        Z[off] = z;
        tile[threadIdx.y + i * 8][threadIdx.x] = z;
        h16 h, l; split_h16(z, h, l);
        size_t o = dbs + (size_t)r * Kp1 + c;
        dh[o] = h; dl[o] = l;
    }
    __syncthreads();
    #pragma unroll
    for (int i = 0; i < 4; i++) {
        int tr = c0 + threadIdx.y + i * 8, tc = r0 + threadIdx.x;
        float v = tile[threadIdx.x][threadIdx.y + i * 8];
        h16 h, l; split_h16(v, h, l);
        size_t o = tbs + (size_t)tr * Cc + tc;
        th[o] = h; tl[o] = l;
    }
}

// ---------------------------------------------------------------------------
__global__ __launch_bounds__(288) void k_softmax_prior(const float* __restrict__ dis)
{
    int p = blockIdx.x, b = blockIdx.y, t = threadIdx.x;
    const float* f = g_F + ((size_t)b * Nn + p) * Nn;
    float v = f[t];
    float m1 = block_reduce(v, 0);
    float e1 = __expf(v - m1);
    float s1 = block_reduce(e1, 1);
    float w  = (e1 / s1) * dis[(size_t)p * Nn + t];
    float m2 = block_reduce(w, 0);
    float e2 = __expf(w - m2);
    float s2 = block_reduce(e2, 1);
    h16 h, l; split_h16(e2 / s2, h, l);
    size_t o = ((size_t)b * Nn + p) * Kp1 + t;
    g_Fh[o] = h; g_Fl[o] = l;
}

__global__ __launch_bounds__(256) void k_softmax_chan()
{
    size_t row = blockIdx.x;
    const float* f = g_F2 + row * (size_t)Cc;
    int t = threadIdx.x;
    float v[4];
    #pragma unroll
    for (int i = 0; i < 4; i++) v[i] = f[t + 256 * i];
    float m = block_reduce(fmaxf(fmaxf(v[0], v[1]), fmaxf(v[2], v[3])), 0);
    float e[4], ls = 0.0f;
    #pragma unroll
    for (int i = 0; i < 4; i++) { e[i] = __expf(v[i] - m); ls += e[i]; }
    float s = block_reduce(ls, 1);
    float inv = 1.0f / s;
    #pragma unroll
    for (int i = 0; i < 4; i++)
        g_F2h[row * (size_t)Cc + t + 256 * i] = __float2half(e[i] * inv);
}

__global__ __launch_bounds__(256) void k_bnstats(
    const float* __restrict__ Y,
    const float* __restrict__ gamma, const float* __restrict__ beta)
{
    int c = blockIdx.x, t = threadIdx.x;
    const int n4 = Nn / 4, tot4 = Bb * n4;
    float s = 0.0f, sq = 0.0f;
    #pragma unroll 4
    for (int idx = t; idx < tot4; idx += 256) {
        int b = idx / n4, i = idx - b * n4;
        float4 v = *(const float4*)(Y + ((size_t)b * Cc + c) * Nn + i * 4);
        s  += (v.x + v.y) + (v.z + v.w);
        sq += (v.x * v.x + v.y * v.y) + (v.z * v.z + v.w * v.w);
    }
    s = block_reduce(s, 1);
    sq = block_reduce(sq, 1);
    if (t == 0) {
        const float invN = 1.0f / (float)(Bb * Nn);
        float mean = s * invN;
        float var  = sq * invN - mean * mean;
        float sc = gamma[c] * rsqrtf(var + EPSv);
        g_scale[c] = sc;
        g_shift[c] = beta[c] - mean * sc;
    }
}

__global__ __launch_bounds__(256) void k_bn_apply_add(
    const float* __restrict__ Y, const float* __restrict__ R, float* __restrict__ out)
{
    size_t i4 = (size_t)blockIdx.x * blockDim.x + threadIdx.x;
    const size_t total4 = (size_t)Bb * Cc * Nn / 4;
    if (i4 >= total4) return;
    int c = (int)((i4 * 4 / Nn) % Cc);
    float4 y = ((const float4*)Y)[i4];
    float4 r = ((const float4*)R)[i4];
    float sc = g_scale[c], sh = g_shift[c];
    float4 o;
    o.x = fmaf(sc, y.x, sh) + r.x;
    o.y = fmaf(sc, y.y, sh) + r.y;
    o.z = fmaf(sc, y.z, sh) + r.z;
    o.w = fmaf(sc, y.w, sh) + r.w;
    ((float4*)out)[i4] = o;
}

// ---------------------------------------------------------------------------
extern "C" void kernel_launch(void* const* d_in, const int* in_sizes, int n_in,
                              void* d_out, int out_size)
{
    const float* x      = (const float*)d_in[0];
    const float* dis    = (const float*)d_in[1];
    const float* gamma1 = (const float*)d_in[2];
    const float* beta1  = (const float*)d_in[3];
    const float* gamma2 = (const float*)d_in[4];
    const float* beta2  = (const float*)d_in[5];
    float* out = (float*)d_out;

    float *pF, *pY, *pZ, *pY2, *pF2;
    cudaGetSymbolAddress((void**)&pF,  g_F);
    cudaGetSymbolAddress((void**)&pY,  g_Y);
    cudaGetSymbolAddress((void**)&pZ,  g_Z);
    cudaGetSymbolAddress((void**)&pY2, g_Y2);
    cudaGetSymbolAddress((void**)&pF2, g_F2);
    h16 *pXh,*pXTh,*pXTl,*pZh,*pZl,*pZTh,*pZTl,*pFh,*pFl,*pF2h;
    cudaGetSymbolAddress((void**)&pXh,  g_Xh);
    cudaGetSymbolAddress((void**)&pXTh, g_XTh); cudaGetSymbolAddress((void**)&pXTl, g_XTl);
    cudaGetSymbolAddress((void**)&pZh,  g_Zh);  cudaGetSymbolAddress((void**)&pZl,  g_Zl);
    cudaGetSymbolAddress((void**)&pZTh, g_ZTh); cudaGetSymbolAddress((void**)&pZTl, g_ZTl);
    cudaGetSymbolAddress((void**)&pFh,  g_Fh);  cudaGetSymbolAddress((void**)&pFl,  g_Fl);
    cudaGetSymbolAddress((void**)&pF2h, g_F2h);

    const int SM2 = 4 * (8192 + 2 * 8192);    // NTILE=128, 4 stages: 98304
    const int SMT = 4 * (8192 + 2 * 2048);    // NTILE=32,  4 stages: 49152
    static bool attr_set = false;
    if (!attr_set) {
        cudaFuncSetAttribute((const void*)k_mma<128, true >,
                             cudaFuncAttributeMaxDynamicSharedMemorySize, SM2);
        cudaFuncSetAttribute((const void*)k_mma<128, false>,
                             cudaFuncAttributeMaxDynamicSharedMemorySize, SM2);
        cudaFuncSetAttribute((const void*)k_mma<32,  false>,
                             cudaFuncAttributeMaxDynamicSharedMemorySize, SMT);
        attr_set = true;
    }

    const size_t sX  = (size_t)Cc * Kp1;
    const size_t sXT = (size_t)Nn * Cc;
    const size_t sFb = (size_t)Nn * Kp1;
    const size_t sF  = (size_t)Nn * Nn;
    const size_t sYb = (size_t)Cc * Nn;
    const size_t sF2 = (size_t)Cc * Cc;

    // 0) split X -> Xh (hi only, Kp=320) + XT hi/lo (K=1024)
    k_split_both<<<dim3(Nn / 32, Cc / 32, Bb), dim3(32, 8)>>>(
        x, pXh, nullptr, Kp1, pXTh, pXTl, Cc, Cc, Nn);

    // 1) F = XT·XTᵀ / 32  (sym, 2-pass)  M=N=288, K=1024
    k_mma<128, true><<<dim3(3, 3, Bb), 128, SM2>>>(
        pXTh, pXTh, pXTl, pF, Nn, Nn, Cc, 0, sXT, sXT, sF, 0.03125f);

    // 2) softmax+prior -> F hi/lo (Kp=320)
    k_softmax_prior<<<dim3(Nn, Bb), 288>>>(dis);

    // 3) Y = X·Fᵀ  M=1024, N=288, Kp=320: full tiles + 32-wide tail
    k_mma<128, false><<<dim3(2, 8, Bb), 128, SM2>>>(
        pXh, pFh, pFl, pY, Cc, Nn, Kp1, 0, sX, sFb, sYb, 1.0f);
    k_mma<32, false><<<dim3(1, 8, Bb), 128, SMT>>>(
        pXh, pFh, pFl, pY, Cc, Nn, Kp1, 256, sX, sFb, sYb, 1.0f);

    // 4) BN1 stats + fused (residual + Z split direct/transposed)
    k_bnstats<<<Cc, 256>>>(pY, gamma1, beta1);
    k_bn_res_split<<<dim3(Nn / 32, Cc / 32, Bb), dim3(32, 8)>>>(
        pY, x, pZ, pZh, pZl, pZTh, pZTl);

    // 6) F2 = Z·Zᵀ  (sym, 2-pass)  M=N=1024, Kp=320
    k_mma<128, true><<<dim3(8, 8, Bb), 128, SM2>>>(
        pZh, pZh, pZl, pF2, Cc, Cc, Kp1, 0, sX, sX, sF2, 1.0f);

    // 7) softmax rows of F2 -> F2 hi
    k_softmax_chan<<<Bb * Cc, 256>>>();

    // 8) Y2 = F2·ZTᵀ  M=1024, N=288, K=1024: full tiles + tail
    k_mma<128, false><<<dim3(2, 8, Bb), 128, SM2>>>(
        pF2h, pZTh, pZTl, pY2, Cc, Nn, Cc, 0, sF2, sXT, sYb, 1.0f);
    k_mma<32, false><<<dim3(1, 8, Bb), 128, SMT>>>(
        pF2h, pZTh, pZTl, pY2, Cc, Nn, Cc, 256, sF2, sXT, sYb, 1.0f);

    // 9) BN2 + residual -> out
    k_bnstats<<<Cc, 256>>>(pY2, gamma2, beta2);
    k_bn_apply_add<<<(int)(((size_t)Bb * Cc * Nn / 4 + 255) / 256), 256>>>(pY2, pZ, out);
}

// round 13
// speedup vs baseline: 4.2621x; 1.0303x over previous
#include <cuda_runtime.h>
#include <cuda_fp16.h>
#include <math.h>
#include <stdint.h>

#define Bb   128
#define Cc   1024
#define Nn   288
#define Kp1  320            // padded K for K=288 (multiple of 32)
#define EPSv 1e-5f

typedef __half h16;

// fp32 scratch
__device__ float g_F [(size_t)Bb * Nn * Nn];
__device__ float g_Y [(size_t)Bb * Cc * Nn];
__device__ float g_Z [(size_t)Bb * Cc * Nn];
__device__ float g_Y2[(size_t)Bb * Cc * Nn];
__device__ float g_F2[(size_t)Bb * Cc * Cc];
__device__ float g_scale[Cc];
__device__ float g_shift[Cc];
// fp16 hi/lo K-major operands (pads stay zero: zero-init, never written)
__device__ h16 g_Xh [(size_t)Bb * Cc * Kp1];
__device__ h16 g_XTh[(size_t)Bb * Nn * Cc];
__device__ h16 g_XTl[(size_t)Bb * Nn * Cc];
__device__ h16 g_Zh [(size_t)Bb * Cc * Kp1];
__device__ h16 g_Zl [(size_t)Bb * Cc * Kp1];
__device__ h16 g_ZTh[(size_t)Bb * Nn * Cc];
__device__ h16 g_ZTl[(size_t)Bb * Nn * Cc];
__device__ h16 g_Fh [(size_t)Bb * Nn * Kp1];
__device__ h16 g_Fl [(size_t)Bb * Nn * Kp1];
__device__ h16 g_F2h[(size_t)Bb * Cc * Cc];

// ---------------- helpers ----------------
__device__ __forceinline__ uint32_t smem_u32(const void* p) {
    uint32_t a;
    asm("{ .reg .u64 t; cvta.to.shared.u64 t, %1; cvt.u32.u64 %0, t; }" : "=r"(a) : "l"(p));
    return a;
}
__device__ __forceinline__ void split_h16(float x, h16& h, h16& l) {
    h = __float2half(x);
    l = __float2half(x - __half2float(h));
}

#define LDMX4(r, a) \
    asm volatile("ldmatrix.sync.aligned.m8n8.x4.shared.b16 {%0,%1,%2,%3}, [%4];" \
        : "=r"((r)[0]), "=r"((r)[1]), "=r"((r)[2]), "=r"((r)[3]) : "r"(a))

__device__ __forceinline__ void mma16816(float* c, const uint32_t* a, const uint32_t* b) {
    asm volatile("mma.sync.aligned.m16n8k16.row.col.f32.f16.f16.f32 "
        "{%0,%1,%2,%3}, {%4,%5,%6,%7}, {%8,%9}, {%0,%1,%2,%3};"
        : "+f"(c[0]), "+f"(c[1]), "+f"(c[2]), "+f"(c[3])
        : "r"(a[0]), "r"(a[1]), "r"(a[2]), "r"(a[3]), "r"(b[0]), "r"(b[1]));
}

#define CP_ASYNC(dst, src, sz) \
    asm volatile("cp.async.cg.shared.global [%0], [%1], 16, %2;" \
        :: "r"(dst), "l"(src), "r"(sz) : "memory")
#define CP_COMMIT() asm volatile("cp.async.commit_group;" ::: "memory")
#define CP_WAIT2()  asm volatile("cp.async.wait_group 2;" ::: "memory")
#define CP_WAIT1()  asm volatile("cp.async.wait_group 1;" ::: "memory")
#define CP_WAIT0()  asm volatile("cp.async.wait_group 0;" ::: "memory")

// conflict-free swizzle (R11): residues {c^j, 4+c^j} distinct over 8-row phase
__device__ __forceinline__ uint32_t sw_off(int row, int chunk) {
    return (uint32_t)((row * 4 + (chunk ^ ((row >> 1) & 3))) * 16);
}

// ---------------- block reduce ----------------
__device__ __forceinline__ float block_reduce(float v, int op) {
    __shared__ float red[32];
    #pragma unroll
    for (int o = 16; o > 0; o >>= 1) {
        float u = __shfl_xor_sync(0xffffffffu, v, o);
        v = op ? (v + u) : fmaxf(v, u);
    }
    int lane = threadIdx.x & 31, wid = threadIdx.x >> 5;
    int nw = (blockDim.x + 31) >> 5;
    if (lane == 0) red[wid] = v;
    __syncthreads();
    if (wid == 0) {
        float r = (lane < nw) ? red[lane] : (op ? 0.0f : -3.4e38f);
        #pragma unroll
        for (int o = 16; o > 0; o >>= 1) {
            float u = __shfl_xor_sync(0xffffffffu, r, o);
            r = op ? (r + u) : fmaxf(r, u);
        }
        if (lane == 0) red[0] = r;
    }
    __syncthreads();
    float r = red[0];
    __syncthreads();
    return r;
}

// ---------------------------------------------------------------------------
// 256-thread HMMA GEMM, NTILE=128 (fp16 2-pass split): C = alpha * A·Bᵀ
// 8 warps in 2(m)x4(n) grid, warp tile 64x32 — 16 warps/SM (4 per SMSP).
// 4-stage cp.async pipeline, one __syncthreads per k-chunk.
// ---------------------------------------------------------------------------
template<bool SYM>
__global__ __launch_bounds__(256, 2) void k_mma256(
    const h16* __restrict__ Ah,
    const h16* __restrict__ Bh, const h16* __restrict__ Bl,
    float* __restrict__ Cd, int M, int Nd, int Kp, int n_off,
    size_t sA, size_t sB, size_t sC, float alpha)
{
    constexpr int ABYTES = 8192;
    constexpr int BSEG   = 8192;
    constexpr int BUF    = ABYTES + 2 * BSEG;   // 24576

    extern __shared__ __align__(16) char dsm[];
    const int bx = blockIdx.x, by = blockIdx.y, bz = blockIdx.z;
    if (SYM && bx < by) return;
    const int m0 = by * 128, n0 = n_off + bx * 128;
    const int t = threadIdx.x;
    const int lane = t & 31, wid = t >> 5;
    const int mbase = (wid >> 2) * 64, nbase = (wid & 3) * 32;

    const h16* Abh = Ah + (size_t)bz * sA;
    const h16* Bbh = Bh + (size_t)bz * sB;
    const h16* Bbl = Bl + (size_t)bz * sB;

    const uint32_t sbase = smem_u32(dsm);

    auto stage = [&](int buf, int k0) {
        #pragma unroll
        for (int i = 0; i < 6; i++) {
            int idx = t + i * 256;              // 0..1535
            const h16* base; int g, row, chunk; uint32_t dstoff; bool valid;
            if (idx < 512) {                    // A: 128 rows x 4 chunks
                row = idx >> 2; chunk = idx & 3;
                base = Abh;
                g = m0 + row; valid = g < M;
                dstoff = sw_off(row, chunk);
            } else {                            // B hi then lo
                int idxb = idx - 512;
                int hl = idxb >= 512;
                int r = idxb - hl * 512;
                row = r >> 2; chunk = r & 3;
                base = hl ? Bbl : Bbh;
                g = n0 + row; valid = g < Nd;
                dstoff = ABYTES + hl * BSEG + sw_off(row, chunk);
            }
            CP_ASYNC(sbase + buf * BUF + dstoff,
                     base + (size_t)g * Kp + k0 + chunk * 8, valid ? 16 : 0);
        }
        CP_COMMIT();
    };

    float acc[4][4][4];
    #pragma unroll
    for (int mi = 0; mi < 4; mi++)
        #pragma unroll
        for (int ni = 0; ni < 4; ni++)
            #pragma unroll
            for (int q = 0; q < 4; q++) acc[mi][ni][q] = 0.0f;

    const int nk = Kp / 32;
    stage(0, 0);
    if (nk > 1) stage(1, 32);
    if (nk > 2) stage(2, 64);
    if (nk > 2)      { CP_WAIT2(); }
    else if (nk > 1) { CP_WAIT1(); }
    else             { CP_WAIT0(); }
    __syncthreads();

    for (int kt = 0; kt < nk; kt++) {
        const int buf = kt & 3;
        if (kt + 3 < nk) stage((kt + 3) & 3, (kt + 3) * 32);

        const uint32_t bb = sbase + buf * BUF;
        #pragma unroll
        for (int s = 0; s < 2; s++) {
            const int c0 = s * 2;
            const int arow = (lane & 15), achk = c0 + (lane >> 4);
            const int brow = (lane & 7) + ((lane & 16) >> 1);
            const int bchk = c0 + ((lane >> 3) & 1);

            uint32_t ah[4][4];
            #pragma unroll
            for (int mi = 0; mi < 4; mi++)
                LDMX4(ah[mi], bb + sw_off(mbase + mi * 16 + arow, achk));

            uint32_t bh[4][2], bl[4][2];
            #pragma unroll
            for (int h = 0; h < 2; h++) {
                uint32_t r4[4];
                int rw = nbase + h * 16 + brow;
                LDMX4(r4, bb + ABYTES + sw_off(rw, bchk));
                bh[h*2][0] = r4[0]; bh[h*2][1] = r4[1];
                bh[h*2+1][0] = r4[2]; bh[h*2+1][1] = r4[3];
                LDMX4(r4, bb + ABYTES + BSEG + sw_off(rw, bchk));
                bl[h*2][0] = r4[0]; bl[h*2][1] = r4[1];
                bl[h*2+1][0] = r4[2]; bl[h*2+1][1] = r4[3];
            }
            // pass 1: all hi*hi (16 independent)
            #pragma unroll
            for (int mi = 0; mi < 4; mi++)
                #pragma unroll
                for (int nj = 0; nj < 4; nj++)
                    mma16816(acc[mi][nj], ah[mi], bh[nj]);
            // pass 2: all hi*lo
            #pragma unroll
            for (int mi = 0; mi < 4; mi++)
                #pragma unroll
                for (int nj = 0; nj < 4; nj++)
                    mma16816(acc[mi][nj], ah[mi], bl[nj]);
        }

        if (kt + 3 < nk)      { CP_WAIT2(); }
        else if (kt + 2 < nk) { CP_WAIT1(); }
        else if (kt + 1 < nk) { CP_WAIT0(); }
        if (kt + 1 < nk) __syncthreads();
    }

    // epilogue (+ mirror for SYM off-diagonal blocks)
    float* cb = Cd + (size_t)bz * sC;
    #pragma unroll
    for (int mi = 0; mi < 4; mi++) {
        #pragma unroll
        for (int ni = 0; ni < 4; ni++) {
            int row = m0 + mbase + mi * 16 + (lane >> 2);
            int col = n0 + nbase + ni * 8 + (lane & 3) * 2;
            float v0 = acc[mi][ni][0] * alpha, v1 = acc[mi][ni][1] * alpha;
            float v2 = acc[mi][ni][2] * alpha, v3 = acc[mi][ni][3] * alpha;
            if (col < Nd) {
                if (row < M)
                    *(float2*)(cb + (size_t)row * Nd + col) = make_float2(v0, v1);
                if (row + 8 < M)
                    *(float2*)(cb + (size_t)(row + 8) * Nd + col) = make_float2(v2, v3);
            }
            if (SYM && bx > by && col < M && row < Nd) {
                cb[(size_t)col * Nd + row] = v0;
                cb[(size_t)(col + 1) * Nd + row] = v1;
                if (row + 8 < Nd) {
                    cb[(size_t)col * Nd + row + 8] = v2;
                    cb[(size_t)(col + 1) * Nd + row + 8] = v3;
                }
            }
        }
    }
}

// ---------------------------------------------------------------------------
// 128-thread tail GEMM, NTILE=32 (fp16 2-pass split). Warp grid 2x2, tile 64x16.
// ---------------------------------------------------------------------------
__global__ __launch_bounds__(128, 2) void k_mma_tail(
    const h16* __restrict__ Ah,
    const h16* __restrict__ Bh, const h16* __restrict__ Bl,
    float* __restrict__ Cd, int M, int Nd, int Kp, int n_off,
    size_t sA, size_t sB, size_t sC, float alpha)
{
    constexpr int NTILE  = 32;
    constexpr int ABYTES = 8192;
    constexpr int BSEG   = NTILE * 64;          // 2048
    constexpr int BUF    = ABYTES + 2 * BSEG;   // 12288
    constexpr int PER_T  = (512 + NTILE * 8) / 128;   // 6

    extern __shared__ __align__(16) char dsm[];
    const int bx = blockIdx.x, by = blockIdx.y, bz = blockIdx.z;
    const int m0 = by * 128, n0 = n_off + bx * NTILE;
    const int t = threadIdx.x;
    const int lane = t & 31, wid = t >> 5;
    const int mbase = (wid >> 1) * 64, nbase = (wid & 1) * 16;

    const h16* Abh = Ah + (size_t)bz * sA;
    const h16* Bbh = Bh + (size_t)bz * sB;
    const h16* Bbl = Bl + (size_t)bz * sB;

    const uint32_t sbase = smem_u32(dsm);

    auto stage = [&](int buf, int k0) {
        #pragma unroll
        for (int i = 0; i < PER_T; i++) {
            int idx = t + i * 128;
            const h16* base; int g, row, chunk; uint32_t dstoff; bool valid;
            if (idx < 512) {
                row = idx >> 2; chunk = idx & 3;
                base = Abh;
                g = m0 + row; valid = g < M;
                dstoff = sw_off(row, chunk);
            } else {
                int idxb = idx - 512;
                int hl = idxb >= NTILE * 4;
                int r = idxb - hl * NTILE * 4;
                row = r >> 2; chunk = r & 3;
                base = hl ? Bbl : Bbh;
                g = n0 + row; valid = g < Nd;
                dstoff = ABYTES + hl * BSEG + sw_off(row, chunk);
            }
            CP_ASYNC(sbase + buf * BUF + dstoff,
                     base + (size_t)g * Kp + k0 + chunk * 8, valid ? 16 : 0);
        }
        CP_COMMIT();
    };

    float acc[4][2][4];
    #pragma unroll
    for (int mi = 0; mi < 4; mi++)
        #pragma unroll
        for (int ni = 0; ni < 2; ni++)
            #pragma unroll
            for (int q = 0; q < 4; q++) acc[mi][ni][q] = 0.0f;

    const int nk = Kp / 32;
    stage(0, 0);
    if (nk > 1) stage(1, 32);
    if (nk > 2) stage(2, 64);
    if (nk > 2)      { CP_WAIT2(); }
    else if (nk > 1) { CP_WAIT1(); }
    else             { CP_WAIT0(); }
    __syncthreads();

    for (int kt = 0; kt < nk; kt++) {
        const int buf = kt & 3;
        if (kt + 3 < nk) stage((kt + 3) & 3, (kt + 3) * 32);

        const uint32_t bb = sbase + buf * BUF;
        #pragma unroll
        for (int s = 0; s < 2; s++) {
            const int c0 = s * 2;
            const int arow = (lane & 15), achk = c0 + (lane >> 4);
            const int brow = (lane & 7) + ((lane & 16) >> 1);
            const int bchk = c0 + ((lane >> 3) & 1);

            uint32_t ah[4][4];
            #pragma unroll
            for (int mi = 0; mi < 4; mi++)
                LDMX4(ah[mi], bb + sw_off(mbase + mi * 16 + arow, achk));

            uint32_t bh[2][2], bl[2][2];
            {
                uint32_t r4[4];
                int rw = nbase + brow;
                LDMX4(r4, bb + ABYTES + sw_off(rw, bchk));
                bh[0][0] = r4[0]; bh[0][1] = r4[1];
                bh[1][0] = r4[2]; bh[1][1] = r4[3];
                LDMX4(r4, bb + ABYTES + BSEG + sw_off(rw, bchk));
                bl[0][0] = r4[0]; bl[0][1] = r4[1];
                bl[1][0] = r4[2]; bl[1][1] = r4[3];
            }
            #pragma unroll
            for (int mi = 0; mi < 4; mi++)
                #pragma unroll
                for (int nj = 0; nj < 2; nj++)
                    mma16816(acc[mi][nj], ah[mi], bh[nj]);
            #pragma unroll
            for (int mi = 0; mi < 4; mi++)
                #pragma unroll
                for (int nj = 0; nj < 2; nj++)
                    mma16816(acc[mi][nj], ah[mi], bl[nj]);
        }

        if (kt + 3 < nk)      { CP_WAIT2(); }
        else if (kt + 2 < nk) { CP_WAIT1(); }
        else if (kt + 1 < nk) { CP_WAIT0(); }
        if (kt + 1 < nk) __syncthreads();
    }

    float* cb = Cd + (size_t)bz * sC;
    #pragma unroll
    for (int mi = 0; mi < 4; mi++) {
        #pragma unroll
        for (int ni = 0; ni < 2; ni++) {
            int row = m0 + mbase + mi * 16 + (lane >> 2);
            int col = n0 + nbase + ni * 8 + (lane & 3) * 2;
            if (col < Nd) {
                if (row < M)
                    *(float2*)(cb + (size_t)row * Nd + col) =
                        make_float2(acc[mi][ni][0] * alpha, acc[mi][ni][1] * alpha);
                if (row + 8 < M)
                    *(float2*)(cb + (size_t)(row + 8) * Nd + col) =
                        make_float2(acc[mi][ni][2] * alpha, acc[mi][ni][3] * alpha);
            }
        }
    }
}

// ---------------------------------------------------------------------------
// fp32 (rows x cols) -> direct hi[/lo] (stride ds) + transposed hi/lo (stride ts)
// ---------------------------------------------------------------------------
__global__ __launch_bounds__(256) void k_split_both(
    const float* __restrict__ src,
    h16* __restrict__ dh, h16* __restrict__ dl, int ds,
    h16* __restrict__ th, h16* __restrict__ tl, int ts,
    int rows, int cols)
{
    __shared__ float tile[32][33];
    const int b = blockIdx.z;
    const int c0 = blockIdx.x * 32, r0 = blockIdx.y * 32;
    const float* s = src + (size_t)b * rows * cols;
    const size_t dbs = (size_t)b * rows * ds;
    const size_t tbs = (size_t)b * cols * ts;

    #pragma unroll
    for (int i = 0; i < 4; i++) {
        int r = r0 + threadIdx.y + i * 8, c = c0 + threadIdx.x;
        float v = s[(size_t)r * cols + c];
        tile[threadIdx.y + i * 8][threadIdx.x] = v;
        h16 h, l; split_h16(v, h, l);
        size_t o = dbs + (size_t)r * ds + c;
        dh[o] = h;
        if (dl) dl[o] = l;
    }
    __syncthreads();
    #pragma unroll
    for (int i = 0; i < 4; i++) {
        int tr = c0 + threadIdx.y + i * 8, tc = r0 + threadIdx.x;
        float v = tile[threadIdx.x][threadIdx.y + i * 8];
        h16 h, l; split_h16(v, h, l);
        size_t o = tbs + (size_t)tr * ts + tc;
        th[o] = h; tl[o] = l;
    }
}

// ---------------------------------------------------------------------------
// Fused: Z = scale[c]*Y + shift[c] + X, plus fp16 hi/lo split of Z (direct,
// stride Kp1) and its transpose (stride Cc).
// ---------------------------------------------------------------------------
__global__ __launch_bounds__(256) void k_bn_res_split(
    const float* __restrict__ Y, const float* __restrict__ X, float* __restrict__ Z,
    h16* __restrict__ dh, h16* __restrict__ dl,
    h16* __restrict__ th, h16* __restrict__ tl)
{
    __shared__ float tile[32][33];
    const int b = blockIdx.z;
    const int c0 = blockIdx.x * 32, r0 = blockIdx.y * 32;
    const size_t fb = (size_t)b * Cc * Nn;
    const size_t dbs = (size_t)b * Cc * Kp1;
    const size_t tbs = (size_t)b * Nn * Cc;

    #pragma unroll
    for (int i = 0; i < 4; i++) {
        int r = r0 + threadIdx.y + i * 8, c = c0 + threadIdx.x;
        size_t off = fb + (size_t)r * Nn + c;
        float z = fmaf(g_scale[r], Y[off], g_shift[r]) + X[off];
        Z[off] = z;
        tile[threadIdx.y + i * 8][threadIdx.x] = z;
        h16 h, l; split_h16(z, h, l);
        size_t o = dbs + (size_t)r * Kp1 + c;
        dh[o] = h; dl[o] = l;
    }
    __syncthreads();
    #pragma unroll
    for (int i = 0; i < 4; i++) {
        int tr = c0 + threadIdx.y + i * 8, tc = r0 + threadIdx.x;
        float v = tile[threadIdx.x][threadIdx.y + i * 8];
        h16 h, l; split_h16(v, h, l);
        size_t o = tbs + (size_t)tr * Cc + tc;
        th[o] = h; tl[o] = l;
    }
}

// ---------------------------------------------------------------------------
__global__ __launch_bounds__(288) void k_softmax_prior(const float* __restrict__ dis)
{
    int p = blockIdx.x, b = blockIdx.y, t = threadIdx.x;
    const float* f = g_F + ((size_t)b * Nn + p) * Nn;
    float v = f[t];
    float m1 = block_reduce(v, 0);
    float e1 = __expf(v - m1);
    float s1 = block_reduce(e1, 1);
    float w  = (e1 / s1) * dis[(size_t)p * Nn + t];
    float m2 = block_reduce(w, 0);
    float e2 = __expf(w - m2);
    float s2 = block_reduce(e2, 1);
    h16 h, l; split_h16(e2 / s2, h, l);
    size_t o = ((size_t)b * Nn + p) * Kp1 + t;
    g_Fh[o] = h; g_Fl[o] = l;
}

__global__ __launch_bounds__(256) void k_softmax_chan()
{
    size_t row = blockIdx.x;
    const float* f = g_F2 + row * (size_t)Cc;
    int t = threadIdx.x;
    float v[4];
    #pragma unroll
    for (int i = 0; i < 4; i++) v[i] = f[t + 256 * i];
    float m = block_reduce(fmaxf(fmaxf(v[0], v[1]), fmaxf(v[2], v[3])), 0);
    float e[4], ls = 0.0f;
    #pragma unroll
    for (int i = 0; i < 4; i++) { e[i] = __expf(v[i] - m); ls += e[i]; }
    float s = block_reduce(ls, 1);
    float inv = 1.0f / s;
    #pragma unroll
    for (int i = 0; i < 4; i++)
        g_F2h[row * (size_t)Cc + t + 256 * i] = __float2half(e[i] * inv);
}

__global__ __launch_bounds__(256) void k_bnstats(
    const float* __restrict__ Y,
    const float* __restrict__ gamma, const float* __restrict__ beta)
{
    int c = blockIdx.x, t = threadIdx.x;
    const int n4 = Nn / 4, tot4 = Bb * n4;
    float s = 0.0f, sq = 0.0f;
    #pragma unroll 4
    for (int idx = t; idx < tot4; idx += 256) {
        int b = idx / n4, i = idx - b * n4;
        float4 v = *(const float4*)(Y + ((size_t)b * Cc + c) * Nn + i * 4);
        s  += (v.x + v.y) + (v.z + v.w);
        sq += (v.x * v.x + v.y * v.y) + (v.z * v.z + v.w * v.w);
    }
    s = block_reduce(s, 1);
    sq = block_reduce(sq, 1);
    if (t == 0) {
        const float invN = 1.0f / (float)(Bb * Nn);
        float mean = s * invN;
        float var  = sq * invN - mean * mean;
        float sc = gamma[c] * rsqrtf(var + EPSv);
        g_scale[c] = sc;
        g_shift[c] = beta[c] - mean * sc;
    }
}

__global__ __launch_bounds__(256) void k_bn_apply_add(
    const float* __restrict__ Y, const float* __restrict__ R, float* __restrict__ out)
{
    size_t i4 = (size_t)blockIdx.x * blockDim.x + threadIdx.x;
    const size_t total4 = (size_t)Bb * Cc * Nn / 4;
    if (i4 >= total4) return;
    int c = (int)((i4 * 4 / Nn) % Cc);
    float4 y = ((const float4*)Y)[i4];
    float4 r = ((const float4*)R)[i4];
    float sc = g_scale[c], sh = g_shift[c];
    float4 o;
    o.x = fmaf(sc, y.x, sh) + r.x;
    o.y = fmaf(sc, y.y, sh) + r.y;
    o.z = fmaf(sc, y.z, sh) + r.z;
    o.w = fmaf(sc, y.w, sh) + r.w;
    ((float4*)out)[i4] = o;
}

// ---------------------------------------------------------------------------
extern "C" void kernel_launch(void* const* d_in, const int* in_sizes, int n_in,
                              void* d_out, int out_size)
{
    const float* x      = (const float*)d_in[0];
    const float* dis    = (const float*)d_in[1];
    const float* gamma1 = (const float*)d_in[2];
    const float* beta1  = (const float*)d_in[3];
    const float* gamma2 = (const float*)d_in[4];
    const float* beta2  = (const float*)d_in[5];
    float* out = (float*)d_out;

    float *pF, *pY, *pZ, *pY2, *pF2;
    cudaGetSymbolAddress((void**)&pF,  g_F);
    cudaGetSymbolAddress((void**)&pY,  g_Y);
    cudaGetSymbolAddress((void**)&pZ,  g_Z);
    cudaGetSymbolAddress((void**)&pY2, g_Y2);
    cudaGetSymbolAddress((void**)&pF2, g_F2);
    h16 *pXh,*pXTh,*pXTl,*pZh,*pZl,*pZTh,*pZTl,*pFh,*pFl,*pF2h;
    cudaGetSymbolAddress((void**)&pXh,  g_Xh);
    cudaGetSymbolAddress((void**)&pXTh, g_XTh); cudaGetSymbolAddress((void**)&pXTl, g_XTl);
    cudaGetSymbolAddress((void**)&pZh,  g_Zh);  cudaGetSymbolAddress((void**)&pZl,  g_Zl);
    cudaGetSymbolAddress((void**)&pZTh, g_ZTh); cudaGetSymbolAddress((void**)&pZTl, g_ZTl);
    cudaGetSymbolAddress((void**)&pFh,  g_Fh);  cudaGetSymbolAddress((void**)&pFl,  g_Fl);
    cudaGetSymbolAddress((void**)&pF2h, g_F2h);

    const int SM2 = 4 * 24576;   // 98304
    const int SMT = 4 * 12288;   // 49152
    static bool attr_set = false;
    if (!attr_set) {
        cudaFuncSetAttribute((const void*)k_mma256<true >,
                             cudaFuncAttributeMaxDynamicSharedMemorySize, SM2);
        cudaFuncSetAttribute((const void*)k_mma256<false>,
                             cudaFuncAttributeMaxDynamicSharedMemorySize, SM2);
        cudaFuncSetAttribute((const void*)k_mma_tail,
                             cudaFuncAttributeMaxDynamicSharedMemorySize, SMT);
        attr_set = true;
    }

    const size_t sX  = (size_t)Cc * Kp1;
    const size_t sXT = (size_t)Nn * Cc;
    const size_t sFb = (size_t)Nn * Kp1;
    const size_t sF  = (size_t)Nn * Nn;
    const size_t sYb = (size_t)Cc * Nn;
    const size_t sF2 = (size_t)Cc * Cc;

    // 0) split X -> Xh (hi only, Kp=320) + XT hi/lo (K=1024)
    k_split_both<<<dim3(Nn / 32, Cc / 32, Bb), dim3(32, 8)>>>(
        x, pXh, nullptr, Kp1, pXTh, pXTl, Cc, Cc, Nn);

    // 1) F = XT·XTᵀ / 32  (sym)  M=N=288, K=1024
    k_mma256<true><<<dim3(3, 3, Bb), 256, SM2>>>(
        pXTh, pXTh, pXTl, pF, Nn, Nn, Cc, 0, sXT, sXT, sF, 0.03125f);

    // 2) softmax+prior -> F hi/lo (Kp=320)
    k_softmax_prior<<<dim3(Nn, Bb), 288>>>(dis);

    // 3) Y = X·Fᵀ  M=1024, N=288, Kp=320: full tiles + 32-wide tail
    k_mma256<false><<<dim3(2, 8, Bb), 256, SM2>>>(
        pXh, pFh, pFl, pY, Cc, Nn, Kp1, 0, sX, sFb, sYb, 1.0f);
    k_mma_tail<<<dim3(1, 8, Bb), 128, SMT>>>(
        pXh, pFh, pFl, pY, Cc, Nn, Kp1, 256, sX, sFb, sYb, 1.0f);

    // 4) BN1 stats + fused (residual + Z split direct/transposed)
    k_bnstats<<<Cc, 256>>>(pY, gamma1, beta1);
    k_bn_res_split<<<dim3(Nn / 32, Cc / 32, Bb), dim3(32, 8)>>>(
        pY, x, pZ, pZh, pZl, pZTh, pZTl);

    // 6) F2 = Z·Zᵀ  (sym)  M=N=1024, Kp=320
    k_mma256<true><<<dim3(8, 8, Bb), 256, SM2>>>(
        pZh, pZh, pZl, pF2, Cc, Cc, Kp1, 0, sX, sX, sF2, 1.0f);

    // 7) softmax rows of F2 -> F2 hi
    k_softmax_chan<<<Bb * Cc, 256>>>();

    // 8) Y2 = F2·ZTᵀ  M=1024, N=288, K=1024: full tiles + tail
    k_mma256<false><<<dim3(2, 8, Bb), 256, SM2>>>(
        pF2h, pZTh, pZTl, pY2, Cc, Nn, Cc, 0, sF2, sXT, sYb, 1.0f);
    k_mma_tail<<<dim3(1, 8, Bb), 128, SMT>>>(
        pF2h, pZTh, pZTl, pY2, Cc, Nn, Cc, 256, sF2, sXT, sYb, 1.0f);

    // 9) BN2 + residual -> out
    k_bnstats<<<Cc, 256>>>(pY2, gamma2, beta2);
    k_bn_apply_add<<<(int)(((size_t)Bb * Cc * Nn / 4 + 255) / 256), 256>>>(pY2, pZ, out);
}

// round 14
// speedup vs baseline: 4.3277x; 1.0154x over previous
#include <cuda_runtime.h>
#include <cuda_fp16.h>
#include <math.h>
#include <stdint.h>

#define Bb   128
#define Cc   1024
#define Nn   288
#define Kp1  320            // padded K for K=288 (multiple of 32)
#define EPSv 1e-5f

typedef __half h16;

// fp32 scratch
__device__ float g_F [(size_t)Bb * Nn * Nn];
__device__ float g_Y [(size_t)Bb * Cc * Nn];
__device__ float g_Y2[(size_t)Bb * Cc * Nn];
__device__ float g_F2[(size_t)Bb * Cc * Cc];
__device__ float g_scale[Cc];
__device__ float g_shift[Cc];
// fp16 hi/lo K-major operands (pads stay zero: zero-init, never written)
__device__ h16 g_Xh [(size_t)Bb * Cc * Kp1];
__device__ h16 g_XTh[(size_t)Bb * Nn * Cc];
__device__ h16 g_XTl[(size_t)Bb * Nn * Cc];
__device__ h16 g_Zh [(size_t)Bb * Cc * Kp1];
__device__ h16 g_Zl [(size_t)Bb * Cc * Kp1];
__device__ h16 g_ZTh[(size_t)Bb * Nn * Cc];
__device__ h16 g_ZTl[(size_t)Bb * Nn * Cc];
__device__ h16 g_Fh [(size_t)Bb * Nn * Kp1];
__device__ h16 g_Fl [(size_t)Bb * Nn * Kp1];
__device__ h16 g_F2h[(size_t)Bb * Cc * Cc];

// ---------------- helpers ----------------
__device__ __forceinline__ uint32_t smem_u32(const void* p) {
    uint32_t a;
    asm("{ .reg .u64 t; cvta.to.shared.u64 t, %1; cvt.u32.u64 %0, t; }" : "=r"(a) : "l"(p));
    return a;
}
__device__ __forceinline__ void split_h16(float x, h16& h, h16& l) {
    h = __float2half(x);
    l = __float2half(x - __half2float(h));
}

#define LDMX4(r, a) \
    asm volatile("ldmatrix.sync.aligned.m8n8.x4.shared.b16 {%0,%1,%2,%3}, [%4];" \
        : "=r"((r)[0]), "=r"((r)[1]), "=r"((r)[2]), "=r"((r)[3]) : "r"(a))

__device__ __forceinline__ void mma16816(float* c, const uint32_t* a, const uint32_t* b) {
    asm volatile("mma.sync.aligned.m16n8k16.row.col.f32.f16.f16.f32 "
        "{%0,%1,%2,%3}, {%4,%5,%6,%7}, {%8,%9}, {%0,%1,%2,%3};"
        : "+f"(c[0]), "+f"(c[1]), "+f"(c[2]), "+f"(c[3])
        : "r"(a[0]), "r"(a[1]), "r"(a[2]), "r"(a[3]), "r"(b[0]), "r"(b[1]));
}

#define CP_ASYNC(dst, src, sz) \
    asm volatile("cp.async.cg.shared.global [%0], [%1], 16, %2;" \
        :: "r"(dst), "l"(src), "r"(sz) : "memory")
#define CP_COMMIT() asm volatile("cp.async.commit_group;" ::: "memory")
#define CP_WAIT2()  asm volatile("cp.async.wait_group 2;" ::: "memory")
#define CP_WAIT1()  asm volatile("cp.async.wait_group 1;" ::: "memory")
#define CP_WAIT0()  asm volatile("cp.async.wait_group 0;" ::: "memory")

// conflict-free swizzle (R11): residues {c^j, 4+c^j} distinct over 8-row phase
__device__ __forceinline__ uint32_t sw_off(int row, int chunk) {
    return (uint32_t)((row * 4 + (chunk ^ ((row >> 1) & 3))) * 16);
}

// ---------------- block reduce ----------------
__device__ __forceinline__ float block_reduce(float v, int op) {
    __shared__ float red[32];
    #pragma unroll
    for (int o = 16; o > 0; o >>= 1) {
        float u = __shfl_xor_sync(0xffffffffu, v, o);
        v = op ? (v + u) : fmaxf(v, u);
    }
    int lane = threadIdx.x & 31, wid = threadIdx.x >> 5;
    int nw = (blockDim.x + 31) >> 5;
    if (lane == 0) red[wid] = v;
    __syncthreads();
    if (wid == 0) {
        float r = (lane < nw) ? red[lane] : (op ? 0.0f : -3.4e38f);
        #pragma unroll
        for (int o = 16; o > 0; o >>= 1) {
            float u = __shfl_xor_sync(0xffffffffu, r, o);
            r = op ? (r + u) : fmaxf(r, u);
        }
        if (lane == 0) red[0] = r;
    }
    __syncthreads();
    float r = red[0];
    __syncthreads();
    return r;
}

// ---------------------------------------------------------------------------
// 256-thread HMMA GEMM, NTILE=128 (fp16 2-pass split): C = alpha * A·Bᵀ
// 8 warps in 2(m)x4(n) grid, warp tile 64x32 — 16 warps/SM (4 per SMSP).
// 4-stage cp.async pipeline, one __syncthreads per k-chunk.
// ---------------------------------------------------------------------------
template<bool SYM>
__global__ __launch_bounds__(256, 2) void k_mma256(
    const h16* __restrict__ Ah,
    const h16* __restrict__ Bh, const h16* __restrict__ Bl,
    float* __restrict__ Cd, int M, int Nd, int Kp, int n_off,
    size_t sA, size_t sB, size_t sC, float alpha)
{
    constexpr int ABYTES = 8192;
    constexpr int BSEG   = 8192;
    constexpr int BUF    = ABYTES + 2 * BSEG;   // 24576

    extern __shared__ __align__(16) char dsm[];
    const int bx = blockIdx.x, by = blockIdx.y, bz = blockIdx.z;
    if (SYM && bx < by) return;
    const int m0 = by * 128, n0 = n_off + bx * 128;
    const int t = threadIdx.x;
    const int lane = t & 31, wid = t >> 5;
    const int mbase = (wid >> 2) * 64, nbase = (wid & 3) * 32;

    const h16* Abh = Ah + (size_t)bz * sA;
    const h16* Bbh = Bh + (size_t)bz * sB;
    const h16* Bbl = Bl + (size_t)bz * sB;

    const uint32_t sbase = smem_u32(dsm);

    auto stage = [&](int buf, int k0) {
        #pragma unroll
        for (int i = 0; i < 6; i++) {
            int idx = t + i * 256;              // 0..1535
            const h16* base; int g, row, chunk; uint32_t dstoff; bool valid;
            if (idx < 512) {                    // A: 128 rows x 4 chunks
                row = idx >> 2; chunk = idx & 3;
                base = Abh;
                g = m0 + row; valid = g < M;
                dstoff = sw_off(row, chunk);
            } else {                            // B hi then lo
                int idxb = idx - 512;
                int hl = idxb >= 512;
                int r = idxb - hl * 512;
                row = r >> 2; chunk = r & 3;
                base = hl ? Bbl : Bbh;
                g = n0 + row; valid = g < Nd;
                dstoff = ABYTES + hl * BSEG + sw_off(row, chunk);
            }
            CP_ASYNC(sbase + buf * BUF + dstoff,
                     base + (size_t)g * Kp + k0 + chunk * 8, valid ? 16 : 0);
        }
        CP_COMMIT();
    };

    float acc[4][4][4];
    #pragma unroll
    for (int mi = 0; mi < 4; mi++)
        #pragma unroll
        for (int ni = 0; ni < 4; ni++)
            #pragma unroll
            for (int q = 0; q < 4; q++) acc[mi][ni][q] = 0.0f;

    const int nk = Kp / 32;
    stage(0, 0);
    if (nk > 1) stage(1, 32);
    if (nk > 2) stage(2, 64);
    if (nk > 2)      { CP_WAIT2(); }
    else if (nk > 1) { CP_WAIT1(); }
    else             { CP_WAIT0(); }
    __syncthreads();

    for (int kt = 0; kt < nk; kt++) {
        const int buf = kt & 3;
        if (kt + 3 < nk) stage((kt + 3) & 3, (kt + 3) * 32);

        const uint32_t bb = sbase + buf * BUF;
        #pragma unroll
        for (int s = 0; s < 2; s++) {
            const int c0 = s * 2;
            const int arow = (lane & 15), achk = c0 + (lane >> 4);
            const int brow = (lane & 7) + ((lane & 16) >> 1);
            const int bchk = c0 + ((lane >> 3) & 1);

            uint32_t ah[4][4];
            #pragma unroll
            for (int mi = 0; mi < 4; mi++)
                LDMX4(ah[mi], bb + sw_off(mbase + mi * 16 + arow, achk));

            uint32_t bh[4][2], bl[4][2];
            #pragma unroll
            for (int h = 0; h < 2; h++) {
                uint32_t r4[4];
                int rw = nbase + h * 16 + brow;
                LDMX4(r4, bb + ABYTES + sw_off(rw, bchk));
                bh[h*2][0] = r4[0]; bh[h*2][1] = r4[1];
                bh[h*2+1][0] = r4[2]; bh[h*2+1][1] = r4[3];
                LDMX4(r4, bb + ABYTES + BSEG + sw_off(rw, bchk));
                bl[h*2][0] = r4[0]; bl[h*2][1] = r4[1];
                bl[h*2+1][0] = r4[2]; bl[h*2+1][1] = r4[3];
            }
            // pass 1: all hi*hi (16 independent)
            #pragma unroll
            for (int mi = 0; mi < 4; mi++)
                #pragma unroll
                for (int nj = 0; nj < 4; nj++)
                    mma16816(acc[mi][nj], ah[mi], bh[nj]);
            // pass 2: all hi*lo
            #pragma unroll
            for (int mi = 0; mi < 4; mi++)
                #pragma unroll
                for (int nj = 0; nj < 4; nj++)
                    mma16816(acc[mi][nj], ah[mi], bl[nj]);
        }

        if (kt + 3 < nk)      { CP_WAIT2(); }
        else if (kt + 2 < nk) { CP_WAIT1(); }
        else if (kt + 1 < nk) { CP_WAIT0(); }
        if (kt + 1 < nk) __syncthreads();
    }

    // epilogue (+ mirror for SYM off-diagonal blocks)
    float* cb = Cd + (size_t)bz * sC;
    #pragma unroll
    for (int mi = 0; mi < 4; mi++) {
        #pragma unroll
        for (int ni = 0; ni < 4; ni++) {
            int row = m0 + mbase + mi * 16 + (lane >> 2);
            int col = n0 + nbase + ni * 8 + (lane & 3) * 2;
            float v0 = acc[mi][ni][0] * alpha, v1 = acc[mi][ni][1] * alpha;
            float v2 = acc[mi][ni][2] * alpha, v3 = acc[mi][ni][3] * alpha;
            if (col < Nd) {
                if (row < M)
                    *(float2*)(cb + (size_t)row * Nd + col) = make_float2(v0, v1);
                if (row + 8 < M)
                    *(float2*)(cb + (size_t)(row + 8) * Nd + col) = make_float2(v2, v3);
            }
            if (SYM && bx > by && col < M && row < Nd) {
                cb[(size_t)col * Nd + row] = v0;
                cb[(size_t)(col + 1) * Nd + row] = v1;
                if (row + 8 < Nd) {
                    cb[(size_t)col * Nd + row + 8] = v2;
                    cb[(size_t)(col + 1) * Nd + row + 8] = v3;
                }
            }
        }
    }
}

// ---------------------------------------------------------------------------
// 128-thread tail GEMM, NTILE=32 (fp16 2-pass split). Warp grid 2x2, tile 64x16.
// ---------------------------------------------------------------------------
__global__ __launch_bounds__(128, 2) void k_mma_tail(
    const h16* __restrict__ Ah,
    const h16* __restrict__ Bh, const h16* __restrict__ Bl,
    float* __restrict__ Cd, int M, int Nd, int Kp, int n_off,
    size_t sA, size_t sB, size_t sC, float alpha)
{
    constexpr int NTILE  = 32;
    constexpr int ABYTES = 8192;
    constexpr int BSEG   = NTILE * 64;          // 2048
    constexpr int BUF    = ABYTES + 2 * BSEG;   // 12288
    constexpr int PER_T  = (512 + NTILE * 8) / 128;   // 6

    extern __shared__ __align__(16) char dsm[];
    const int bx = blockIdx.x, by = blockIdx.y, bz = blockIdx.z;
    const int m0 = by * 128, n0 = n_off + bx * NTILE;
    const int t = threadIdx.x;
    const int lane = t & 31, wid = t >> 5;
    const int mbase = (wid >> 1) * 64, nbase = (wid & 1) * 16;

    const h16* Abh = Ah + (size_t)bz * sA;
    const h16* Bbh = Bh + (size_t)bz * sB;
    const h16* Bbl = Bl + (size_t)bz * sB;

    const uint32_t sbase = smem_u32(dsm);

    auto stage = [&](int buf, int k0) {
        #pragma unroll
        for (int i = 0; i < PER_T; i++) {
            int idx = t + i * 128;
            const h16* base; int g, row, chunk; uint32_t dstoff; bool valid;
            if (idx < 512) {
                row = idx >> 2; chunk = idx & 3;
                base = Abh;
                g = m0 + row; valid = g < M;
                dstoff = sw_off(row, chunk);
            } else {
                int idxb = idx - 512;
                int hl = idxb >= NTILE * 4;
                int r = idxb - hl * NTILE * 4;
                row = r >> 2; chunk = r & 3;
                base = hl ? Bbl : Bbh;
                g = n0 + row; valid = g < Nd;
                dstoff = ABYTES + hl * BSEG + sw_off(row, chunk);
            }
            CP_ASYNC(sbase + buf * BUF + dstoff,
                     base + (size_t)g * Kp + k0 + chunk * 8, valid ? 16 : 0);
        }
        CP_COMMIT();
    };

    float acc[4][2][4];
    #pragma unroll
    for (int mi = 0; mi < 4; mi++)
        #pragma unroll
        for (int ni = 0; ni < 2; ni++)
            #pragma unroll
            for (int q = 0; q < 4; q++) acc[mi][ni][q] = 0.0f;

    const int nk = Kp / 32;
    stage(0, 0);
    if (nk > 1) stage(1, 32);
    if (nk > 2) stage(2, 64);
    if (nk > 2)      { CP_WAIT2(); }
    else if (nk > 1) { CP_WAIT1(); }
    else             { CP_WAIT0(); }
    __syncthreads();

    for (int kt = 0; kt < nk; kt++) {
        const int buf = kt & 3;
        if (kt + 3 < nk) stage((kt + 3) & 3, (kt + 3) * 32);

        const uint32_t bb = sbase + buf * BUF;
        #pragma unroll
        for (int s = 0; s < 2; s++) {
            const int c0 = s * 2;
            const int arow = (lane & 15), achk = c0 + (lane >> 4);
            const int brow = (lane & 7) + ((lane & 16) >> 1);
            const int bchk = c0 + ((lane >> 3) & 1);

            uint32_t ah[4][4];
            #pragma unroll
            for (int mi = 0; mi < 4; mi++)
                LDMX4(ah[mi], bb + sw_off(mbase + mi * 16 + arow, achk));

            uint32_t bh[2][2], bl[2][2];
            {
                uint32_t r4[4];
                int rw = nbase + brow;
                LDMX4(r4, bb + ABYTES + sw_off(rw, bchk));
                bh[0][0] = r4[0]; bh[0][1] = r4[1];
                bh[1][0] = r4[2]; bh[1][1] = r4[3];
                LDMX4(r4, bb + ABYTES + BSEG + sw_off(rw, bchk));
                bl[0][0] = r4[0]; bl[0][1] = r4[1];
                bl[1][0] = r4[2]; bl[1][1] = r4[3];
            }
            #pragma unroll
            for (int mi = 0; mi < 4; mi++)
                #pragma unroll
                for (int nj = 0; nj < 2; nj++)
                    mma16816(acc[mi][nj], ah[mi], bh[nj]);
            #pragma unroll
            for (int mi = 0; mi < 4; mi++)
                #pragma unroll
                for (int nj = 0; nj < 2; nj++)
                    mma16816(acc[mi][nj], ah[mi], bl[nj]);
        }

        if (kt + 3 < nk)      { CP_WAIT2(); }
        else if (kt + 2 < nk) { CP_WAIT1(); }
        else if (kt + 1 < nk) { CP_WAIT0(); }
        if (kt + 1 < nk) __syncthreads();
    }

    float* cb = Cd + (size_t)bz * sC;
    #pragma unroll
    for (int mi = 0; mi < 4; mi++) {
        #pragma unroll
        for (int ni = 0; ni < 2; ni++) {
            int row = m0 + mbase + mi * 16 + (lane >> 2);
            int col = n0 + nbase + ni * 8 + (lane & 3) * 2;
            if (col < Nd) {
                if (row < M)
                    *(float2*)(cb + (size_t)row * Nd + col) =
                        make_float2(acc[mi][ni][0] * alpha, acc[mi][ni][1] * alpha);
                if (row + 8 < M)
                    *(float2*)(cb + (size_t)(row + 8) * Nd + col) =
                        make_float2(acc[mi][ni][2] * alpha, acc[mi][ni][3] * alpha);
            }
        }
    }
}

// ---------------------------------------------------------------------------
// fp32 (rows x cols) -> direct hi[/lo] (stride ds) + transposed hi/lo (stride ts)
// ---------------------------------------------------------------------------
__global__ __launch_bounds__(256) void k_split_both(
    const float* __restrict__ src,
    h16* __restrict__ dh, h16* __restrict__ dl, int ds,
    h16* __restrict__ th, h16* __restrict__ tl, int ts,
    int rows, int cols)
{
    __shared__ float tile[32][33];
    const int b = blockIdx.z;
    const int c0 = blockIdx.x * 32, r0 = blockIdx.y * 32;
    const float* s = src + (size_t)b * rows * cols;
    const size_t dbs = (size_t)b * rows * ds;
    const size_t tbs = (size_t)b * cols * ts;

    #pragma unroll
    for (int i = 0; i < 4; i++) {
        int r = r0 + threadIdx.y + i * 8, c = c0 + threadIdx.x;
        float v = s[(size_t)r * cols + c];
        tile[threadIdx.y + i * 8][threadIdx.x] = v;
        h16 h, l; split_h16(v, h, l);
        size_t o = dbs + (size_t)r * ds + c;
        dh[o] = h;
        if (dl) dl[o] = l;
    }
    __syncthreads();
    #pragma unroll
    for (int i = 0; i < 4; i++) {
        int tr = c0 + threadIdx.y + i * 8, tc = r0 + threadIdx.x;
        float v = tile[threadIdx.x][threadIdx.y + i * 8];
        h16 h, l; split_h16(v, h, l);
        size_t o = tbs + (size_t)tr * ts + tc;
        th[o] = h; tl[o] = l;
    }
}

// ---------------------------------------------------------------------------
// Fused: z = scale[c]*Y + shift[c] + X (fp32 z NOT stored), writes fp16 hi/lo
// split of z (direct, stride Kp1) and its transpose (stride Cc).
// ---------------------------------------------------------------------------
__global__ __launch_bounds__(256) void k_bn_res_split(
    const float* __restrict__ Y, const float* __restrict__ X,
    h16* __restrict__ dh, h16* __restrict__ dl,
    h16* __restrict__ th, h16* __restrict__ tl)
{
    __shared__ float tile[32][33];
    const int b = blockIdx.z;
    const int c0 = blockIdx.x * 32, r0 = blockIdx.y * 32;
    const size_t fb = (size_t)b * Cc * Nn;
    const size_t dbs = (size_t)b * Cc * Kp1;
    const size_t tbs = (size_t)b * Nn * Cc;

    #pragma unroll
    for (int i = 0; i < 4; i++) {
        int r = r0 + threadIdx.y + i * 8, c = c0 + threadIdx.x;
        size_t off = fb + (size_t)r * Nn + c;
        float z = fmaf(g_scale[r], Y[off], g_shift[r]) + X[off];
        tile[threadIdx.y + i * 8][threadIdx.x] = z;
        h16 h, l; split_h16(z, h, l);
        size_t o = dbs + (size_t)r * Kp1 + c;
        dh[o] = h; dl[o] = l;
    }
    __syncthreads();
    #pragma unroll
    for (int i = 0; i < 4; i++) {
        int tr = c0 + threadIdx.y + i * 8, tc = r0 + threadIdx.x;
        float v = tile[threadIdx.x][threadIdx.y + i * 8];
        h16 h, l; split_h16(v, h, l);
        size_t o = tbs + (size_t)tr * Cc + tc;
        th[o] = h; tl[o] = l;
    }
}

// ---------------------------------------------------------------------------
__global__ __launch_bounds__(288) void k_softmax_prior(const float* __restrict__ dis)
{
    int p = blockIdx.x, b = blockIdx.y, t = threadIdx.x;
    const float* f = g_F + ((size_t)b * Nn + p) * Nn;
    float v = f[t];
    float m1 = block_reduce(v, 0);
    float e1 = __expf(v - m1);
    float s1 = block_reduce(e1, 1);
    float w  = (e1 / s1) * dis[(size_t)p * Nn + t];
    float m2 = block_reduce(w, 0);
    float e2 = __expf(w - m2);
    float s2 = block_reduce(e2, 1);
    h16 h, l; split_h16(e2 / s2, h, l);
    size_t o = ((size_t)b * Nn + p) * Kp1 + t;
    g_Fh[o] = h; g_Fl[o] = l;
}

// rows of g_F2 (len 1024): 256 threads x 4 contiguous, float4/half2 vectorized
__global__ __launch_bounds__(256) void k_softmax_chan()
{
    size_t row = blockIdx.x;
    const float* f = g_F2 + row * (size_t)Cc;
    int t = threadIdx.x;
    float4 v4 = ((const float4*)f)[t];
    float v[4] = {v4.x, v4.y, v4.z, v4.w};
    float m = block_reduce(fmaxf(fmaxf(v[0], v[1]), fmaxf(v[2], v[3])), 0);
    float e[4], ls = 0.0f;
    #pragma unroll
    for (int i = 0; i < 4; i++) { e[i] = __expf(v[i] - m); ls += e[i]; }
    float s = block_reduce(ls, 1);
    float inv = 1.0f / s;
    __half2 h0 = __floats2half2_rn(e[0] * inv, e[1] * inv);
    __half2 h1 = __floats2half2_rn(e[2] * inv, e[3] * inv);
    uint2 pk = make_uint2(*(uint32_t*)&h0, *(uint32_t*)&h1);
    ((uint2*)(g_F2h + row * (size_t)Cc))[t] = pk;
}

__global__ __launch_bounds__(256) void k_bnstats(
    const float* __restrict__ Y,
    const float* __restrict__ gamma, const float* __restrict__ beta)
{
    int c = blockIdx.x, t = threadIdx.x;
    const int n4 = Nn / 4, tot4 = Bb * n4;
    float s = 0.0f, sq = 0.0f;
    #pragma unroll 4
    for (int idx = t; idx < tot4; idx += 256) {
        int b = idx / n4, i = idx - b * n4;
        float4 v = *(const float4*)(Y + ((size_t)b * Cc + c) * Nn + i * 4);
        s  += (v.x + v.y) + (v.z + v.w);
        sq += (v.x * v.x + v.y * v.y) + (v.z * v.z + v.w * v.w);
    }
    s = block_reduce(s, 1);
    sq = block_reduce(sq, 1);
    if (t == 0) {
        const float invN = 1.0f / (float)(Bb * Nn);
        float mean = s * invN;
        float var  = sq * invN - mean * mean;
        float sc = gamma[c] * rsqrtf(var + EPSv);
        g_scale[c] = sc;
        g_shift[c] = beta[c] - mean * sc;
    }
}

// out = scale[c]*Y2 + shift[c] + (Zh + Zl)   (residual reconstructed from split)
__global__ __launch_bounds__(256) void k_bn_apply_add_h(
    const float* __restrict__ Y, float* __restrict__ out)
{
    size_t i4 = (size_t)blockIdx.x * blockDim.x + threadIdx.x;
    const size_t total4 = (size_t)Bb * Cc * Nn / 4;
    if (i4 >= total4) return;
    size_t e = i4 * 4;
    int b = (int)(e / ((size_t)Cc * Nn));
    int rem = (int)(e - (size_t)b * Cc * Nn);
    int c = rem / Nn;
    int n = rem - c * Nn;
    float4 y = ((const float4*)Y)[i4];
    size_t zo = (size_t)b * Cc * Kp1 + (size_t)c * Kp1 + n;
    uint2 zhp = *(const uint2*)(g_Zh + zo);
    uint2 zlp = *(const uint2*)(g_Zl + zo);
    __half2 zh0 = *(__half2*)&zhp.x, zh1 = *(__half2*)&zhp.y;
    __half2 zl0 = *(__half2*)&zlp.x, zl1 = *(__half2*)&zlp.y;
    float r0 = __low2float(zh0) + __low2float(zl0);
    float r1 = __high2float(zh0) + __high2float(zl0);
    float r2 = __low2float(zh1) + __low2float(zl1);
    float r3 = __high2float(zh1) + __high2float(zl1);
    float sc = g_scale[c], sh = g_shift[c];
    float4 o;
    o.x = fmaf(sc, y.x, sh) + r0;
    o.y = fmaf(sc, y.y, sh) + r1;
    o.z = fmaf(sc, y.z, sh) + r2;
    o.w = fmaf(sc, y.w, sh) + r3;
    ((float4*)out)[i4] = o;
}

// ---------------------------------------------------------------------------
extern "C" void kernel_launch(void* const* d_in, const int* in_sizes, int n_in,
                              void* d_out, int out_size)
{
    const float* x      = (const float*)d_in[0];
    const float* dis    = (const float*)d_in[1];
    const float* gamma1 = (const float*)d_in[2];
    const float* beta1  = (const float*)d_in[3];
    const float* gamma2 = (const float*)d_in[4];
    const float* beta2  = (const float*)d_in[5];
    float* out = (float*)d_out;

    float *pF, *pY, *pY2, *pF2;
    cudaGetSymbolAddress((void**)&pF,  g_F);
    cudaGetSymbolAddress((void**)&pY,  g_Y);
    cudaGetSymbolAddress((void**)&pY2, g_Y2);
    cudaGetSymbolAddress((void**)&pF2, g_F2);
    h16 *pXh,*pXTh,*pXTl,*pZh,*pZl,*pZTh,*pZTl,*pFh,*pFl,*pF2h;
    cudaGetSymbolAddress((void**)&pXh,  g_Xh);
    cudaGetSymbolAddress((void**)&pXTh, g_XTh); cudaGetSymbolAddress((void**)&pXTl, g_XTl);
    cudaGetSymbolAddress((void**)&pZh,  g_Zh);  cudaGetSymbolAddress((void**)&pZl,  g_Zl);
    cudaGetSymbolAddress((void**)&pZTh, g_ZTh); cudaGetSymbolAddress((void**)&pZTl, g_ZTl);
    cudaGetSymbolAddress((void**)&pFh,  g_Fh);  cudaGetSymbolAddress((void**)&pFl,  g_Fl);
    cudaGetSymbolAddress((void**)&pF2h, g_F2h);

    const int SM2 = 4 * 24576;   // 98304
    const int SMT = 4 * 12288;   // 49152
    static bool attr_set = false;
    if (!attr_set) {
        cudaFuncSetAttribute((const void*)k_mma256<true >,
                             cudaFuncAttributeMaxDynamicSharedMemorySize, SM2);
        cudaFuncSetAttribute((const void*)k_mma256<false>,
                             cudaFuncAttributeMaxDynamicSharedMemorySize, SM2);
        cudaFuncSetAttribute((const void*)k_mma_tail,
                             cudaFuncAttributeMaxDynamicSharedMemorySize, SMT);
        attr_set = true;
    }

    const size_t sX  = (size_t)Cc * Kp1;
    const size_t sXT = (size_t)Nn * Cc;
    const size_t sFb = (size_t)Nn * Kp1;
    const size_t sF  = (size_t)Nn * Nn;
    const size_t sYb = (size_t)Cc * Nn;
    const size_t sF2 = (size_t)Cc * Cc;

    // 0) split X -> Xh (hi only, Kp=320) + XT hi/lo (K=1024)
    k_split_both<<<dim3(Nn / 32, Cc / 32, Bb), dim3(32, 8)>>>(
        x, pXh, nullptr, Kp1, pXTh, pXTl, Cc, Cc, Nn);

    // 1) F = XT·XTᵀ / 32  (sym)  M=N=288, K=1024
    k_mma256<true><<<dim3(3, 3, Bb), 256, SM2>>>(
        pXTh, pXTh, pXTl, pF, Nn, Nn, Cc, 0, sXT, sXT, sF, 0.03125f);

    // 2) softmax+prior -> F hi/lo (Kp=320)
    k_softmax_prior<<<dim3(Nn, Bb), 288>>>(dis);

    // 3) Y = X·Fᵀ  M=1024, N=288, Kp=320: full tiles + 32-wide tail
    k_mma256<false><<<dim3(2, 8, Bb), 256, SM2>>>(
        pXh, pFh, pFl, pY, Cc, Nn, Kp1, 0, sX, sFb, sYb, 1.0f);
    k_mma_tail<<<dim3(1, 8, Bb), 128, SMT>>>(
        pXh, pFh, pFl, pY, Cc, Nn, Kp1, 256, sX, sFb, sYb, 1.0f);

    // 4) BN1 stats + fused (residual + Z split direct/transposed; no fp32 Z)
    k_bnstats<<<Cc, 256>>>(pY, gamma1, beta1);
    k_bn_res_split<<<dim3(Nn / 32, Cc / 32, Bb), dim3(32, 8)>>>(
        pY, x, pZh, pZl, pZTh, pZTl);

    // 6) F2 = Z·Zᵀ  (sym)  M=N=1024, Kp=320
    k_mma256<true><<<dim3(8, 8, Bb), 256, SM2>>>(
        pZh, pZh, pZl, pF2, Cc, Cc, Kp1, 0, sX, sX, sF2, 1.0f);

    // 7) softmax rows of F2 -> F2 hi
    k_softmax_chan<<<Bb * Cc, 256>>>();

    // 8) Y2 = F2·ZTᵀ  M=1024, N=288, K=1024: full tiles + tail
    k_mma256<false><<<dim3(2, 8, Bb), 256, SM2>>>(
        pF2h, pZTh, pZTl, pY2, Cc, Nn, Cc, 0, sF2, sXT, sYb, 1.0f);
    k_mma_tail<<<dim3(1, 8, Bb), 128, SMT>>>(
        pF2h, pZTh, pZTl, pY2, Cc, Nn, Cc, 256, sF2, sXT, sYb, 1.0f);

    // 9) BN2 stats + final: out = bn2(Y2) + (Zh+Zl)
    k_bnstats<<<Cc, 256>>>(pY2, gamma2, beta2);
    k_bn_apply_add_h<<<(int)(((size_t)Bb * Cc * Nn / 4 + 255) / 256), 256>>>(pY2, out);
}

// round 15
// speedup vs baseline: 4.3420x; 1.0033x over previous
#include <cuda_runtime.h>
#include <cuda_fp16.h>
#include <math.h>
#include <stdint.h>

#define Bb   128
#define Cc   1024
#define Nn   288
#define Kp1  320            // padded K for K=288 (multiple of 32)
#define EPSv 1e-5f

typedef __half h16;

// fp32 scratch
__device__ float g_F [(size_t)Bb * Nn * Nn];
__device__ float g_Y [(size_t)Bb * Cc * Nn];
__device__ float g_Y2[(size_t)Bb * Cc * Nn];
__device__ float g_F2[(size_t)Bb * Cc * Cc];
__device__ float g_scale[Cc];
__device__ float g_shift[Cc];
// fp16 hi/lo K-major operands (pads stay zero: zero-init, never written)
__device__ h16 g_Xh [(size_t)Bb * Cc * Kp1];
__device__ h16 g_XTh[(size_t)Bb * Nn * Cc];
__device__ h16 g_XTl[(size_t)Bb * Nn * Cc];
__device__ h16 g_Zh [(size_t)Bb * Cc * Kp1];
__device__ h16 g_Zl [(size_t)Bb * Cc * Kp1];
__device__ h16 g_ZTh[(size_t)Bb * Nn * Cc];
__device__ h16 g_ZTl[(size_t)Bb * Nn * Cc];
__device__ h16 g_Fh [(size_t)Bb * Nn * Kp1];
__device__ h16 g_Fl [(size_t)Bb * Nn * Kp1];
__device__ h16 g_F2h[(size_t)Bb * Cc * Cc];

// ---------------- helpers ----------------
__device__ __forceinline__ uint32_t smem_u32(const void* p) {
    uint32_t a;
    asm("{ .reg .u64 t; cvta.to.shared.u64 t, %1; cvt.u32.u64 %0, t; }" : "=r"(a) : "l"(p));
    return a;
}
__device__ __forceinline__ void split_h16(float x, h16& h, h16& l) {
    h = __float2half(x);
    l = __float2half(x - __half2float(h));
}

#define LDMX4(r, a) \
    asm volatile("ldmatrix.sync.aligned.m8n8.x4.shared.b16 {%0,%1,%2,%3}, [%4];" \
        : "=r"((r)[0]), "=r"((r)[1]), "=r"((r)[2]), "=r"((r)[3]) : "r"(a))

__device__ __forceinline__ void mma16816(float* c, const uint32_t* a, const uint32_t* b) {
    asm volatile("mma.sync.aligned.m16n8k16.row.col.f32.f16.f16.f32 "
        "{%0,%1,%2,%3}, {%4,%5,%6,%7}, {%8,%9}, {%0,%1,%2,%3};"
        : "+f"(c[0]), "+f"(c[1]), "+f"(c[2]), "+f"(c[3])
        : "r"(a[0]), "r"(a[1]), "r"(a[2]), "r"(a[3]), "r"(b[0]), "r"(b[1]));
}

#define CP_ASYNC(dst, src, sz) \
    asm volatile("cp.async.cg.shared.global [%0], [%1], 16, %2;" \
        :: "r"(dst), "l"(src), "r"(sz) : "memory")
#define CP_COMMIT() asm volatile("cp.async.commit_group;" ::: "memory")
#define CP_WAIT2()  asm volatile("cp.async.wait_group 2;" ::: "memory")
#define CP_WAIT1()  asm volatile("cp.async.wait_group 1;" ::: "memory")
#define CP_WAIT0()  asm volatile("cp.async.wait_group 0;" ::: "memory")

// conflict-free swizzle (R11): residues {c^j, 4+c^j} distinct over 8-row phase
__device__ __forceinline__ uint32_t sw_off(int row, int chunk) {
    return (uint32_t)((row * 4 + (chunk ^ ((row >> 1) & 3))) * 16);
}

// ---------------- block reduce ----------------
__device__ __forceinline__ float block_reduce(float v, int op) {
    __shared__ float red[32];
    #pragma unroll
    for (int o = 16; o > 0; o >>= 1) {
        float u = __shfl_xor_sync(0xffffffffu, v, o);
        v = op ? (v + u) : fmaxf(v, u);
    }
    int lane = threadIdx.x & 31, wid = threadIdx.x >> 5;
    int nw = (blockDim.x + 31) >> 5;
    if (lane == 0) red[wid] = v;
    __syncthreads();
    if (wid == 0) {
        float r = (lane < nw) ? red[lane] : (op ? 0.0f : -3.4e38f);
        #pragma unroll
        for (int o = 16; o > 0; o >>= 1) {
            float u = __shfl_xor_sync(0xffffffffu, r, o);
            r = op ? (r + u) : fmaxf(r, u);
        }
        if (lane == 0) red[0] = r;
    }
    __syncthreads();
    float r = red[0];
    __syncthreads();
    return r;
}

// ---------------------------------------------------------------------------
// 256-thread HMMA GEMM, NTILE=128 (fp16 2-pass split): C = alpha * A·Bᵀ
// For symmetric grams (F, F2). 8 warps 2x4, warp tile 64x32.
// ---------------------------------------------------------------------------
template<bool SYM>
__global__ __launch_bounds__(256, 2) void k_mma256(
    const h16* __restrict__ Ah,
    const h16* __restrict__ Bh, const h16* __restrict__ Bl,
    float* __restrict__ Cd, int M, int Nd, int Kp,
    size_t sA, size_t sB, size_t sC, float alpha)
{
    constexpr int ABYTES = 8192;
    constexpr int BSEG   = 8192;
    constexpr int BUF    = ABYTES + 2 * BSEG;   // 24576

    extern __shared__ __align__(16) char dsm[];
    const int bx = blockIdx.x, by = blockIdx.y, bz = blockIdx.z;
    if (SYM && bx < by) return;
    const int m0 = by * 128, n0 = bx * 128;
    const int t = threadIdx.x;
    const int lane = t & 31, wid = t >> 5;
    const int mbase = (wid >> 2) * 64, nbase = (wid & 3) * 32;

    const h16* Abh = Ah + (size_t)bz * sA;
    const h16* Bbh = Bh + (size_t)bz * sB;
    const h16* Bbl = Bl + (size_t)bz * sB;

    const uint32_t sbase = smem_u32(dsm);

    auto stage = [&](int buf, int k0) {
        #pragma unroll
        for (int i = 0; i < 6; i++) {
            int idx = t + i * 256;              // 0..1535
            const h16* base; int g, row, chunk; uint32_t dstoff; bool valid;
            if (idx < 512) {                    // A: 128 rows x 4 chunks
                row = idx >> 2; chunk = idx & 3;
                base = Abh;
                g = m0 + row; valid = g < M;
                dstoff = sw_off(row, chunk);
            } else {                            // B hi then lo
                int idxb = idx - 512;
                int hl = idxb >= 512;
                int r = idxb - hl * 512;
                row = r >> 2; chunk = r & 3;
                base = hl ? Bbl : Bbh;
                g = n0 + row; valid = g < Nd;
                dstoff = ABYTES + hl * BSEG + sw_off(row, chunk);
            }
            CP_ASYNC(sbase + buf * BUF + dstoff,
                     base + (size_t)g * Kp + k0 + chunk * 8, valid ? 16 : 0);
        }
        CP_COMMIT();
    };

    float acc[4][4][4];
    #pragma unroll
    for (int mi = 0; mi < 4; mi++)
        #pragma unroll
        for (int ni = 0; ni < 4; ni++)
            #pragma unroll
            for (int q = 0; q < 4; q++) acc[mi][ni][q] = 0.0f;

    const int nk = Kp / 32;
    stage(0, 0);
    if (nk > 1) stage(1, 32);
    if (nk > 2) stage(2, 64);
    if (nk > 2)      { CP_WAIT2(); }
    else if (nk > 1) { CP_WAIT1(); }
    else             { CP_WAIT0(); }
    __syncthreads();

    for (int kt = 0; kt < nk; kt++) {
        const int buf = kt & 3;
        if (kt + 3 < nk) stage((kt + 3) & 3, (kt + 3) * 32);

        const uint32_t bb = sbase + buf * BUF;
        #pragma unroll
        for (int s = 0; s < 2; s++) {
            const int c0 = s * 2;
            const int arow = (lane & 15), achk = c0 + (lane >> 4);
            const int brow = (lane & 7) + ((lane & 16) >> 1);
            const int bchk = c0 + ((lane >> 3) & 1);

            uint32_t ah[4][4];
            #pragma unroll
            for (int mi = 0; mi < 4; mi++)
                LDMX4(ah[mi], bb + sw_off(mbase + mi * 16 + arow, achk));

            uint32_t bh[4][2], bl[4][2];
            #pragma unroll
            for (int h = 0; h < 2; h++) {
                uint32_t r4[4];
                int rw = nbase + h * 16 + brow;
                LDMX4(r4, bb + ABYTES + sw_off(rw, bchk));
                bh[h*2][0] = r4[0]; bh[h*2][1] = r4[1];
                bh[h*2+1][0] = r4[2]; bh[h*2+1][1] = r4[3];
                LDMX4(r4, bb + ABYTES + BSEG + sw_off(rw, bchk));
                bl[h*2][0] = r4[0]; bl[h*2][1] = r4[1];
                bl[h*2+1][0] = r4[2]; bl[h*2+1][1] = r4[3];
            }
            #pragma unroll
            for (int mi = 0; mi < 4; mi++)
                #pragma unroll
                for (int nj = 0; nj < 4; nj++)
                    mma16816(acc[mi][nj], ah[mi], bh[nj]);
            #pragma unroll
            for (int mi = 0; mi < 4; mi++)
                #pragma unroll
                for (int nj = 0; nj < 4; nj++)
                    mma16816(acc[mi][nj], ah[mi], bl[nj]);
        }

        if (kt + 3 < nk)      { CP_WAIT2(); }
        else if (kt + 2 < nk) { CP_WAIT1(); }
        else if (kt + 1 < nk) { CP_WAIT0(); }
        if (kt + 1 < nk) __syncthreads();
    }

    float* cb = Cd + (size_t)bz * sC;
    #pragma unroll
    for (int mi = 0; mi < 4; mi++) {
        #pragma unroll
        for (int ni = 0; ni < 4; ni++) {
            int row = m0 + mbase + mi * 16 + (lane >> 2);
            int col = n0 + nbase + ni * 8 + (lane & 3) * 2;
            float v0 = acc[mi][ni][0] * alpha, v1 = acc[mi][ni][1] * alpha;
            float v2 = acc[mi][ni][2] * alpha, v3 = acc[mi][ni][3] * alpha;
            if (col < Nd) {
                if (row < M)
                    *(float2*)(cb + (size_t)row * Nd + col) = make_float2(v0, v1);
                if (row + 8 < M)
                    *(float2*)(cb + (size_t)(row + 8) * Nd + col) = make_float2(v2, v3);
            }
            if (SYM && bx > by && col < M && row < Nd) {
                cb[(size_t)col * Nd + row] = v0;
                cb[(size_t)(col + 1) * Nd + row] = v1;
                if (row + 8 < Nd) {
                    cb[(size_t)col * Nd + row + 8] = v2;
                    cb[(size_t)(col + 1) * Nd + row + 8] = v3;
                }
            }
        }
    }
}

// ---------------------------------------------------------------------------
// 192-thread HMMA GEMM, NTILE=96 (fp16 2-pass split): C = alpha * A·Bᵀ
// For Y/Y2 (N=288 = 3x96, no tails). 6 warps 2(m)x3(n), warp tile 64x32.
// ---------------------------------------------------------------------------
__global__ __launch_bounds__(192, 2) void k_mma192(
    const h16* __restrict__ Ah,
    const h16* __restrict__ Bh, const h16* __restrict__ Bl,
    float* __restrict__ Cd, int M, int Nd, int Kp,
    size_t sA, size_t sB, size_t sC, float alpha)
{
    constexpr int ABYTES = 8192;
    constexpr int BSEG   = 6144;                // 96 rows x 64B
    constexpr int BUF    = ABYTES + 2 * BSEG;   // 20480
    constexpr int TOTCH  = 512 + 768;           // A chunks + B chunks (hi+lo)

    extern __shared__ __align__(16) char dsm[];
    const int bx = blockIdx.x, by = blockIdx.y, bz = blockIdx.z;
    const int m0 = by * 128, n0 = bx * 96;
    const int t = threadIdx.x;
    const int lane = t & 31, wid = t >> 5;
    const int wm = (wid >= 3) ? 1 : 0;          // 2 m-groups x 3 n-groups
    const int wn = wid - wm * 3;
    const int mbase = wm * 64, nbase = wn * 32;

    const h16* Abh = Ah + (size_t)bz * sA;
    const h16* Bbh = Bh + (size_t)bz * sB;
    const h16* Bbl = Bl + (size_t)bz * sB;

    const uint32_t sbase = smem_u32(dsm);

    auto stage = [&](int buf, int k0) {
        #pragma unroll
        for (int i = 0; i < 7; i++) {
            int idx = t + i * 192;
            if (idx >= TOTCH) break;
            const h16* base; int g, row, chunk; uint32_t dstoff; bool valid;
            if (idx < 512) {
                row = idx >> 2; chunk = idx & 3;
                base = Abh;
                g = m0 + row; valid = g < M;
                dstoff = sw_off(row, chunk);
            } else {
                int idxb = idx - 512;           // 0..767
                int hl = idxb >= 384;
                int r = idxb - hl * 384;
                row = r >> 2; chunk = r & 3;
                base = hl ? Bbl : Bbh;
                g = n0 + row; valid = g < Nd;
                dstoff = ABYTES + hl * BSEG + sw_off(row, chunk);
            }
            CP_ASYNC(sbase + buf * BUF + dstoff,
                     base + (size_t)g * Kp + k0 + chunk * 8, valid ? 16 : 0);
        }
        CP_COMMIT();
    };

    float acc[4][4][4];
    #pragma unroll
    for (int mi = 0; mi < 4; mi++)
        #pragma unroll
        for (int ni = 0; ni < 4; ni++)
            #pragma unroll
            for (int q = 0; q < 4; q++) acc[mi][ni][q] = 0.0f;

    const int nk = Kp / 32;
    stage(0, 0);
    if (nk > 1) stage(1, 32);
    if (nk > 2) stage(2, 64);
    if (nk > 2)      { CP_WAIT2(); }
    else if (nk > 1) { CP_WAIT1(); }
    else             { CP_WAIT0(); }
    __syncthreads();

    for (int kt = 0; kt < nk; kt++) {
        const int buf = kt & 3;
        if (kt + 3 < nk) stage((kt + 3) & 3, (kt + 3) * 32);

        const uint32_t bb = sbase + buf * BUF;
        #pragma unroll
        for (int s = 0; s < 2; s++) {
            const int c0 = s * 2;
            const int arow = (lane & 15), achk = c0 + (lane >> 4);
            const int brow = (lane & 7) + ((lane & 16) >> 1);
            const int bchk = c0 + ((lane >> 3) & 1);

            uint32_t ah[4][4];
            #pragma unroll
            for (int mi = 0; mi < 4; mi++)
                LDMX4(ah[mi], bb + sw_off(mbase + mi * 16 + arow, achk));

            uint32_t bh[4][2], bl[4][2];
            #pragma unroll
            for (int h = 0; h < 2; h++) {
                uint32_t r4[4];
                int rw = nbase + h * 16 + brow;
                LDMX4(r4, bb + ABYTES + sw_off(rw, bchk));
                bh[h*2][0] = r4[0]; bh[h*2][1] = r4[1];
                bh[h*2+1][0] = r4[2]; bh[h*2+1][1] = r4[3];
                LDMX4(r4, bb + ABYTES + BSEG + sw_off(rw, bchk));
                bl[h*2][0] = r4[0]; bl[h*2][1] = r4[1];
                bl[h*2+1][0] = r4[2]; bl[h*2+1][1] = r4[3];
            }
            #pragma unroll
            for (int mi = 0; mi < 4; mi++)
                #pragma unroll
                for (int nj = 0; nj < 4; nj++)
                    mma16816(acc[mi][nj], ah[mi], bh[nj]);
            #pragma unroll
            for (int mi = 0; mi < 4; mi++)
                #pragma unroll
                for (int nj = 0; nj < 4; nj++)
                    mma16816(acc[mi][nj], ah[mi], bl[nj]);
        }

        if (kt + 3 < nk)      { CP_WAIT2(); }
        else if (kt + 2 < nk) { CP_WAIT1(); }
        else if (kt + 1 < nk) { CP_WAIT0(); }
        if (kt + 1 < nk) __syncthreads();
    }

    float* cb = Cd + (size_t)bz * sC;
    #pragma unroll
    for (int mi = 0; mi < 4; mi++) {
        #pragma unroll
        for (int ni = 0; ni < 4; ni++) {
            int row = m0 + mbase + mi * 16 + (lane >> 2);
            int col = n0 + nbase + ni * 8 + (lane & 3) * 2;
            if (col < Nd) {
                if (row < M)
                    *(float2*)(cb + (size_t)row * Nd + col) =
                        make_float2(acc[mi][ni][0] * alpha, acc[mi][ni][1] * alpha);
                if (row + 8 < M)
                    *(float2*)(cb + (size_t)(row + 8) * Nd + col) =
                        make_float2(acc[mi][ni][2] * alpha, acc[mi][ni][3] * alpha);
            }
        }
    }
}

// ---------------------------------------------------------------------------
// fp32 (rows x cols) -> direct hi[/lo] (stride ds) + transposed hi/lo (stride ts)
// ---------------------------------------------------------------------------
__global__ __launch_bounds__(256) void k_split_both(
    const float* __restrict__ src,
    h16* __restrict__ dh, h16* __restrict__ dl, int ds,
    h16* __restrict__ th, h16* __restrict__ tl, int ts,
    int rows, int cols)
{
    __shared__ float tile[32][33];
    const int b = blockIdx.z;
    const int c0 = blockIdx.x * 32, r0 = blockIdx.y * 32;
    const float* s = src + (size_t)b * rows * cols;
    const size_t dbs = (size_t)b * rows * ds;
    const size_t tbs = (size_t)b * cols * ts;

    #pragma unroll
    for (int i = 0; i < 4; i++) {
        int r = r0 + threadIdx.y + i * 8, c = c0 + threadIdx.x;
        float v = s[(size_t)r * cols + c];
        tile[threadIdx.y + i * 8][threadIdx.x] = v;
        h16 h, l; split_h16(v, h, l);
        size_t o = dbs + (size_t)r * ds + c;
        dh[o] = h;
        if (dl) dl[o] = l;
    }
    __syncthreads();
    #pragma unroll
    for (int i = 0; i < 4; i++) {
        int tr = c0 + threadIdx.y + i * 8, tc = r0 + threadIdx.x;
        float v = tile[threadIdx.x][threadIdx.y + i * 8];
        h16 h, l; split_h16(v, h, l);
        size_t o = tbs + (size_t)tr * ts + tc;
        th[o] = h; tl[o] = l;
    }
}

// ---------------------------------------------------------------------------
// Fused: z = scale[c]*Y + shift[c] + X (fp32 z NOT stored), writes fp16 hi/lo
// split of z (direct, stride Kp1) and its transpose (stride Cc).
// ---------------------------------------------------------------------------
__global__ __launch_bounds__(256) void k_bn_res_split(
    const float* __restrict__ Y, const float* __restrict__ X,
    h16* __restrict__ dh, h16* __restrict__ dl,
    h16* __restrict__ th, h16* __restrict__ tl)
{
    __shared__ float tile[32][33];
    const int b = blockIdx.z;
    const int c0 = blockIdx.x * 32, r0 = blockIdx.y * 32;
    const size_t fb = (size_t)b * Cc * Nn;
    const size_t dbs = (size_t)b * Cc * Kp1;
    const size_t tbs = (size_t)b * Nn * Cc;

    #pragma unroll
    for (int i = 0; i < 4; i++) {
        int r = r0 + threadIdx.y + i * 8, c = c0 + threadIdx.x;
        size_t off = fb + (size_t)r * Nn + c;
        float z = fmaf(g_scale[r], Y[off], g_shift[r]) + X[off];
        tile[threadIdx.y + i * 8][threadIdx.x] = z;
        h16 h, l; split_h16(z, h, l);
        size_t o = dbs + (size_t)r * Kp1 + c;
        dh[o] = h; dl[o] = l;
    }
    __syncthreads();
    #pragma unroll
    for (int i = 0; i < 4; i++) {
        int tr = c0 + threadIdx.y + i * 8, tc = r0 + threadIdx.x;
        float v = tile[threadIdx.x][threadIdx.y + i * 8];
        h16 h, l; split_h16(v, h, l);
        size_t o = tbs + (size_t)tr * Cc + tc;
        th[o] = h; tl[o] = l;
    }
}

// ---------------------------------------------------------------------------
__global__ __launch_bounds__(288) void k_softmax_prior(const float* __restrict__ dis)
{
    int p = blockIdx.x, b = blockIdx.y, t = threadIdx.x;
    const float* f = g_F + ((size_t)b * Nn + p) * Nn;
    float v = f[t];
    float m1 = block_reduce(v, 0);
    float e1 = __expf(v - m1);
    float s1 = block_reduce(e1, 1);
    float w  = (e1 / s1) * dis[(size_t)p * Nn + t];
    float m2 = block_reduce(w, 0);
    float e2 = __expf(w - m2);
    float s2 = block_reduce(e2, 1);
    h16 h, l; split_h16(e2 / s2, h, l);
    size_t o = ((size_t)b * Nn + p) * Kp1 + t;
    g_Fh[o] = h; g_Fl[o] = l;
}

// rows of g_F2 (len 1024): 256 threads x 4 contiguous, float4/half2 vectorized
__global__ __launch_bounds__(256) void k_softmax_chan()
{
    size_t row = blockIdx.x;
    const float* f = g_F2 + row * (size_t)Cc;
    int t = threadIdx.x;
    float4 v4 = ((const float4*)f)[t];
    float v[4] = {v4.x, v4.y, v4.z, v4.w};
    float m = block_reduce(fmaxf(fmaxf(v[0], v[1]), fmaxf(v[2], v[3])), 0);
    float e[4], ls = 0.0f;
    #pragma unroll
    for (int i = 0; i < 4; i++) { e[i] = __expf(v[i] - m); ls += e[i]; }
    float s = block_reduce(ls, 1);
    float inv = 1.0f / s;
    __half2 h0 = __floats2half2_rn(e[0] * inv, e[1] * inv);
    __half2 h1 = __floats2half2_rn(e[2] * inv, e[3] * inv);
    uint2 pk = make_uint2(*(uint32_t*)&h0, *(uint32_t*)&h1);
    ((uint2*)(g_F2h + row * (size_t)Cc))[t] = pk;
}

__global__ __launch_bounds__(256) void k_bnstats(
    const float* __restrict__ Y,
    const float* __restrict__ gamma, const float* __restrict__ beta)
{
    int c = blockIdx.x, t = threadIdx.x;
    const int n4 = Nn / 4, tot4 = Bb * n4;
    float s = 0.0f, sq = 0.0f;
    #pragma unroll 4
    for (int idx = t; idx < tot4; idx += 256) {
        int b = idx / n4, i = idx - b * n4;
        float4 v = *(const float4*)(Y + ((size_t)b * Cc + c) * Nn + i * 4);
        s  += (v.x + v.y) + (v.z + v.w);
        sq += (v.x * v.x + v.y * v.y) + (v.z * v.z + v.w * v.w);
    }
    s = block_reduce(s, 1);
    sq = block_reduce(sq, 1);
    if (t == 0) {
        const float invN = 1.0f / (float)(Bb * Nn);
        float mean = s * invN;
        float var  = sq * invN - mean * mean;
        float sc = gamma[c] * rsqrtf(var + EPSv);
        g_scale[c] = sc;
        g_shift[c] = beta[c] - mean * sc;
    }
}

// out = scale[c]*Y2 + shift[c] + (Zh + Zl)   (residual reconstructed from split)
__global__ __launch_bounds__(256) void k_bn_apply_add_h(
    const float* __restrict__ Y, float* __restrict__ out)
{
    size_t i4 = (size_t)blockIdx.x * blockDim.x + threadIdx.x;
    const size_t total4 = (size_t)Bb * Cc * Nn / 4;
    if (i4 >= total4) return;
    size_t e = i4 * 4;
    int b = (int)(e / ((size_t)Cc * Nn));
    int rem = (int)(e - (size_t)b * Cc * Nn);
    int c = rem / Nn;
    int n = rem - c * Nn;
    float4 y = ((const float4*)Y)[i4];
    size_t zo = (size_t)b * Cc * Kp1 + (size_t)c * Kp1 + n;
    uint2 zhp = *(const uint2*)(g_Zh + zo);
    uint2 zlp = *(const uint2*)(g_Zl + zo);
    __half2 zh0 = *(__half2*)&zhp.x, zh1 = *(__half2*)&zhp.y;
    __half2 zl0 = *(__half2*)&zlp.x, zl1 = *(__half2*)&zlp.y;
    float r0 = __low2float(zh0) + __low2float(zl0);
    float r1 = __high2float(zh0) + __high2float(zl0);
    float r2 = __low2float(zh1) + __low2float(zl1);
    float r3 = __high2float(zh1) + __high2float(zl1);
    float sc = g_scale[c], sh = g_shift[c];
    float4 o;
    o.x = fmaf(sc, y.x, sh) + r0;
    o.y = fmaf(sc, y.y, sh) + r1;
    o.z = fmaf(sc, y.z, sh) + r2;
    o.w = fmaf(sc, y.w, sh) + r3;
    ((float4*)out)[i4] = o;
}

// ---------------------------------------------------------------------------
extern "C" void kernel_launch(void* const* d_in, const int* in_sizes, int n_in,
                              void* d_out, int out_size)
{
    const float* x      = (const float*)d_in[0];
    const float* dis    = (const float*)d_in[1];
    const float* gamma1 = (const float*)d_in[2];
    const float* beta1  = (const float*)d_in[3];
    const float* gamma2 = (const float*)d_in[4];
    const float* beta2  = (const float*)d_in[5];
    float* out = (float*)d_out;

    float *pF, *pY, *pY2, *pF2;
    cudaGetSymbolAddress((void**)&pF,  g_F);
    cudaGetSymbolAddress((void**)&pY,  g_Y);
    cudaGetSymbolAddress((void**)&pY2, g_Y2);
    cudaGetSymbolAddress((void**)&pF2, g_F2);
    h16 *pXh,*pXTh,*pXTl,*pZh,*pZl,*pZTh,*pZTl,*pFh,*pFl,*pF2h;
    cudaGetSymbolAddress((void**)&pXh,  g_Xh);
    cudaGetSymbolAddress((void**)&pXTh, g_XTh); cudaGetSymbolAddress((void**)&pXTl, g_XTl);
    cudaGetSymbolAddress((void**)&pZh,  g_Zh);  cudaGetSymbolAddress((void**)&pZl,  g_Zl);
    cudaGetSymbolAddress((void**)&pZTh, g_ZTh); cudaGetSymbolAddress((void**)&pZTl, g_ZTl);
    cudaGetSymbolAddress((void**)&pFh,  g_Fh);  cudaGetSymbolAddress((void**)&pFl,  g_Fl);
    cudaGetSymbolAddress((void**)&pF2h, g_F2h);

    const int SM2 = 4 * 24576;   // 98304 (k_mma256)
    const int SM9 = 4 * 20480;   // 81920 (k_mma192)
    static bool attr_set = false;
    if (!attr_set) {
        cudaFuncSetAttribute((const void*)k_mma256<true >,
                             cudaFuncAttributeMaxDynamicSharedMemorySize, SM2);
        cudaFuncSetAttribute((const void*)k_mma192,
                             cudaFuncAttributeMaxDynamicSharedMemorySize, SM9);
        attr_set = true;
    }

    const size_t sX  = (size_t)Cc * Kp1;
    const size_t sXT = (size_t)Nn * Cc;
    const size_t sFb = (size_t)Nn * Kp1;
    const size_t sF  = (size_t)Nn * Nn;
    const size_t sYb = (size_t)Cc * Nn;
    const size_t sF2 = (size_t)Cc * Cc;

    // 0) split X -> Xh (hi only, Kp=320) + XT hi/lo (K=1024)
    k_split_both<<<dim3(Nn / 32, Cc / 32, Bb), dim3(32, 8)>>>(
        x, pXh, nullptr, Kp1, pXTh, pXTl, Cc, Cc, Nn);

    // 1) F = XT·XTᵀ / 32  (sym)  M=N=288, K=1024
    k_mma256<true><<<dim3(3, 3, Bb), 256, SM2>>>(
        pXTh, pXTh, pXTl, pF, Nn, Nn, Cc, sXT, sXT, sF, 0.03125f);

    // 2) softmax+prior -> F hi/lo (Kp=320)
    k_softmax_prior<<<dim3(Nn, Bb), 288>>>(dis);

    // 3) Y = X·Fᵀ  M=1024, N=288 = 3x96 tiles, Kp=320
    k_mma192<<<dim3(3, 8, Bb), 192, SM9>>>(
        pXh, pFh, pFl, pY, Cc, Nn, Kp1, sX, sFb, sYb, 1.0f);

    // 4) BN1 stats + fused (residual + Z split direct/transposed; no fp32 Z)
    k_bnstats<<<Cc, 256>>>(pY, gamma1, beta1);
    k_bn_res_split<<<dim3(Nn / 32, Cc / 32, Bb), dim3(32, 8)>>>(
        pY, x, pZh, pZl, pZTh, pZTl);

    // 6) F2 = Z·Zᵀ  (sym)  M=N=1024, Kp=320
    k_mma256<true><<<dim3(8, 8, Bb), 256, SM2>>>(
        pZh, pZh, pZl, pF2, Cc, Cc, Kp1, sX, sX, sF2, 1.0f);

    // 7) softmax rows of F2 -> F2 hi
    k_softmax_chan<<<Bb * Cc, 256>>>();

    // 8) Y2 = F2·ZTᵀ  M=1024, N=288 = 3x96 tiles, K=1024
    k_mma192<<<dim3(3, 8, Bb), 192, SM9>>>(
        pF2h, pZTh, pZTl, pY2, Cc, Nn, Cc, sF2, sXT, sYb, 1.0f);

    // 9) BN2 stats + final: out = bn2(Y2) + (Zh+Zl)
    k_bnstats<<<Cc, 256>>>(pY2, gamma2, beta2);
    k_bn_apply_add_h<<<(int)(((size_t)Bb * Cc * Nn / 4 + 255) / 256), 256>>>(pY2, out);
}

// round 16
// speedup vs baseline: 4.3495x; 1.0017x over previous
#include <cuda_runtime.h>
#include <cuda_fp16.h>
#include <math.h>
#include <stdint.h>

#define Bb   128
#define Cc   1024
#define Nn   288
#define Kp1  320            // padded K for K=288 (multiple of 32)
#define EPSv 1e-5f

typedef __half h16;

// fp32 scratch
__device__ float g_F [(size_t)Bb * Nn * Nn];
__device__ float g_Y [(size_t)Bb * Cc * Nn];
__device__ float g_Y2[(size_t)Bb * Cc * Nn];
__device__ float g_F2[(size_t)Bb * Cc * Cc];
__device__ float g_scale[Cc];
__device__ float g_shift[Cc];
// fp16 hi/lo K-major operands (pads stay zero: zero-init, never written)
__device__ h16 g_Xh [(size_t)Bb * Cc * Kp1];
__device__ h16 g_XTh[(size_t)Bb * Nn * Cc];
__device__ h16 g_XTl[(size_t)Bb * Nn * Cc];
__device__ h16 g_Zh [(size_t)Bb * Cc * Kp1];
__device__ h16 g_Zl [(size_t)Bb * Cc * Kp1];
__device__ h16 g_ZTh[(size_t)Bb * Nn * Cc];
__device__ h16 g_ZTl[(size_t)Bb * Nn * Cc];
__device__ h16 g_Fh [(size_t)Bb * Nn * Kp1];
__device__ h16 g_Fl [(size_t)Bb * Nn * Kp1];
__device__ h16 g_F2h[(size_t)Bb * Cc * Cc];

// ---------------- helpers ----------------
__device__ __forceinline__ uint32_t smem_u32(const void* p) {
    uint32_t a;
    asm("{ .reg .u64 t; cvta.to.shared.u64 t, %1; cvt.u32.u64 %0, t; }" : "=r"(a) : "l"(p));
    return a;
}
__device__ __forceinline__ void split_h16(float x, h16& h, h16& l) {
    h = __float2half(x);
    l = __float2half(x - __half2float(h));
}

#define LDMX4(r, a) \
    asm volatile("ldmatrix.sync.aligned.m8n8.x4.shared.b16 {%0,%1,%2,%3}, [%4];" \
        : "=r"((r)[0]), "=r"((r)[1]), "=r"((r)[2]), "=r"((r)[3]) : "r"(a))

__device__ __forceinline__ void mma16816(float* c, const uint32_t* a, const uint32_t* b) {
    asm volatile("mma.sync.aligned.m16n8k16.row.col.f32.f16.f16.f32 "
        "{%0,%1,%2,%3}, {%4,%5,%6,%7}, {%8,%9}, {%0,%1,%2,%3};"
        : "+f"(c[0]), "+f"(c[1]), "+f"(c[2]), "+f"(c[3])
        : "r"(a[0]), "r"(a[1]), "r"(a[2]), "r"(a[3]), "r"(b[0]), "r"(b[1]));
}

#define CP_ASYNC(dst, src, sz) \
    asm volatile("cp.async.cg.shared.global [%0], [%1], 16, %2;" \
        :: "r"(dst), "l"(src), "r"(sz) : "memory")
#define CP_COMMIT() asm volatile("cp.async.commit_group;" ::: "memory")
#define CP_WAIT2()  asm volatile("cp.async.wait_group 2;" ::: "memory")
#define CP_WAIT1()  asm volatile("cp.async.wait_group 1;" ::: "memory")
#define CP_WAIT0()  asm volatile("cp.async.wait_group 0;" ::: "memory")

// conflict-free swizzle (R11): residues {c^j, 4+c^j} distinct over 8-row phase
__device__ __forceinline__ uint32_t sw_off(int row, int chunk) {
    return (uint32_t)((row * 4 + (chunk ^ ((row >> 1) & 3))) * 16);
}

// ---------------- block reduce ----------------
__device__ __forceinline__ float block_reduce(float v, int op) {
    __shared__ float red[32];
    #pragma unroll
    for (int o = 16; o > 0; o >>= 1) {
        float u = __shfl_xor_sync(0xffffffffu, v, o);
        v = op ? (v + u) : fmaxf(v, u);
    }
    int lane = threadIdx.x & 31, wid = threadIdx.x >> 5;
    int nw = (blockDim.x + 31) >> 5;
    if (lane == 0) red[wid] = v;
    __syncthreads();
    if (wid == 0) {
        float r = (lane < nw) ? red[lane] : (op ? 0.0f : -3.4e38f);
        #pragma unroll
        for (int o = 16; o > 0; o >>= 1) {
            float u = __shfl_xor_sync(0xffffffffu, r, o);
            r = op ? (r + u) : fmaxf(r, u);
        }
        if (lane == 0) red[0] = r;
    }
    __syncthreads();
    float r = red[0];
    __syncthreads();
    return r;
}

// ---------------------------------------------------------------------------
// 256-thread HMMA GEMM, NTILE=128 (fp16 2-pass split): C = alpha * A·Bᵀ
// For symmetric grams (F, F2): skip bx<by blocks; bx>by blocks mirror-write
// through an smem transpose (coalesced, vs the old stride-Nd scatter).
// 8 warps 2x4, warp tile 64x32; 4-stage cp.async pipeline.
// ---------------------------------------------------------------------------
template<bool SYM>
__global__ __launch_bounds__(256, 2) void k_mma256(
    const h16* __restrict__ Ah,
    const h16* __restrict__ Bh, const h16* __restrict__ Bl,
    float* __restrict__ Cd, int M, int Nd, int Kp,
    size_t sA, size_t sB, size_t sC, float alpha)
{
    constexpr int ABYTES = 8192;
    constexpr int BSEG   = 8192;
    constexpr int BUF    = ABYTES + 2 * BSEG;   // 24576

    extern __shared__ __align__(16) char dsm[];
    const int bx = blockIdx.x, by = blockIdx.y, bz = blockIdx.z;
    if (SYM && bx < by) return;
    const int m0 = by * 128, n0 = bx * 128;
    const int t = threadIdx.x;
    const int lane = t & 31, wid = t >> 5;
    const int mbase = (wid >> 2) * 64, nbase = (wid & 3) * 32;

    const h16* Abh = Ah + (size_t)bz * sA;
    const h16* Bbh = Bh + (size_t)bz * sB;
    const h16* Bbl = Bl + (size_t)bz * sB;

    const uint32_t sbase = smem_u32(dsm);

    auto stage = [&](int buf, int k0) {
        #pragma unroll
        for (int i = 0; i < 6; i++) {
            int idx = t + i * 256;              // 0..1535
            const h16* base; int g, row, chunk; uint32_t dstoff; bool valid;
            if (idx < 512) {                    // A: 128 rows x 4 chunks
                row = idx >> 2; chunk = idx & 3;
                base = Abh;
                g = m0 + row; valid = g < M;
                dstoff = sw_off(row, chunk);
            } else {                            // B hi then lo
                int idxb = idx - 512;
                int hl = idxb >= 512;
                int r = idxb - hl * 512;
                row = r >> 2; chunk = r & 3;
                base = hl ? Bbl : Bbh;
                g = n0 + row; valid = g < Nd;
                dstoff = ABYTES + hl * BSEG + sw_off(row, chunk);
            }
            CP_ASYNC(sbase + buf * BUF + dstoff,
                     base + (size_t)g * Kp + k0 + chunk * 8, valid ? 16 : 0);
        }
        CP_COMMIT();
    };

    float acc[4][4][4];
    #pragma unroll
    for (int mi = 0; mi < 4; mi++)
        #pragma unroll
        for (int ni = 0; ni < 4; ni++)
            #pragma unroll
            for (int q = 0; q < 4; q++) acc[mi][ni][q] = 0.0f;

    const int nk = Kp / 32;
    stage(0, 0);
    if (nk > 1) stage(1, 32);
    if (nk > 2) stage(2, 64);
    if (nk > 2)      { CP_WAIT2(); }
    else if (nk > 1) { CP_WAIT1(); }
    else             { CP_WAIT0(); }
    __syncthreads();

    for (int kt = 0; kt < nk; kt++) {
        const int buf = kt & 3;
        if (kt + 3 < nk) stage((kt + 3) & 3, (kt + 3) * 32);

        const uint32_t bb = sbase + buf * BUF;
        #pragma unroll
        for (int s = 0; s < 2; s++) {
            const int c0 = s * 2;
            const int arow = (lane & 15), achk = c0 + (lane >> 4);
            const int brow = (lane & 7) + ((lane & 16) >> 1);
            const int bchk = c0 + ((lane >> 3) & 1);

            uint32_t ah[4][4];
            #pragma unroll
            for (int mi = 0; mi < 4; mi++)
                LDMX4(ah[mi], bb + sw_off(mbase + mi * 16 + arow, achk));

            uint32_t bh[4][2], bl[4][2];
            #pragma unroll
            for (int h = 0; h < 2; h++) {
                uint32_t r4[4];
                int rw = nbase + h * 16 + brow;
                LDMX4(r4, bb + ABYTES + sw_off(rw, bchk));
                bh[h*2][0] = r4[0]; bh[h*2][1] = r4[1];
                bh[h*2+1][0] = r4[2]; bh[h*2+1][1] = r4[3];
                LDMX4(r4, bb + ABYTES + BSEG + sw_off(rw, bchk));
                bl[h*2][0] = r4[0]; bl[h*2][1] = r4[1];
                bl[h*2+1][0] = r4[2]; bl[h*2+1][1] = r4[3];
            }
            #pragma unroll
            for (int mi = 0; mi < 4; mi++)
                #pragma unroll
                for (int nj = 0; nj < 4; nj++)
                    mma16816(acc[mi][nj], ah[mi], bh[nj]);
            #pragma unroll
            for (int mi = 0; mi < 4; mi++)
                #pragma unroll
                for (int nj = 0; nj < 4; nj++)
                    mma16816(acc[mi][nj], ah[mi], bl[nj]);
        }

        if (kt + 3 < nk)      { CP_WAIT2(); }
        else if (kt + 2 < nk) { CP_WAIT1(); }
        else if (kt + 1 < nk) { CP_WAIT0(); }
        if (kt + 1 < nk) __syncthreads();
    }

    float* cb = Cd + (size_t)bz * sC;
    // direct block write (coalesced)
    #pragma unroll
    for (int mi = 0; mi < 4; mi++) {
        #pragma unroll
        for (int ni = 0; ni < 4; ni++) {
            int row = m0 + mbase + mi * 16 + (lane >> 2);
            int col = n0 + nbase + ni * 8 + (lane & 3) * 2;
            if (col < Nd) {
                if (row < M)
                    *(float2*)(cb + (size_t)row * Nd + col) =
                        make_float2(acc[mi][ni][0] * alpha, acc[mi][ni][1] * alpha);
                if (row + 8 < M)
                    *(float2*)(cb + (size_t)(row + 8) * Nd + col) =
                        make_float2(acc[mi][ni][2] * alpha, acc[mi][ni][3] * alpha);
            }
        }
    }
    // mirror block: transpose via smem, then coalesced row writes
    if (SYM && bx > by) {
        __syncthreads();                       // staging smem now reusable
        float* tsm = (float*)dsm;              // 128 x 133 fp32 (pad 133: bank-free T-read)
        #pragma unroll
        for (int mi = 0; mi < 4; mi++) {
            #pragma unroll
            for (int ni = 0; ni < 4; ni++) {
                int lr = mbase + mi * 16 + (lane >> 2);
                int lc = nbase + ni * 8 + (lane & 3) * 2;
                tsm[lr * 133 + lc]           = acc[mi][ni][0] * alpha;
                tsm[lr * 133 + lc + 1]       = acc[mi][ni][1] * alpha;
                tsm[(lr + 8) * 133 + lc]     = acc[mi][ni][2] * alpha;
                tsm[(lr + 8) * 133 + lc + 1] = acc[mi][ni][3] * alpha;
            }
        }
        __syncthreads();
        #pragma unroll
        for (int r8 = 0; r8 < 16; r8++) {
            int rr = wid * 16 + r8;            // mirrored row = original col
            if (n0 + rr >= Nd) continue;
            float* dst = cb + (size_t)(n0 + rr) * Nd + m0;
            #pragma unroll
            for (int cc4 = 0; cc4 < 4; cc4++) {
                int cc = cc4 * 32 + lane;      // mirrored col = original row
                if (m0 + cc < M)
                    dst[cc] = tsm[cc * 133 + rr];
            }
        }
    }
}

// ---------------------------------------------------------------------------
// 192-thread HMMA GEMM, NTILE=96 (fp16 2-pass split): C = alpha * A·Bᵀ
// For Y/Y2 (N=288 = 3x96, no tails). 6 warps 2(m)x3(n), warp tile 64x32.
// ---------------------------------------------------------------------------
__global__ __launch_bounds__(192, 2) void k_mma192(
    const h16* __restrict__ Ah,
    const h16* __restrict__ Bh, const h16* __restrict__ Bl,
    float* __restrict__ Cd, int M, int Nd, int Kp,
    size_t sA, size_t sB, size_t sC, float alpha)
{
    constexpr int ABYTES = 8192;
    constexpr int BSEG   = 6144;                // 96 rows x 64B
    constexpr int BUF    = ABYTES + 2 * BSEG;   // 20480
    constexpr int TOTCH  = 512 + 768;

    extern __shared__ __align__(16) char dsm[];
    const int bx = blockIdx.x, by = blockIdx.y, bz = blockIdx.z;
    const int m0 = by * 128, n0 = bx * 96;
    const int t = threadIdx.x;
    const int lane = t & 31, wid = t >> 5;
    const int wm = (wid >= 3) ? 1 : 0;
    const int wn = wid - wm * 3;
    const int mbase = wm * 64, nbase = wn * 32;

    const h16* Abh = Ah + (size_t)bz * sA;
    const h16* Bbh = Bh + (size_t)bz * sB;
    const h16* Bbl = Bl + (size_t)bz * sB;

    const uint32_t sbase = smem_u32(dsm);

    auto stage = [&](int buf, int k0) {
        #pragma unroll
        for (int i = 0; i < 7; i++) {
            int idx = t + i * 192;
            if (idx >= TOTCH) break;
            const h16* base; int g, row, chunk; uint32_t dstoff; bool valid;
            if (idx < 512) {
                row = idx >> 2; chunk = idx & 3;
                base = Abh;
                g = m0 + row; valid = g < M;
                dstoff = sw_off(row, chunk);
            } else {
                int idxb = idx - 512;
                int hl = idxb >= 384;
                int r = idxb - hl * 384;
                row = r >> 2; chunk = r & 3;
                base = hl ? Bbl : Bbh;
                g = n0 + row; valid = g < Nd;
                dstoff = ABYTES + hl * BSEG + sw_off(row, chunk);
            }
            CP_ASYNC(sbase + buf * BUF + dstoff,
                     base + (size_t)g * Kp + k0 + chunk * 8, valid ? 16 : 0);
        }
        CP_COMMIT();
    };

    float acc[4][4][4];
    #pragma unroll
    for (int mi = 0; mi < 4; mi++)
        #pragma unroll
        for (int ni = 0; ni < 4; ni++)
            #pragma unroll
            for (int q = 0; q < 4; q++) acc[mi][ni][q] = 0.0f;

    const int nk = Kp / 32;
    stage(0, 0);
    if (nk > 1) stage(1, 32);
    if (nk > 2) stage(2, 64);
    if (nk > 2)      { CP_WAIT2(); }
    else if (nk > 1) { CP_WAIT1(); }
    else             { CP_WAIT0(); }
    __syncthreads();

    for (int kt = 0; kt < nk; kt++) {
        const int buf = kt & 3;
        if (kt + 3 < nk) stage((kt + 3) & 3, (kt + 3) * 32);

        const uint32_t bb = sbase + buf * BUF;
        #pragma unroll
        for (int s = 0; s < 2; s++) {
            const int c0 = s * 2;
            const int arow = (lane & 15), achk = c0 + (lane >> 4);
            const int brow = (lane & 7) + ((lane & 16) >> 1);
            const int bchk = c0 + ((lane >> 3) & 1);

            uint32_t ah[4][4];
            #pragma unroll
            for (int mi = 0; mi < 4; mi++)
                LDMX4(ah[mi], bb + sw_off(mbase + mi * 16 + arow, achk));

            uint32_t bh[4][2], bl[4][2];
            #pragma unroll
            for (int h = 0; h < 2; h++) {
                uint32_t r4[4];
                int rw = nbase + h * 16 + brow;
                LDMX4(r4, bb + ABYTES + sw_off(rw, bchk));
                bh[h*2][0] = r4[0]; bh[h*2][1] = r4[1];
                bh[h*2+1][0] = r4[2]; bh[h*2+1][1] = r4[3];
                LDMX4(r4, bb + ABYTES + BSEG + sw_off(rw, bchk));
                bl[h*2][0] = r4[0]; bl[h*2][1] = r4[1];
                bl[h*2+1][0] = r4[2]; bl[h*2+1][1] = r4[3];
            }
            #pragma unroll
            for (int mi = 0; mi < 4; mi++)
                #pragma unroll
                for (int nj = 0; nj < 4; nj++)
                    mma16816(acc[mi][nj], ah[mi], bh[nj]);
            #pragma unroll
            for (int mi = 0; mi < 4; mi++)
                #pragma unroll
                for (int nj = 0; nj < 4; nj++)
                    mma16816(acc[mi][nj], ah[mi], bl[nj]);
        }

        if (kt + 3 < nk)      { CP_WAIT2(); }
        else if (kt + 2 < nk) { CP_WAIT1(); }
        else if (kt + 1 < nk) { CP_WAIT0(); }
        if (kt + 1 < nk) __syncthreads();
    }

    float* cb = Cd + (size_t)bz * sC;
    #pragma unroll
    for (int mi = 0; mi < 4; mi++) {
        #pragma unroll
        for (int ni = 0; ni < 4; ni++) {
            int row = m0 + mbase + mi * 16 + (lane >> 2);
            int col = n0 + nbase + ni * 8 + (lane & 3) * 2;
            if (col < Nd) {
                if (row < M)
                    *(float2*)(cb + (size_t)row * Nd + col) =
                        make_float2(acc[mi][ni][0] * alpha, acc[mi][ni][1] * alpha);
                if (row + 8 < M)
                    *(float2*)(cb + (size_t)(row + 8) * Nd + col) =
                        make_float2(acc[mi][ni][2] * alpha, acc[mi][ni][3] * alpha);
            }
        }
    }
}

// ---------------------------------------------------------------------------
// fp32 (rows x cols) -> direct hi[/lo] (stride ds) + transposed hi/lo (stride ts)
// ---------------------------------------------------------------------------
__global__ __launch_bounds__(256) void k_split_both(
    const float* __restrict__ src,
    h16* __restrict__ dh, h16* __restrict__ dl, int ds,
    h16* __restrict__ th, h16* __restrict__ tl, int ts,
    int rows, int cols)
{
    __shared__ float tile[32][33];
    const int b = blockIdx.z;
    const int c0 = blockIdx.x * 32, r0 = blockIdx.y * 32;
    const float* s = src + (size_t)b * rows * cols;
    const size_t dbs = (size_t)b * rows * ds;
    const size_t tbs = (size_t)b * cols * ts;

    #pragma unroll
    for (int i = 0; i < 4; i++) {
        int r = r0 + threadIdx.y + i * 8, c = c0 + threadIdx.x;
        float v = s[(size_t)r * cols + c];
        tile[threadIdx.y + i * 8][threadIdx.x] = v;
        h16 h, l; split_h16(v, h, l);
        size_t o = dbs + (size_t)r * ds + c;
        dh[o] = h;
        if (dl) dl[o] = l;
    }
    __syncthreads();
    #pragma unroll
    for (int i = 0; i < 4; i++) {
        int tr = c0 + threadIdx.y + i * 8, tc = r0 + threadIdx.x;
        float v = tile[threadIdx.x][threadIdx.y + i * 8];
        h16 h, l; split_h16(v, h, l);
        size_t o = tbs + (size_t)tr * ts + tc;
        th[o] = h; tl[o] = l;
    }
}

// ---------------------------------------------------------------------------
// Fused: z = scale[c]*Y + shift[c] + X (fp32 z NOT stored), writes fp16 hi/lo
// split of z (direct, stride Kp1) and its transpose (stride Cc).
// ---------------------------------------------------------------------------
__global__ __launch_bounds__(256) void k_bn_res_split(
    const float* __restrict__ Y, const float* __restrict__ X,
    h16* __restrict__ dh, h16* __restrict__ dl,
    h16* __restrict__ th, h16* __restrict__ tl)
{
    __shared__ float tile[32][33];
    const int b = blockIdx.z;
    const int c0 = blockIdx.x * 32, r0 = blockIdx.y * 32;
    const size_t fb = (size_t)b * Cc * Nn;
    const size_t dbs = (size_t)b * Cc * Kp1;
    const size_t tbs = (size_t)b * Nn * Cc;

    #pragma unroll
    for (int i = 0; i < 4; i++) {
        int r = r0 + threadIdx.y + i * 8, c = c0 + threadIdx.x;
        size_t off = fb + (size_t)r * Nn + c;
        float z = fmaf(g_scale[r], Y[off], g_shift[r]) + X[off];
        tile[threadIdx.y + i * 8][threadIdx.x] = z;
        h16 h, l; split_h16(z, h, l);
        size_t o = dbs + (size_t)r * Kp1 + c;
        dh[o] = h; dl[o] = l;
    }
    __syncthreads();
    #pragma unroll
    for (int i = 0; i < 4; i++) {
        int tr = c0 + threadIdx.y + i * 8, tc = r0 + threadIdx.x;
        float v = tile[threadIdx.x][threadIdx.y + i * 8];
        h16 h, l; split_h16(v, h, l);
        size_t o = tbs + (size_t)tr * Cc + tc;
        th[o] = h; tl[o] = l;
    }
}

// ---------------------------------------------------------------------------
__global__ __launch_bounds__(288) void k_softmax_prior(const float* __restrict__ dis)
{
    int p = blockIdx.x, b = blockIdx.y, t = threadIdx.x;
    const float* f = g_F + ((size_t)b * Nn + p) * Nn;
    float v = f[t];
    float m1 = block_reduce(v, 0);
    float e1 = __expf(v - m1);
    float s1 = block_reduce(e1, 1);
    float w  = (e1 / s1) * dis[(size_t)p * Nn + t];
    float m2 = block_reduce(w, 0);
    float e2 = __expf(w - m2);
    float s2 = block_reduce(e2, 1);
    h16 h, l; split_h16(e2 / s2, h, l);
    size_t o = ((size_t)b * Nn + p) * Kp1 + t;
    g_Fh[o] = h; g_Fl[o] = l;
}

// rows of g_F2 (len 1024): 256 threads x 4 contiguous, float4/half2 vectorized
__global__ __launch_bounds__(256) void k_softmax_chan()
{
    size_t row = blockIdx.x;
    const float* f = g_F2 + row * (size_t)Cc;
    int t = threadIdx.x;
    float4 v4 = ((const float4*)f)[t];
    float v[4] = {v4.x, v4.y, v4.z, v4.w};
    float m = block_reduce(fmaxf(fmaxf(v[0], v[1]), fmaxf(v[2], v[3])), 0);
    float e[4], ls = 0.0f;
    #pragma unroll
    for (int i = 0; i < 4; i++) { e[i] = __expf(v[i] - m); ls += e[i]; }
    float s = block_reduce(ls, 1);
    float inv = 1.0f / s;
    __half2 h0 = __floats2half2_rn(e[0] * inv, e[1] * inv);
    __half2 h1 = __floats2half2_rn(e[2] * inv, e[3] * inv);
    uint2 pk = make_uint2(*(uint32_t*)&h0, *(uint32_t*)&h1);
    ((uint2*)(g_F2h + row * (size_t)Cc))[t] = pk;
}

__global__ __launch_bounds__(256) void k_bnstats(
    const float* __restrict__ Y,
    const float* __restrict__ gamma, const float* __restrict__ beta)
{
    int c = blockIdx.x, t = threadIdx.x;
    const int n4 = Nn / 4, tot4 = Bb * n4;
    float s = 0.0f, sq = 0.0f;
    #pragma unroll 4
    for (int idx = t; idx < tot4; idx += 256) {
        int b = idx / n4, i = idx - b * n4;
        float4 v = *(const float4*)(Y + ((size_t)b * Cc + c) * Nn + i * 4);
        s  += (v.x + v.y) + (v.z + v.w);
        sq += (v.x * v.x + v.y * v.y) + (v.z * v.z + v.w * v.w);
    }
    s = block_reduce(s, 1);
    sq = block_reduce(sq, 1);
    if (t == 0) {
        const float invN = 1.0f / (float)(Bb * Nn);
        float mean = s * invN;
        float var  = sq * invN - mean * mean;
        float sc = gamma[c] * rsqrtf(var + EPSv);
        g_scale[c] = sc;
        g_shift[c] = beta[c] - mean * sc;
    }
}

// out = scale[c]*Y2 + shift[c] + (Zh + Zl)   (residual reconstructed from split)
__global__ __launch_bounds__(256) void k_bn_apply_add_h(
    const float* __restrict__ Y, float* __restrict__ out)
{
    size_t i4 = (size_t)blockIdx.x * blockDim.x + threadIdx.x;
    const size_t total4 = (size_t)Bb * Cc * Nn / 4;
    if (i4 >= total4) return;
    size_t e = i4 * 4;
    int b = (int)(e / ((size_t)Cc * Nn));
    int rem = (int)(e - (size_t)b * Cc * Nn);
    int c = rem / Nn;
    int n = rem - c * Nn;
    float4 y = ((const float4*)Y)[i4];
    size_t zo = (size_t)b * Cc * Kp1 + (size_t)c * Kp1 + n;
    uint2 zhp = *(const uint2*)(g_Zh + zo);
    uint2 zlp = *(const uint2*)(g_Zl + zo);
    __half2 zh0 = *(__half2*)&zhp.x, zh1 = *(__half2*)&zhp.y;
    __half2 zl0 = *(__half2*)&zlp.x, zl1 = *(__half2*)&zlp.y;
    float r0 = __low2float(zh0) + __low2float(zl0);
    float r1 = __high2float(zh0) + __high2float(zl0);
    float r2 = __low2float(zh1) + __low2float(zl1);
    float r3 = __high2float(zh1) + __high2float(zl1);
    float sc = g_scale[c], sh = g_shift[c];
    float4 o;
    o.x = fmaf(sc, y.x, sh) + r0;
    o.y = fmaf(sc, y.y, sh) + r1;
    o.z = fmaf(sc, y.z, sh) + r2;
    o.w = fmaf(sc, y.w, sh) + r3;
    ((float4*)out)[i4] = o;
}

// ---------------------------------------------------------------------------
extern "C" void kernel_launch(void* const* d_in, const int* in_sizes, int n_in,
                              void* d_out, int out_size)
{
    const float* x      = (const float*)d_in[0];
    const float* dis    = (const float*)d_in[1];
    const float* gamma1 = (const float*)d_in[2];
    const float* beta1  = (const float*)d_in[3];
    const float* gamma2 = (const float*)d_in[4];
    const float* beta2  = (const float*)d_in[5];
    float* out = (float*)d_out;

    float *pF, *pY, *pY2, *pF2;
    cudaGetSymbolAddress((void**)&pF,  g_F);
    cudaGetSymbolAddress((void**)&pY,  g_Y);
    cudaGetSymbolAddress((void**)&pY2, g_Y2);
    cudaGetSymbolAddress((void**)&pF2, g_F2);
    h16 *pXh,*pXTh,*pXTl,*pZh,*pZl,*pZTh,*pZTl,*pFh,*pFl,*pF2h;
    cudaGetSymbolAddress((void**)&pXh,  g_Xh);
    cudaGetSymbolAddress((void**)&pXTh, g_XTh); cudaGetSymbolAddress((void**)&pXTl, g_XTl);
    cudaGetSymbolAddress((void**)&pZh,  g_Zh);  cudaGetSymbolAddress((void**)&pZl,  g_Zl);
    cudaGetSymbolAddress((void**)&pZTh, g_ZTh); cudaGetSymbolAddress((void**)&pZTl, g_ZTl);
    cudaGetSymbolAddress((void**)&pFh,  g_Fh);  cudaGetSymbolAddress((void**)&pFl,  g_Fl);
    cudaGetSymbolAddress((void**)&pF2h, g_F2h);

    const int SM2 = 4 * 24576;   // 98304 (k_mma256; also covers 128x133 fp32 transpose = 68 KB)
    const int SM9 = 4 * 20480;   // 81920 (k_mma192)
    static bool attr_set = false;
    if (!attr_set) {
        cudaFuncSetAttribute((const void*)k_mma256<true >,
                             cudaFuncAttributeMaxDynamicSharedMemorySize, SM2);
        cudaFuncSetAttribute((const void*)k_mma192,
                             cudaFuncAttributeMaxDynamicSharedMemorySize, SM9);
        attr_set = true;
    }

    const size_t sX  = (size_t)Cc * Kp1;
    const size_t sXT = (size_t)Nn * Cc;
    const size_t sFb = (size_t)Nn * Kp1;
    const size_t sF  = (size_t)Nn * Nn;
    const size_t sYb = (size_t)Cc * Nn;
    const size_t sF2 = (size_t)Cc * Cc;

    // 0) split X -> Xh (hi only, Kp=320) + XT hi/lo (K=1024)
    k_split_both<<<dim3(Nn / 32, Cc / 32, Bb), dim3(32, 8)>>>(
        x, pXh, nullptr, Kp1, pXTh, pXTl, Cc, Cc, Nn);

    // 1) F = XT·XTᵀ / 32  (sym)  M=N=288, K=1024
    k_mma256<true><<<dim3(3, 3, Bb), 256, SM2>>>(
        pXTh, pXTh, pXTl, pF, Nn, Nn, Cc, sXT, sXT, sF, 0.03125f);

    // 2) softmax+prior -> F hi/lo (Kp=320)
    k_softmax_prior<<<dim3(Nn, Bb), 288>>>(dis);

    // 3) Y = X·Fᵀ  M=1024, N=288 = 3x96 tiles, Kp=320
    k_mma192<<<dim3(3, 8, Bb), 192, SM9>>>(
        pXh, pFh, pFl, pY, Cc, Nn, Kp1, sX, sFb, sYb, 1.0f);

    // 4) BN1 stats + fused (residual + Z split direct/transposed; no fp32 Z)
    k_bnstats<<<Cc, 256>>>(pY, gamma1, beta1);
    k_bn_res_split<<<dim3(Nn / 32, Cc / 32, Bb), dim3(32, 8)>>>(
        pY, x, pZh, pZl, pZTh, pZTl);

    // 6) F2 = Z·Zᵀ  (sym)  M=N=1024, Kp=320
    k_mma256<true><<<dim3(8, 8, Bb), 256, SM2>>>(
        pZh, pZh, pZl, pF2, Cc, Cc, Kp1, sX, sX, sF2, 1.0f);

    // 7) softmax rows of F2 -> F2 hi
    k_softmax_chan<<<Bb * Cc, 256>>>();

    // 8) Y2 = F2·ZTᵀ  M=1024, N=288 = 3x96 tiles, K=1024
    k_mma192<<<dim3(3, 8, Bb), 192, SM9>>>(
        pF2h, pZTh, pZTl, pY2, Cc, Nn, Cc, sF2, sXT, sYb, 1.0f);

    // 9) BN2 stats + final: out = bn2(Y2) + (Zh+Zl)
    k_bnstats<<<Cc, 256>>>(pY2, gamma2, beta2);
    k_bn_apply_add_h<<<(int)(((size_t)Bb * Cc * Nn / 4 + 255) / 256), 256>>>(pY2, out);
}

// round 17
// speedup vs baseline: 4.5326x; 1.0421x over previous
#include <cuda_runtime.h>
#include <cuda_fp16.h>
#include <math.h>
#include <stdint.h>

#define Bb   128
#define Cc   1024
#define Nn   288
#define Kp1  320            // padded K for K=288 (multiple of 32)
#define EPSv 1e-5f

typedef __half h16;

// fp32 scratch
__device__ float g_F [(size_t)Bb * Nn * Nn];
__device__ float g_Y [(size_t)Bb * Cc * Nn];
__device__ float g_Y2[(size_t)Bb * Cc * Nn];
__device__ float g_F2[(size_t)Bb * Cc * Cc];
__device__ float g_scale[Cc];
__device__ float g_shift[Cc];
// fp16 hi/lo K-major operands (pads stay zero: zero-init, never written)
__device__ h16 g_Xh [(size_t)Bb * Cc * Kp1];
__device__ h16 g_XTh[(size_t)Bb * Nn * Cc];
__device__ h16 g_XTl[(size_t)Bb * Nn * Cc];
__device__ h16 g_Zh [(size_t)Bb * Cc * Kp1];
__device__ h16 g_Zl [(size_t)Bb * Cc * Kp1];
__device__ h16 g_ZTh[(size_t)Bb * Nn * Cc];
__device__ h16 g_ZTl[(size_t)Bb * Nn * Cc];
__device__ h16 g_Fh [(size_t)Bb * Nn * Kp1];
__device__ h16 g_Fl [(size_t)Bb * Nn * Kp1];
__device__ h16 g_F2h[(size_t)Bb * Cc * Cc];

// ---------------- helpers ----------------
__device__ __forceinline__ uint32_t smem_u32(const void* p) {
    uint32_t a;
    asm("{ .reg .u64 t; cvta.to.shared.u64 t, %1; cvt.u32.u64 %0, t; }" : "=r"(a) : "l"(p));
    return a;
}
__device__ __forceinline__ void split_h16(float x, h16& h, h16& l) {
    h = __float2half(x);
    l = __float2half(x - __half2float(h));
}

#define LDMX4(r, a) \
    asm volatile("ldmatrix.sync.aligned.m8n8.x4.shared.b16 {%0,%1,%2,%3}, [%4];" \
        : "=r"((r)[0]), "=r"((r)[1]), "=r"((r)[2]), "=r"((r)[3]) : "r"(a))

__device__ __forceinline__ void mma16816(float* c, const uint32_t* a, const uint32_t* b) {
    asm volatile("mma.sync.aligned.m16n8k16.row.col.f32.f16.f16.f32 "
        "{%0,%1,%2,%3}, {%4,%5,%6,%7}, {%8,%9}, {%0,%1,%2,%3};"
        : "+f"(c[0]), "+f"(c[1]), "+f"(c[2]), "+f"(c[3])
        : "r"(a[0]), "r"(a[1]), "r"(a[2]), "r"(a[3]), "r"(b[0]), "r"(b[1]));
}

#define CP_ASYNC(dst, src, sz) \
    asm volatile("cp.async.cg.shared.global [%0], [%1], 16, %2;" \
        :: "r"(dst), "l"(src), "r"(sz) : "memory")
#define CP_COMMIT() asm volatile("cp.async.commit_group;" ::: "memory")
#define CP_WAIT2()  asm volatile("cp.async.wait_group 2;" ::: "memory")
#define CP_WAIT1()  asm volatile("cp.async.wait_group 1;" ::: "memory")
#define CP_WAIT0()  asm volatile("cp.async.wait_group 0;" ::: "memory")

// conflict-free swizzle (R11): residues {c^j, 4+c^j} distinct over 8-row phase
__device__ __forceinline__ uint32_t sw_off(int row, int chunk) {
    return (uint32_t)((row * 4 + (chunk ^ ((row >> 1) & 3))) * 16);
}

// ---------------- block reduce ----------------
__device__ __forceinline__ float block_reduce(float v, int op) {
    __shared__ float red[32];
    #pragma unroll
    for (int o = 16; o > 0; o >>= 1) {
        float u = __shfl_xor_sync(0xffffffffu, v, o);
        v = op ? (v + u) : fmaxf(v, u);
    }
    int lane = threadIdx.x & 31, wid = threadIdx.x >> 5;
    int nw = (blockDim.x + 31) >> 5;
    if (lane == 0) red[wid] = v;
    __syncthreads();
    if (wid == 0) {
        float r = (lane < nw) ? red[lane] : (op ? 0.0f : -3.4e38f);
        #pragma unroll
        for (int o = 16; o > 0; o >>= 1) {
            float u = __shfl_xor_sync(0xffffffffu, r, o);
            r = op ? (r + u) : fmaxf(r, u);
        }
        if (lane == 0) red[0] = r;
    }
    __syncthreads();
    float r = red[0];
    __syncthreads();
    return r;
}

// ---------------------------------------------------------------------------
// 256-thread HMMA GEMM, NTILE=128 (fp16 2-pass split): C = alpha * A·Bᵀ
// For symmetric grams (F, F2): skip bx<by; bx>by mirror via smem transpose.
// 8 warps 2x4, warp tile 64x32; 4-stage cp.async pipeline.
// ---------------------------------------------------------------------------
template<bool SYM>
__global__ __launch_bounds__(256, 2) void k_mma256(
    const h16* __restrict__ Ah,
    const h16* __restrict__ Bh, const h16* __restrict__ Bl,
    float* __restrict__ Cd, int M, int Nd, int Kp,
    size_t sA, size_t sB, size_t sC, float alpha)
{
    constexpr int ABYTES = 8192;
    constexpr int BSEG   = 8192;
    constexpr int BUF    = ABYTES + 2 * BSEG;   // 24576

    extern __shared__ __align__(16) char dsm[];
    const int bx = blockIdx.x, by = blockIdx.y, bz = blockIdx.z;
    if (SYM && bx < by) return;
    const int m0 = by * 128, n0 = bx * 128;
    const int t = threadIdx.x;
    const int lane = t & 31, wid = t >> 5;
    const int mbase = (wid >> 2) * 64, nbase = (wid & 3) * 32;

    const h16* Abh = Ah + (size_t)bz * sA;
    const h16* Bbh = Bh + (size_t)bz * sB;
    const h16* Bbl = Bl + (size_t)bz * sB;

    const uint32_t sbase = smem_u32(dsm);

    auto stage = [&](int buf, int k0) {
        #pragma unroll
        for (int i = 0; i < 6; i++) {
            int idx = t + i * 256;
            const h16* base; int g, row, chunk; uint32_t dstoff; bool valid;
            if (idx < 512) {
                row = idx >> 2; chunk = idx & 3;
                base = Abh;
                g = m0 + row; valid = g < M;
                dstoff = sw_off(row, chunk);
            } else {
                int idxb = idx - 512;
                int hl = idxb >= 512;
                int r = idxb - hl * 512;
                row = r >> 2; chunk = r & 3;
                base = hl ? Bbl : Bbh;
                g = n0 + row; valid = g < Nd;
                dstoff = ABYTES + hl * BSEG + sw_off(row, chunk);
            }
            CP_ASYNC(sbase + buf * BUF + dstoff,
                     base + (size_t)g * Kp + k0 + chunk * 8, valid ? 16 : 0);
        }
        CP_COMMIT();
    };

    float acc[4][4][4];
    #pragma unroll
    for (int mi = 0; mi < 4; mi++)
        #pragma unroll
        for (int ni = 0; ni < 4; ni++)
            #pragma unroll
            for (int q = 0; q < 4; q++) acc[mi][ni][q] = 0.0f;

    const int nk = Kp / 32;
    stage(0, 0);
    if (nk > 1) stage(1, 32);
    if (nk > 2) stage(2, 64);
    if (nk > 2)      { CP_WAIT2(); }
    else if (nk > 1) { CP_WAIT1(); }
    else             { CP_WAIT0(); }
    __syncthreads();

    for (int kt = 0; kt < nk; kt++) {
        const int buf = kt & 3;
        if (kt + 3 < nk) stage((kt + 3) & 3, (kt + 3) * 32);

        const uint32_t bb = sbase + buf * BUF;
        #pragma unroll
        for (int s = 0; s < 2; s++) {
            const int c0 = s * 2;
            const int arow = (lane & 15), achk = c0 + (lane >> 4);
            const int brow = (lane & 7) + ((lane & 16) >> 1);
            const int bchk = c0 + ((lane >> 3) & 1);

            uint32_t ah[4][4];
            #pragma unroll
            for (int mi = 0; mi < 4; mi++)
                LDMX4(ah[mi], bb + sw_off(mbase + mi * 16 + arow, achk));

            uint32_t bh[4][2], bl[4][2];
            #pragma unroll
            for (int h = 0; h < 2; h++) {
                uint32_t r4[4];
                int rw = nbase + h * 16 + brow;
                LDMX4(r4, bb + ABYTES + sw_off(rw, bchk));
                bh[h*2][0] = r4[0]; bh[h*2][1] = r4[1];
                bh[h*2+1][0] = r4[2]; bh[h*2+1][1] = r4[3];
                LDMX4(r4, bb + ABYTES + BSEG + sw_off(rw, bchk));
                bl[h*2][0] = r4[0]; bl[h*2][1] = r4[1];
                bl[h*2+1][0] = r4[2]; bl[h*2+1][1] = r4[3];
            }
            #pragma unroll
            for (int mi = 0; mi < 4; mi++)
                #pragma unroll
                for (int nj = 0; nj < 4; nj++)
                    mma16816(acc[mi][nj], ah[mi], bh[nj]);
            #pragma unroll
            for (int mi = 0; mi < 4; mi++)
                #pragma unroll
                for (int nj = 0; nj < 4; nj++)
                    mma16816(acc[mi][nj], ah[mi], bl[nj]);
        }

        if (kt + 3 < nk)      { CP_WAIT2(); }
        else if (kt + 2 < nk) { CP_WAIT1(); }
        else if (kt + 1 < nk) { CP_WAIT0(); }
        if (kt + 1 < nk) __syncthreads();
    }

    float* cb = Cd + (size_t)bz * sC;
    #pragma unroll
    for (int mi = 0; mi < 4; mi++) {
        #pragma unroll
        for (int ni = 0; ni < 4; ni++) {
            int row = m0 + mbase + mi * 16 + (lane >> 2);
            int col = n0 + nbase + ni * 8 + (lane & 3) * 2;
            if (col < Nd) {
                if (row < M)
                    *(float2*)(cb + (size_t)row * Nd + col) =
                        make_float2(acc[mi][ni][0] * alpha, acc[mi][ni][1] * alpha);
                if (row + 8 < M)
                    *(float2*)(cb + (size_t)(row + 8) * Nd + col) =
                        make_float2(acc[mi][ni][2] * alpha, acc[mi][ni][3] * alpha);
            }
        }
    }
    if (SYM && bx > by) {
        __syncthreads();
        float* tsm = (float*)dsm;              // 128 x 133 fp32
        #pragma unroll
        for (int mi = 0; mi < 4; mi++) {
            #pragma unroll
            for (int ni = 0; ni < 4; ni++) {
                int lr = mbase + mi * 16 + (lane >> 2);
                int lc = nbase + ni * 8 + (lane & 3) * 2;
                tsm[lr * 133 + lc]           = acc[mi][ni][0] * alpha;
                tsm[lr * 133 + lc + 1]       = acc[mi][ni][1] * alpha;
                tsm[(lr + 8) * 133 + lc]     = acc[mi][ni][2] * alpha;
                tsm[(lr + 8) * 133 + lc + 1] = acc[mi][ni][3] * alpha;
            }
        }
        __syncthreads();
        #pragma unroll
        for (int r8 = 0; r8 < 16; r8++) {
            int rr = wid * 16 + r8;
            if (n0 + rr >= Nd) continue;
            float* dst = cb + (size_t)(n0 + rr) * Nd + m0;
            #pragma unroll
            for (int cc4 = 0; cc4 < 4; cc4++) {
                int cc = cc4 * 32 + lane;
                if (m0 + cc < M)
                    dst[cc] = tsm[cc * 133 + rr];
            }
        }
    }
}

// ---------------------------------------------------------------------------
// 192-thread HMMA GEMM, NTILE=96: for Y/Y2 (N=288 = 3x96, no tails).
// 6 warps 2(m)x3(n), warp tile 64x32.
// ---------------------------------------------------------------------------
__global__ __launch_bounds__(192, 2) void k_mma192(
    const h16* __restrict__ Ah,
    const h16* __restrict__ Bh, const h16* __restrict__ Bl,
    float* __restrict__ Cd, int M, int Nd, int Kp,
    size_t sA, size_t sB, size_t sC, float alpha)
{
    constexpr int ABYTES = 8192;
    constexpr int BSEG   = 6144;
    constexpr int BUF    = ABYTES + 2 * BSEG;   // 20480
    constexpr int TOTCH  = 512 + 768;

    extern __shared__ __align__(16) char dsm[];
    const int bx = blockIdx.x, by = blockIdx.y, bz = blockIdx.z;
    const int m0 = by * 128, n0 = bx * 96;
    const int t = threadIdx.x;
    const int lane = t & 31, wid = t >> 5;
    const int wm = (wid >= 3) ? 1 : 0;
    const int wn = wid - wm * 3;
    const int mbase = wm * 64, nbase = wn * 32;

    const h16* Abh = Ah + (size_t)bz * sA;
    const h16* Bbh = Bh + (size_t)bz * sB;
    const h16* Bbl = Bl + (size_t)bz * sB;

    const uint32_t sbase = smem_u32(dsm);

    auto stage = [&](int buf, int k0) {
        #pragma unroll
        for (int i = 0; i < 7; i++) {
            int idx = t + i * 192;
            if (idx >= TOTCH) break;
            const h16* base; int g, row, chunk; uint32_t dstoff; bool valid;
            if (idx < 512) {
                row = idx >> 2; chunk = idx & 3;
                base = Abh;
                g = m0 + row; valid = g < M;
                dstoff = sw_off(row, chunk);
            } else {
                int idxb = idx - 512;
                int hl = idxb >= 384;
                int r = idxb - hl * 384;
                row = r >> 2; chunk = r & 3;
                base = hl ? Bbl : Bbh;
                g = n0 + row; valid = g < Nd;
                dstoff = ABYTES + hl * BSEG + sw_off(row, chunk);
            }
            CP_ASYNC(sbase + buf * BUF + dstoff,
                     base + (size_t)g * Kp + k0 + chunk * 8, valid ? 16 : 0);
        }
        CP_COMMIT();
    };

    float acc[4][4][4];
    #pragma unroll
    for (int mi = 0; mi < 4; mi++)
        #pragma unroll
        for (int ni = 0; ni < 4; ni++)
            #pragma unroll
            for (int q = 0; q < 4; q++) acc[mi][ni][q] = 0.0f;

    const int nk = Kp / 32;
    stage(0, 0);
    if (nk > 1) stage(1, 32);
    if (nk > 2) stage(2, 64);
    if (nk > 2)      { CP_WAIT2(); }
    else if (nk > 1) { CP_WAIT1(); }
    else             { CP_WAIT0(); }
    __syncthreads();

    for (int kt = 0; kt < nk; kt++) {
        const int buf = kt & 3;
        if (kt + 3 < nk) stage((kt + 3) & 3, (kt + 3) * 32);

        const uint32_t bb = sbase + buf * BUF;
        #pragma unroll
        for (int s = 0; s < 2; s++) {
            const int c0 = s * 2;
            const int arow = (lane & 15), achk = c0 + (lane >> 4);
            const int brow = (lane & 7) + ((lane & 16) >> 1);
            const int bchk = c0 + ((lane >> 3) & 1);

            uint32_t ah[4][4];
            #pragma unroll
            for (int mi = 0; mi < 4; mi++)
                LDMX4(ah[mi], bb + sw_off(mbase + mi * 16 + arow, achk));

            uint32_t bh[4][2], bl[4][2];
            #pragma unroll
            for (int h = 0; h < 2; h++) {
                uint32_t r4[4];
                int rw = nbase + h * 16 + brow;
                LDMX4(r4, bb + ABYTES + sw_off(rw, bchk));
                bh[h*2][0] = r4[0]; bh[h*2][1] = r4[1];
                bh[h*2+1][0] = r4[2]; bh[h*2+1][1] = r4[3];
                LDMX4(r4, bb + ABYTES + BSEG + sw_off(rw, bchk));
                bl[h*2][0] = r4[0]; bl[h*2][1] = r4[1];
                bl[h*2+1][0] = r4[2]; bl[h*2+1][1] = r4[3];
            }
            #pragma unroll
            for (int mi = 0; mi < 4; mi++)
                #pragma unroll
                for (int nj = 0; nj < 4; nj++)
                    mma16816(acc[mi][nj], ah[mi], bh[nj]);
            #pragma unroll
            for (int mi = 0; mi < 4; mi++)
                #pragma unroll
                for (int nj = 0; nj < 4; nj++)
                    mma16816(acc[mi][nj], ah[mi], bl[nj]);
        }

        if (kt + 3 < nk)      { CP_WAIT2(); }
        else if (kt + 2 < nk) { CP_WAIT1(); }
        else if (kt + 1 < nk) { CP_WAIT0(); }
        if (kt + 1 < nk) __syncthreads();
    }

    float* cb = Cd + (size_t)bz * sC;
    #pragma unroll
    for (int mi = 0; mi < 4; mi++) {
        #pragma unroll
        for (int ni = 0; ni < 4; ni++) {
            int row = m0 + mbase + mi * 16 + (lane >> 2);
            int col = n0 + nbase + ni * 8 + (lane & 3) * 2;
            if (col < Nd) {
                if (row < M)
                    *(float2*)(cb + (size_t)row * Nd + col) =
                        make_float2(acc[mi][ni][0] * alpha, acc[mi][ni][1] * alpha);
                if (row + 8 < M)
                    *(float2*)(cb + (size_t)(row + 8) * Nd + col) =
                        make_float2(acc[mi][ni][2] * alpha, acc[mi][ni][3] * alpha);
            }
        }
    }
}

// ---------------------------------------------------------------------------
// fp32 (rows x cols) -> direct hi[/lo] (stride ds) + transposed hi/lo (stride ts)
// ---------------------------------------------------------------------------
__global__ __launch_bounds__(256) void k_split_both(
    const float* __restrict__ src,
    h16* __restrict__ dh, h16* __restrict__ dl, int ds,
    h16* __restrict__ th, h16* __restrict__ tl, int ts,
    int rows, int cols)
{
    __shared__ float tile[32][33];
    const int b = blockIdx.z;
    const int c0 = blockIdx.x * 32, r0 = blockIdx.y * 32;
    const float* s = src + (size_t)b * rows * cols;
    const size_t dbs = (size_t)b * rows * ds;
    const size_t tbs = (size_t)b * cols * ts;

    #pragma unroll
    for (int i = 0; i < 4; i++) {
        int r = r0 + threadIdx.y + i * 8, c = c0 + threadIdx.x;
        float v = s[(size_t)r * cols + c];
        tile[threadIdx.y + i * 8][threadIdx.x] = v;
        h16 h, l; split_h16(v, h, l);
        size_t o = dbs + (size_t)r * ds + c;
        dh[o] = h;
        if (dl) dl[o] = l;
    }
    __syncthreads();
    #pragma unroll
    for (int i = 0; i < 4; i++) {
        int tr = c0 + threadIdx.y + i * 8, tc = r0 + threadIdx.x;
        float v = tile[threadIdx.x][threadIdx.y + i * 8];
        h16 h, l; split_h16(v, h, l);
        size_t o = tbs + (size_t)tr * ts + tc;
        th[o] = h; tl[o] = l;
    }
}

// ---------------------------------------------------------------------------
// Fused: z = scale[c]*Y + shift[c] + X (fp32 z NOT stored), writes fp16 hi/lo
// split of z (direct, stride Kp1) and its transpose (stride Cc).
// ---------------------------------------------------------------------------
__global__ __launch_bounds__(256) void k_bn_res_split(
    const float* __restrict__ Y, const float* __restrict__ X,
    h16* __restrict__ dh, h16* __restrict__ dl,
    h16* __restrict__ th, h16* __restrict__ tl)
{
    __shared__ float tile[32][33];
    const int b = blockIdx.z;
    const int c0 = blockIdx.x * 32, r0 = blockIdx.y * 32;
    const size_t fb = (size_t)b * Cc * Nn;
    const size_t dbs = (size_t)b * Cc * Kp1;
    const size_t tbs = (size_t)b * Nn * Cc;

    #pragma unroll
    for (int i = 0; i < 4; i++) {
        int r = r0 + threadIdx.y + i * 8, c = c0 + threadIdx.x;
        size_t off = fb + (size_t)r * Nn + c;
        float z = fmaf(g_scale[r], Y[off], g_shift[r]) + X[off];
        tile[threadIdx.y + i * 8][threadIdx.x] = z;
        h16 h, l; split_h16(z, h, l);
        size_t o = dbs + (size_t)r * Kp1 + c;
        dh[o] = h; dl[o] = l;
    }
    __syncthreads();
    #pragma unroll
    for (int i = 0; i < 4; i++) {
        int tr = c0 + threadIdx.y + i * 8, tc = r0 + threadIdx.x;
        float v = tile[threadIdx.x][threadIdx.y + i * 8];
        h16 h, l; split_h16(v, h, l);
        size_t o = tbs + (size_t)tr * Cc + tc;
        th[o] = h; tl[o] = l;
    }
}

// ---------------------------------------------------------------------------
__global__ __launch_bounds__(288) void k_softmax_prior(const float* __restrict__ dis)
{
    int p = blockIdx.x, b = blockIdx.y, t = threadIdx.x;
    const float* f = g_F + ((size_t)b * Nn + p) * Nn;
    float v = f[t];
    float m1 = block_reduce(v, 0);
    float e1 = __expf(v - m1);
    float s1 = block_reduce(e1, 1);
    float w  = (e1 / s1) * dis[(size_t)p * Nn + t];
    float m2 = block_reduce(w, 0);
    float e2 = __expf(w - m2);
    float s2 = block_reduce(e2, 1);
    h16 h, l; split_h16(e2 / s2, h, l);
    size_t o = ((size_t)b * Nn + p) * Kp1 + t;
    g_Fh[o] = h; g_Fl[o] = l;
}

// warp-per-row softmax over g_F2 (row len 1024): 8 rows/block, no barriers.
__global__ __launch_bounds__(256) void k_softmax_chan()
{
    const int wid = threadIdx.x >> 5, lane = threadIdx.x & 31;
    const size_t row = (size_t)blockIdx.x * 8 + wid;
    const float* f = g_F2 + row * (size_t)Cc;
    float4 v[8];
    #pragma unroll
    for (int i = 0; i < 8; i++) v[i] = ((const float4*)f)[i * 32 + lane];
    float m = -3.4e38f;
    #pragma unroll
    for (int i = 0; i < 8; i++)
        m = fmaxf(m, fmaxf(fmaxf(v[i].x, v[i].y), fmaxf(v[i].z, v[i].w)));
    #pragma unroll
    for (int o = 16; o > 0; o >>= 1)
        m = fmaxf(m, __shfl_xor_sync(0xffffffffu, m, o));
    float s = 0.0f;
    #pragma unroll
    for (int i = 0; i < 8; i++) {
        v[i].x = __expf(v[i].x - m); v[i].y = __expf(v[i].y - m);
        v[i].z = __expf(v[i].z - m); v[i].w = __expf(v[i].w - m);
        s += (v[i].x + v[i].y) + (v[i].z + v[i].w);
    }
    #pragma unroll
    for (int o = 16; o > 0; o >>= 1)
        s += __shfl_xor_sync(0xffffffffu, s, o);
    const float inv = 1.0f / s;
    uint2* dst = (uint2*)(g_F2h + row * (size_t)Cc);
    #pragma unroll
    for (int i = 0; i < 8; i++) {
        __half2 h0 = __floats2half2_rn(v[i].x * inv, v[i].y * inv);
        __half2 h1 = __floats2half2_rn(v[i].z * inv, v[i].w * inv);
        dst[i * 32 + lane] = make_uint2(*(uint32_t*)&h0, *(uint32_t*)&h1);
    }
}

__global__ __launch_bounds__(256) void k_bnstats(
    const float* __restrict__ Y,
    const float* __restrict__ gamma, const float* __restrict__ beta)
{
    int c = blockIdx.x, t = threadIdx.x;
    const int n4 = Nn / 4, tot4 = Bb * n4;
    float s = 0.0f, sq = 0.0f;
    #pragma unroll 4
    for (int idx = t; idx < tot4; idx += 256) {
        int b = idx / n4, i = idx - b * n4;
        float4 v = *(const float4*)(Y + ((size_t)b * Cc + c) * Nn + i * 4);
        s  += (v.x + v.y) + (v.z + v.w);
        sq += (v.x * v.x + v.y * v.y) + (v.z * v.z + v.w * v.w);
    }
    s = block_reduce(s, 1);
    sq = block_reduce(sq, 1);
    if (t == 0) {
        const float invN = 1.0f / (float)(Bb * Nn);
        float mean = s * invN;
        float var  = sq * invN - mean * mean;
        float sc = gamma[c] * rsqrtf(var + EPSv);
        g_scale[c] = sc;
        g_shift[c] = beta[c] - mean * sc;
    }
}

// out = scale[c]*Y2 + shift[c] + (Zh + Zl)
__global__ __launch_bounds__(256) void k_bn_apply_add_h(
    const float* __restrict__ Y, float* __restrict__ out)
{
    size_t i4 = (size_t)blockIdx.x * blockDim.x + threadIdx.x;
    const size_t total4 = (size_t)Bb * Cc * Nn / 4;
    if (i4 >= total4) return;
    size_t e = i4 * 4;
    int b = (int)(e / ((size_t)Cc * Nn));
    int rem = (int)(e - (size_t)b * Cc * Nn);
    int c = rem / Nn;
    int n = rem - c * Nn;
    float4 y = ((const float4*)Y)[i4];
    size_t zo = (size_t)b * Cc * Kp1 + (size_t)c * Kp1 + n;
    uint2 zhp = *(const uint2*)(g_Zh + zo);
    uint2 zlp = *(const uint2*)(g_Zl + zo);
    __half2 zh0 = *(__half2*)&zhp.x, zh1 = *(__half2*)&zhp.y;
    __half2 zl0 = *(__half2*)&zlp.x, zl1 = *(__half2*)&zlp.y;
    float r0 = __low2float(zh0) + __low2float(zl0);
    float r1 = __high2float(zh0) + __high2float(zl0);
    float r2 = __low2float(zh1) + __low2float(zl1);
    float r3 = __high2float(zh1) + __high2float(zl1);
    float sc = g_scale[c], sh = g_shift[c];
    float4 o;
    o.x = fmaf(sc, y.x, sh) + r0;
    o.y = fmaf(sc, y.y, sh) + r1;
    o.z = fmaf(sc, y.z, sh) + r2;
    o.w = fmaf(sc, y.w, sh) + r3;
    ((float4*)out)[i4] = o;
}

// ---------------------------------------------------------------------------
extern "C" void kernel_launch(void* const* d_in, const int* in_sizes, int n_in,
                              void* d_out, int out_size)
{
    const float* x      = (const float*)d_in[0];
    const float* dis    = (const float*)d_in[1];
    const float* gamma1 = (const float*)d_in[2];
    const float* beta1  = (const float*)d_in[3];
    const float* gamma2 = (const float*)d_in[4];
    const float* beta2  = (const float*)d_in[5];
    float* out = (float*)d_out;

    float *pF, *pY, *pY2, *pF2;
    cudaGetSymbolAddress((void**)&pF,  g_F);
    cudaGetSymbolAddress((void**)&pY,  g_Y);
    cudaGetSymbolAddress((void**)&pY2, g_Y2);
    cudaGetSymbolAddress((void**)&pF2, g_F2);
    h16 *pXh,*pXTh,*pXTl,*pZh,*pZl,*pZTh,*pZTl,*pFh,*pFl,*pF2h;
    cudaGetSymbolAddress((void**)&pXh,  g_Xh);
    cudaGetSymbolAddress((void**)&pXTh, g_XTh); cudaGetSymbolAddress((void**)&pXTl, g_XTl);
    cudaGetSymbolAddress((void**)&pZh,  g_Zh);  cudaGetSymbolAddress((void**)&pZl,  g_Zl);
    cudaGetSymbolAddress((void**)&pZTh, g_ZTh); cudaGetSymbolAddress((void**)&pZTl, g_ZTl);
    cudaGetSymbolAddress((void**)&pFh,  g_Fh);  cudaGetSymbolAddress((void**)&pFl,  g_Fl);
    cudaGetSymbolAddress((void**)&pF2h, g_F2h);

    const int SM2 = 4 * 24576;   // 98304
    const int SM9 = 4 * 20480;   // 81920
    static bool attr_set = false;
    if (!attr_set) {
        cudaFuncSetAttribute((const void*)k_mma256<true >,
                             cudaFuncAttributeMaxDynamicSharedMemorySize, SM2);
        cudaFuncSetAttribute((const void*)k_mma192,
                             cudaFuncAttributeMaxDynamicSharedMemorySize, SM9);
        attr_set = true;
    }

    const size_t sX  = (size_t)Cc * Kp1;
    const size_t sXT = (size_t)Nn * Cc;
    const size_t sFb = (size_t)Nn * Kp1;
    const size_t sF  = (size_t)Nn * Nn;
    const size_t sYb = (size_t)Cc * Nn;
    const size_t sF2 = (size_t)Cc * Cc;

    // 0) split X -> Xh (hi only, Kp=320) + XT hi/lo (K=1024)
    k_split_both<<<dim3(Nn / 32, Cc / 32, Bb), dim3(32, 8)>>>(
        x, pXh, nullptr, Kp1, pXTh, pXTl, Cc, Cc, Nn);

    // 1) F = XT·XTᵀ / 32  (sym)  M=N=288, K=1024
    k_mma256<true><<<dim3(3, 3, Bb), 256, SM2>>>(
        pXTh, pXTh, pXTl, pF, Nn, Nn, Cc, sXT, sXT, sF, 0.03125f);

    // 2) softmax+prior -> F hi/lo (Kp=320)
    k_softmax_prior<<<dim3(Nn, Bb), 288>>>(dis);

    // 3) Y = X·Fᵀ  M=1024, N=288 = 3x96 tiles, Kp=320
    k_mma192<<<dim3(3, 8, Bb), 192, SM9>>>(
        pXh, pFh, pFl, pY, Cc, Nn, Kp1, sX, sFb, sYb, 1.0f);

    // 4) BN1 stats + fused (residual + Z split direct/transposed; no fp32 Z)
    k_bnstats<<<Cc, 256>>>(pY, gamma1, beta1);
    k_bn_res_split<<<dim3(Nn / 32, Cc / 32, Bb), dim3(32, 8)>>>(
        pY, x, pZh, pZl, pZTh, pZTl);

    // 6) F2 = Z·Zᵀ  (sym)  M=N=1024, Kp=320
    k_mma256<true><<<dim3(8, 8, Bb), 256, SM2>>>(
        pZh, pZh, pZl, pF2, Cc, Cc, Kp1, sX, sX, sF2, 1.0f);

    // 7) softmax rows of F2 -> F2 hi (warp-per-row, 8 rows/block)
    k_softmax_chan<<<Bb * Cc / 8, 256>>>();

    // 8) Y2 = F2·ZTᵀ  M=1024, N=288 = 3x96 tiles, K=1024
    k_mma192<<<dim3(3, 8, Bb), 192, SM9>>>(
        pF2h, pZTh, pZTl, pY2, Cc, Nn, Cc, sF2, sXT, sYb, 1.0f);

    // 9) BN2 stats + final: out = bn2(Y2) + (Zh+Zl)
    k_bnstats<<<Cc, 256>>>(pY2, gamma2, beta2);
    k_bn_apply_add_h<<<(int)(((size_t)Bb * Cc * Nn / 4 + 255) / 256), 256>>>(pY2, out);
}